// round 9
// baseline (speedup 1.0000x reference)
#include <cuda_runtime.h>
#include <cstdint>

#define D_MODEL 768
#define NHEAD   12
#define SEQ     1024
#define BATCH   4
#define NTOK    (BATCH*SEQ)        /* 4096 */
#define DH      (D_MODEL*NHEAD)    /* 9216 */
#define DFF     (4*D_MODEL)        /* 3072 */
#define LN_EPS  1e-5f

typedef long long ll;

// ---------------- scratch (device globals; no allocation allowed) ----------------
__device__ float g_Y  [(size_t)NTOK * D_MODEL];
__device__ float g_Q  [(size_t)NTOK * DH];
__device__ float g_K  [(size_t)NTOK * DH];
__device__ float g_V  [(size_t)NTOK * DH];
__device__ float g_S  [(size_t)BATCH * NHEAD * SEQ * SEQ];   // scores; later aliased as split-K partials
__device__ float g_ATT[(size_t)NTOK * DH];
__device__ float g_X1 [(size_t)NTOK * D_MODEL];
__device__ float g_H1 [(size_t)NTOK * DFF];

// ---------------- helpers ----------------
__device__ __forceinline__ float to_tf32(float x) {
    uint32_t u;
    asm("cvt.rna.tf32.f32 %0, %1;" : "=r"(u) : "f"(x));
    return __uint_as_float(u);
}
__device__ __forceinline__ uint32_t smem_u32(const void* p) {
    uint32_t a;
    asm("{ .reg .u64 t; cvta.to.shared.u64 t, %1; cvt.u32.u64 %0, t; }" : "=r"(a) : "l"(p));
    return a;
}
__device__ __forceinline__ void cp16(uint32_t dst, const void* src) {
    asm volatile("cp.async.cg.shared.global [%0], [%1], 16;" :: "r"(dst), "l"(src) : "memory");
}
__device__ __forceinline__ void cp_commit() {
    asm volatile("cp.async.commit_group;" ::: "memory");
}
template<int N>
__device__ __forceinline__ void cp_wait() {
    asm volatile("cp.async.wait_group %0;" :: "n"(N) : "memory");
}
__device__ __forceinline__ void mma_tf32(float c[4],
                                         uint32_t a0, uint32_t a1, uint32_t a2, uint32_t a3,
                                         uint32_t b0, uint32_t b1) {
    asm("mma.sync.aligned.m16n8k8.row.col.f32.tf32.tf32.f32 "
        "{%0,%1,%2,%3}, {%4,%5,%6,%7}, {%8,%9}, {%0,%1,%2,%3};"
        : "+f"(c[0]), "+f"(c[1]), "+f"(c[2]), "+f"(c[3])
        : "r"(a0), "r"(a1), "r"(a2), "r"(a3), "r"(b0), "r"(b1));
}

// ---------------- tf32 tensor-core GEMM, cp.async 3-stage, 8 warps, warp tile 32x64 -
// C[m,n] = epi( alpha * sum_k A[m,k] * B(k,n) )
//   BT=false: B is K x N row-major.  BT=true: B is N x K row-major (A @ B^T).
// CTA tile 128x128x32, 256 threads (8 warps as 4m x 2n), warp tile 32x64.
// acc = 64 regs/thread -> ~110 total: ptxas has headroom to rotate fragment
// loads across nt/ksi; 4 warps/SMSP at 2 CTAs/SM hide LDS latency.
// smem A: [m][k] pitch 36.  B NN: [k][n] pitch 136.  B NT: [n][k] pitch 36.
// All LDS gathers and cp.async stores are 32-bank conflict-free.
template<bool BT, bool RELU, bool HASB, bool HASR, bool ROUND>
__global__ __launch_bounds__(256, 2)
void gemm_cp(const float* __restrict__ A, const float* __restrict__ B,
             const float* __restrict__ bias, const float* __restrict__ Res,
             float* __restrict__ C,
             int K, int lda, int ldb, int ldc, int ldr, float alpha,
             ll saO, ll saI, ll sbO, ll sbI, ll scO, ll scI, ll srO, ll srI,
             int innerCnt)
{
    constexpr int STAGES  = 3;
    constexpr int PA      = 36;                  // A / B-NT pitch
    constexpr int PB      = 136;                 // B-NN pitch
    constexpr int A_F     = 128 * PA;            // 4608 floats
    constexpr int B_F     = BT ? 128 * PA : 32 * PB;
    constexpr int STAGE_F = A_F + B_F;

    extern __shared__ float dynsm[];

    const int tid  = threadIdx.x;
    const int wid  = tid >> 5;
    const int lane = tid & 31;
    const int g    = lane >> 2;
    const int tig  = lane & 3;
    const int wm   = wid >> 1;                   // 0..3 -> 32 rows each
    const int wn   = wid & 1;                    // 0..1 -> 64 cols each

    const int z  = blockIdx.z;
    const int zo = z / innerCnt;
    const int zi = z - zo * innerCnt;
    A += zo * saO + zi * saI;
    B += zo * sbO + zi * sbI;
    C += zo * scO + zi * scI;
    if (HASR) Res += zo * srO + zi * srI;

    const int m0 = blockIdx.y * 128;
    const int n0 = blockIdx.x * 128;
    A += (ll)m0 * lda;
    B += BT ? (ll)n0 * ldb : (ll)n0;

    const uint32_t smb = smem_u32(dynsm);

    auto issue = [&](int tile) {
        const int stage = tile % STAGES;
        const uint32_t sA = smb + (uint32_t)(stage * STAGE_F) * 4u;
        const uint32_t sB = sA + (uint32_t)A_F * 4u;
        const int k0 = tile * 32;
        #pragma unroll
        for (int i = 0; i < 4; i++) {            // A: 128x32, 4 float4/thread
            const int v = tid + i * 256;
            const int m = v >> 3, kc = (v & 7) * 4;
            cp16(sA + (uint32_t)(m * PA + kc) * 4u, A + (ll)m * lda + k0 + kc);
        }
        #pragma unroll
        for (int i = 0; i < 4; i++) {            // B: 128x32 (either orientation)
            const int v = tid + i * 256;
            if (BT) {
                const int n = v >> 3, kc = (v & 7) * 4;
                cp16(sB + (uint32_t)(n * PA + kc) * 4u, B + (ll)n * ldb + k0 + kc);
            } else {
                const int k = v >> 5, nc = (v & 31) * 4;
                cp16(sB + (uint32_t)(k * PB + nc) * 4u, B + (ll)(k0 + k) * ldb + nc);
            }
        }
        cp_commit();
    };

    float acc[2][8][4];
    #pragma unroll
    for (int mt = 0; mt < 2; mt++)
        #pragma unroll
        for (int nt = 0; nt < 8; nt++)
            #pragma unroll
            for (int r = 0; r < 4; r++) acc[mt][nt][r] = 0.f;

    const int T = K >> 5;
    issue(0); issue(1);

    for (int it = 0; it < T; ++it) {
        cp_wait<1>();
        __syncthreads();
        if (it + 2 < T) issue(it + 2);

        const float* As  = dynsm + (it % STAGES) * STAGE_F;
        const float* Bsm = As + A_F;

        #pragma unroll
        for (int ksi = 0; ksi < 4; ksi++) {
            const int kk = ksi * 8 + tig;
            uint32_t a[2][4];
            #pragma unroll
            for (int mt = 0; mt < 2; mt++) {
                const int mA = wm * 32 + mt * 16 + g;
                a[mt][0] = __float_as_uint(As[(mA    ) * PA + kk    ]);
                a[mt][1] = __float_as_uint(As[(mA + 8) * PA + kk    ]);
                a[mt][2] = __float_as_uint(As[(mA    ) * PA + kk + 4]);
                a[mt][3] = __float_as_uint(As[(mA + 8) * PA + kk + 4]);
            }
            // rolling B fragment: load nt+1 while mma'ing nt
            uint32_t b0, b1, p0, p1;
            {
                const int nB = wn * 64 + g;
                if (BT) {
                    b0 = __float_as_uint(Bsm[nB * PA + kk    ]);
                    b1 = __float_as_uint(Bsm[nB * PA + kk + 4]);
                } else {
                    b0 = __float_as_uint(Bsm[(kk    ) * PB + nB]);
                    b1 = __float_as_uint(Bsm[(kk + 4) * PB + nB]);
                }
            }
            #pragma unroll
            for (int nt = 0; nt < 8; nt++) {
                if (nt < 7) {
                    const int nB = wn * 64 + (nt + 1) * 8 + g;
                    if (BT) {
                        p0 = __float_as_uint(Bsm[nB * PA + kk    ]);
                        p1 = __float_as_uint(Bsm[nB * PA + kk + 4]);
                    } else {
                        p0 = __float_as_uint(Bsm[(kk    ) * PB + nB]);
                        p1 = __float_as_uint(Bsm[(kk + 4) * PB + nB]);
                    }
                }
                mma_tf32(acc[0][nt], a[0][0], a[0][1], a[0][2], a[0][3], b0, b1);
                mma_tf32(acc[1][nt], a[1][0], a[1][1], a[1][2], a[1][3], b0, b1);
                b0 = p0; b1 = p1;
            }
        }
    }

    // ---- epilogue ----
    #pragma unroll
    for (int mt = 0; mt < 2; mt++) {
        #pragma unroll
        for (int nt = 0; nt < 8; nt++) {
            const int n = n0 + wn * 64 + nt * 8 + tig * 2;
            float bv0 = 0.f, bv1 = 0.f;
            if (HASB) { bv0 = bias[n]; bv1 = bias[n + 1]; }
            #pragma unroll
            for (int h = 0; h < 2; h++) {
                const int m = m0 + wm * 32 + mt * 16 + g + h * 8;
                float x0 = alpha * acc[mt][nt][h * 2 + 0] + bv0;
                float x1 = alpha * acc[mt][nt][h * 2 + 1] + bv1;
                if (RELU) { x0 = fmaxf(x0, 0.f); x1 = fmaxf(x1, 0.f); }
                if (HASR) {
                    x0 += Res[(ll)m * ldr + n];
                    x1 += Res[(ll)m * ldr + n + 1];
                }
                if (ROUND) { x0 = to_tf32(x0); x1 = to_tf32(x1); }
                float2 w; w.x = x0; w.y = x1;
                *reinterpret_cast<float2*>(C + (ll)m * ldc + n) = w;
            }
        }
    }
}

// ---------------- split-K combine (3-way): out = P0 + P1 + P2 + bias + res ----------
__global__ void combine3_kernel(const float4* __restrict__ P0, const float4* __restrict__ P1,
                                const float4* __restrict__ P2,
                                const float* __restrict__ bias, const float4* __restrict__ res,
                                float4* __restrict__ out, int n4)
{
    const int i = blockIdx.x * blockDim.x + threadIdx.x;
    if (i >= n4) return;
    const int c = (i % (D_MODEL / 4)) * 4;
    const float4 p = P0[i], q = P1[i], s = P2[i], r = res[i];
    float4 o;
    o.x = p.x + q.x + s.x + bias[c + 0] + r.x;
    o.y = p.y + q.y + s.y + bias[c + 1] + r.y;
    o.z = p.z + q.z + s.z + bias[c + 2] + r.z;
    o.w = p.w + q.w + s.w + bias[c + 3] + r.w;
    out[i] = o;
}

// ---------------- layernorm (rounds output to tf32: it feeds GEMM A) ----------------
__global__ void layernorm_kernel(const float* __restrict__ x,
                                 const float* __restrict__ gm,
                                 const float* __restrict__ bt,
                                 float* __restrict__ y)
{
    const ll base = (ll)blockIdx.x * D_MODEL;
    const int t = threadIdx.x;
    float v[3];
    float lsum = 0.f, lsq = 0.f;
    #pragma unroll
    for (int i = 0; i < 3; i++) {
        v[i] = x[base + t + i * 256];
        lsum += v[i];
        lsq  += v[i] * v[i];
    }
    __shared__ float sh[16];
    #pragma unroll
    for (int o = 16; o; o >>= 1) {
        lsum += __shfl_xor_sync(0xffffffffu, lsum, o);
        lsq  += __shfl_xor_sync(0xffffffffu, lsq,  o);
    }
    const int wid = t >> 5, lane = t & 31;
    if (lane == 0) { sh[wid] = lsum; sh[8 + wid] = lsq; }
    __syncthreads();
    if (wid == 0) {
        float a = (lane < 8) ? sh[lane] : 0.f;
        float b = (lane < 8) ? sh[8 + lane] : 0.f;
        #pragma unroll
        for (int o = 4; o; o >>= 1) {
            a += __shfl_xor_sync(0xffffffffu, a, o);
            b += __shfl_xor_sync(0xffffffffu, b, o);
        }
        if (lane == 0) { sh[0] = a; sh[1] = b; }
    }
    __syncthreads();
    const float mu   = sh[0] * (1.f / D_MODEL);
    const float var  = sh[1] * (1.f / D_MODEL) - mu * mu;
    const float rstd = rsqrtf(var + LN_EPS);
    #pragma unroll
    for (int i = 0; i < 3; i++) {
        const int idx = t + i * 256;
        y[base + idx] = to_tf32((v[i] - mu) * rstd * gm[idx] + bt[idx]);
    }
}

// ---------------- row softmax over length-1024 rows (rounds output to tf32) --------
__global__ void softmax_kernel(float* __restrict__ S)
{
    float* p = S + (ll)blockIdx.x * SEQ;
    const int t = threadIdx.x;
    const int wid = t >> 5, lane = t & 31;
    __shared__ float sh[8];

    float v[4];
    float mx = -3.4e38f;
    #pragma unroll
    for (int i = 0; i < 4; i++) { v[i] = p[t + i * 256]; mx = fmaxf(mx, v[i]); }
    #pragma unroll
    for (int o = 16; o; o >>= 1) mx = fmaxf(mx, __shfl_xor_sync(0xffffffffu, mx, o));
    if (lane == 0) sh[wid] = mx;
    __syncthreads();
    if (wid == 0) {
        float a = (lane < 8) ? sh[lane] : -3.4e38f;
        #pragma unroll
        for (int o = 4; o; o >>= 1) a = fmaxf(a, __shfl_xor_sync(0xffffffffu, a, o));
        if (lane == 0) sh[0] = a;
    }
    __syncthreads();
    mx = sh[0];
    __syncthreads();

    float s = 0.f;
    #pragma unroll
    for (int i = 0; i < 4; i++) { v[i] = __expf(v[i] - mx); s += v[i]; }
    #pragma unroll
    for (int o = 16; o; o >>= 1) s += __shfl_xor_sync(0xffffffffu, s, o);
    if (lane == 0) sh[wid] = s;
    __syncthreads();
    if (wid == 0) {
        float a = (lane < 8) ? sh[lane] : 0.f;
        #pragma unroll
        for (int o = 4; o; o >>= 1) a += __shfl_xor_sync(0xffffffffu, a, o);
        if (lane == 0) sh[0] = a;
    }
    __syncthreads();
    const float inv = 1.f / sh[0];
    #pragma unroll
    for (int i = 0; i < 4; i++) p[t + i * 256] = to_tf32(v[i] * inv);
}

// ---------------- launch ----------------
#define SMEM_NN 107520   /* (128*36 + 32*136)*3st*4B */
#define SMEM_NT 110592   /* (128*36 + 128*36)*3st*4B */

extern "C" void kernel_launch(void* const* d_in, const int* in_sizes, int n_in,
                              void* d_out, int out_size)
{
    const float* x    = (const float*)d_in[0];
    const float* Wq   = (const float*)d_in[1];
    const float* Wk   = (const float*)d_in[2];
    const float* Wv   = (const float*)d_in[3];
    const float* Wu   = (const float*)d_in[4];
    const float* bu   = (const float*)d_in[5];
    const float* ln1g = (const float*)d_in[6];
    const float* ln1b = (const float*)d_in[7];
    const float* ln2g = (const float*)d_in[8];
    const float* ln2b = (const float*)d_in[9];
    const float* W1   = (const float*)d_in[10];
    const float* b1   = (const float*)d_in[11];
    const float* W2   = (const float*)d_in[12];
    const float* b2   = (const float*)d_in[13];
    float* out = (float*)d_out;

    float *Y, *Q, *Kp, *V, *S, *ATT, *X1, *H1;
    cudaGetSymbolAddress((void**)&Y,   g_Y);
    cudaGetSymbolAddress((void**)&Q,   g_Q);
    cudaGetSymbolAddress((void**)&Kp,  g_K);
    cudaGetSymbolAddress((void**)&V,   g_V);
    cudaGetSymbolAddress((void**)&S,   g_S);
    cudaGetSymbolAddress((void**)&ATT, g_ATT);
    cudaGetSymbolAddress((void**)&X1,  g_X1);
    cudaGetSymbolAddress((void**)&H1,  g_H1);

    // split-K partial buffers alias g_S (dead after PV GEMM)
    float* P0 = S;
    float* P1 = S + (size_t)NTOK * D_MODEL;
    float* P2 = S + (size_t)2 * NTOK * D_MODEL;

    cudaFuncSetAttribute(gemm_cp<false,false,false,false,true >, cudaFuncAttributeMaxDynamicSharedMemorySize, SMEM_NN);
    cudaFuncSetAttribute(gemm_cp<true ,false,false,false,false>, cudaFuncAttributeMaxDynamicSharedMemorySize, SMEM_NT);
    cudaFuncSetAttribute(gemm_cp<false,true ,true ,false,true >, cudaFuncAttributeMaxDynamicSharedMemorySize, SMEM_NN);
    cudaFuncSetAttribute(gemm_cp<false,false,false,false,false>, cudaFuncAttributeMaxDynamicSharedMemorySize, SMEM_NN);

    const float inv_sqrt_d = 0.03608439182435161f;   // 1/sqrt(768)

    // 0) LN1
    layernorm_kernel<<<NTOK, 256>>>(x, ln1g, ln1b, Y);

    // 1) Q/K/V = Y @ W{q,k,v}  (M=4096, N=9216, K=768)
    {
        dim3 grid(DH / 128, NTOK / 128, 1);
        gemm_cp<false,false,false,false,true><<<grid, 256, SMEM_NN>>>(Y, Wq, nullptr, nullptr, Q,
            D_MODEL, D_MODEL, DH, DH, 0, 1.f, 0,0,0,0,0,0,0,0, 1);
        gemm_cp<false,false,false,false,true><<<grid, 256, SMEM_NN>>>(Y, Wk, nullptr, nullptr, Kp,
            D_MODEL, D_MODEL, DH, DH, 0, 1.f, 0,0,0,0,0,0,0,0, 1);
        gemm_cp<false,false,false,false,true><<<grid, 256, SMEM_NN>>>(Y, Wv, nullptr, nullptr, V,
            D_MODEL, D_MODEL, DH, DH, 0, 1.f, 0,0,0,0,0,0,0,0, 1);
    }

    // 2) S[b,h] = (Q_bh @ K_bh^T)/sqrt(768)  (M=N=1024, K=768, batch=48; NT)
    {
        dim3 grid(SEQ / 128, SEQ / 128, BATCH * NHEAD);
        gemm_cp<true,false,false,false,false><<<grid, 256, SMEM_NT>>>(Q, Kp, nullptr, nullptr, S,
            D_MODEL, DH, DH, SEQ, 0, inv_sqrt_d,
            (ll)SEQ * DH, (ll)D_MODEL,
            (ll)SEQ * DH, (ll)D_MODEL,
            (ll)NHEAD * SEQ * SEQ, (ll)SEQ * SEQ,
            0, 0, NHEAD);
    }

    // 3) softmax (rounds P to tf32)
    softmax_kernel<<<BATCH * NHEAD * SEQ, 256>>>(S);

    // 4) ATT[b,:,h,:] = P_bh @ V_bh  (M=1024, N=768, K=1024, batch=48; NN)
    {
        dim3 grid(D_MODEL / 128, SEQ / 128, BATCH * NHEAD);
        gemm_cp<false,false,false,false,true><<<grid, 256, SMEM_NN>>>(S, V, nullptr, nullptr, ATT,
            SEQ, SEQ, DH, DH, 0, 1.f,
            (ll)NHEAD * SEQ * SEQ, (ll)SEQ * SEQ,
            (ll)SEQ * DH, (ll)D_MODEL,
            (ll)SEQ * DH, (ll)D_MODEL,
            0, 0, NHEAD);
    }

    // 5) Wu split-K=3: partials (batched via z), then X1 = P0+P1+P2 + bu + x
    {
        dim3 grid(D_MODEL / 128, NTOK / 128, 3);
        gemm_cp<false,false,false,false,false><<<grid, 256, SMEM_NN>>>(ATT, Wu,
            nullptr, nullptr, P0, DH/3, DH, D_MODEL, D_MODEL, 0, 1.f,
            0, (ll)(DH/3),
            0, (ll)(DH/3) * D_MODEL,
            0, (ll)NTOK * D_MODEL,
            0, 0, 3);
        const int n4 = NTOK * D_MODEL / 4;
        combine3_kernel<<<(n4 + 255) / 256, 256>>>((const float4*)P0, (const float4*)P1,
                                                   (const float4*)P2, bu,
                                                   (const float4*)x, (float4*)X1, n4);
    }

    // 6) LN2
    layernorm_kernel<<<NTOK, 256>>>(X1, ln2g, ln2b, Y);

    // 7) H1 = relu(Y @ W1 + b1)  (M=4096, N=3072, K=768)
    {
        dim3 grid(DFF / 128, NTOK / 128, 1);
        gemm_cp<false,true,true,false,true><<<grid, 256, SMEM_NN>>>(Y, W1, b1, nullptr, H1,
            D_MODEL, D_MODEL, DFF, DFF, 0, 1.f, 0,0,0,0,0,0,0,0, 1);
    }

    // 8) W2 split-K=3: partials, then out = P0+P1+P2 + b2 + X1
    {
        dim3 grid(D_MODEL / 128, NTOK / 128, 3);
        gemm_cp<false,false,false,false,false><<<grid, 256, SMEM_NN>>>(H1, W2,
            nullptr, nullptr, P0, DFF/3, DFF, D_MODEL, D_MODEL, 0, 1.f,
            0, (ll)(DFF/3),
            0, (ll)(DFF/3) * D_MODEL,
            0, (ll)NTOK * D_MODEL,
            0, 0, 3);
        const int n4 = NTOK * D_MODEL / 4;
        combine3_kernel<<<(n4 + 255) / 256, 256>>>((const float4*)P0, (const float4*)P1,
                                                   (const float4*)P2, b2,
                                                   (const float4*)X1, (float4*)out, n4);
    }

    (void)in_sizes; (void)n_in; (void)out_size;
}

// round 10
// speedup vs baseline: 1.1210x; 1.1210x over previous
#include <cuda_runtime.h>
#include <cstdint>

#define D_MODEL 768
#define NHEAD   12
#define SEQ     1024
#define BATCH   4
#define NTOK    (BATCH*SEQ)        /* 4096 */
#define DH      (D_MODEL*NHEAD)    /* 9216 */
#define DFF     (4*D_MODEL)        /* 3072 */
#define LN_EPS  1e-5f

typedef long long ll;

// ---------------- scratch (device globals; no allocation allowed) ----------------
__device__ float g_Y  [(size_t)NTOK * D_MODEL];
__device__ float g_Q  [(size_t)NTOK * DH];
__device__ float g_K  [(size_t)NTOK * DH];
__device__ float g_V  [(size_t)NTOK * DH];
__device__ float g_S  [(size_t)BATCH * NHEAD * SEQ * SEQ];   // scores; later aliased as split-K partials
__device__ float g_ATT[(size_t)NTOK * DH];
__device__ float g_X1 [(size_t)NTOK * D_MODEL];
__device__ float g_H1 [(size_t)NTOK * DFF];

// ---------------- helpers ----------------
__device__ __forceinline__ float to_tf32(float x) {
    uint32_t u;
    asm("cvt.rna.tf32.f32 %0, %1;" : "=r"(u) : "f"(x));
    return __uint_as_float(u);
}
__device__ __forceinline__ uint32_t smem_u32(const void* p) {
    uint32_t a;
    asm("{ .reg .u64 t; cvta.to.shared.u64 t, %1; cvt.u32.u64 %0, t; }" : "=r"(a) : "l"(p));
    return a;
}
__device__ __forceinline__ void cp16(uint32_t dst, const void* src) {
    asm volatile("cp.async.cg.shared.global [%0], [%1], 16;" :: "r"(dst), "l"(src) : "memory");
}
__device__ __forceinline__ void cp_commit() {
    asm volatile("cp.async.commit_group;" ::: "memory");
}
template<int N>
__device__ __forceinline__ void cp_wait() {
    asm volatile("cp.async.wait_group %0;" :: "n"(N) : "memory");
}
__device__ __forceinline__ void ldsm_x4(uint32_t& r0, uint32_t& r1, uint32_t& r2, uint32_t& r3,
                                        uint32_t addr) {
    asm volatile("ldmatrix.sync.aligned.m8n8.x4.shared.b16 {%0,%1,%2,%3}, [%4];"
                 : "=r"(r0), "=r"(r1), "=r"(r2), "=r"(r3) : "r"(addr));
}
__device__ __forceinline__ void mma_tf32(float c[4],
                                         uint32_t a0, uint32_t a1, uint32_t a2, uint32_t a3,
                                         uint32_t b0, uint32_t b1) {
    asm("mma.sync.aligned.m16n8k8.row.col.f32.tf32.tf32.f32 "
        "{%0,%1,%2,%3}, {%4,%5,%6,%7}, {%8,%9}, {%0,%1,%2,%3};"
        : "+f"(c[0]), "+f"(c[1]), "+f"(c[2]), "+f"(c[3])
        : "r"(a0), "r"(a1), "r"(a2), "r"(a3), "r"(b0), "r"(b1));
}

// ---------------- tf32 tensor-core GEMM, cp.async 3-stage, 2 CTAs/SM, ldmatrix -----
// C[m,n] = epi( alpha * sum_k A[m,k] * B(k,n) )
//   BT=false: B is K x N row-major.  BT=true: B is N x K row-major (A @ B^T).
// CTA tile 128x128x32, 128 threads (4 warps, 2x2), warp tile 64x64; 2 CTAs/SM.
// A fragments via ldmatrix.x4 (one instr per 16x8 tf32 fragment); B via ldmatrix
// in NT orientation, scalar LDS in NN. tf32 b16-lane mapping of ldmatrix matches
// the mma fragment layout exactly (4B chunk (t&3) of row (t>>2)).
// smem A: [m][k] pitch 36.  B NN: [k][n] pitch 136.  B NT: [n][k] pitch 36.
template<bool BT, bool RELU, bool HASB, bool HASR, bool ROUND>
__global__ __launch_bounds__(128, 2)
void gemm_cp(const float* __restrict__ A, const float* __restrict__ B,
             const float* __restrict__ bias, const float* __restrict__ Res,
             float* __restrict__ C,
             int K, int lda, int ldb, int ldc, int ldr, float alpha,
             ll saO, ll saI, ll sbO, ll sbI, ll scO, ll scI, ll srO, ll srI,
             int innerCnt)
{
    constexpr int STAGES  = 3;
    constexpr int PA      = 36;                  // A / B-NT pitch
    constexpr int PB      = 136;                 // B-NN pitch
    constexpr int A_F     = 128 * PA;            // 4608 floats
    constexpr int B_F     = BT ? 128 * PA : 32 * PB;
    constexpr int STAGE_F = A_F + B_F;

    extern __shared__ float dynsm[];

    const int tid  = threadIdx.x;
    const int wid  = tid >> 5;
    const int lane = tid & 31;
    const int g    = lane >> 2;
    const int tig  = lane & 3;
    const int wm   = wid >> 1;                   // 0..1
    const int wn   = wid & 1;                    // 0..1

    // ldmatrix lane decomposition: matrix index mi = lane>>3, row-in-matrix r = lane&7
    const int mi = lane >> 3;
    const int r8 = lane & 7;
    const int aRowOff = (mi & 1) * 8 + r8;       // A: matrices 0/2 rows 0-7, 1/3 rows 8-15
    const int aKOff   = (mi >> 1) * 4;           // A: matrices 0/1 cols k..k+3, 2/3 k+4..k+7
    const int bRowOff = (mi >> 1) * 8 + r8;      // B-NT: matrices 0/1 -> nt, 2/3 -> nt+1
    const int bKOff   = (mi & 1) * 4;            // B-NT: matrices 0/2 cols k.., 1/3 k+4..

    const int z  = blockIdx.z;
    const int zo = z / innerCnt;
    const int zi = z - zo * innerCnt;
    A += zo * saO + zi * saI;
    B += zo * sbO + zi * sbI;
    C += zo * scO + zi * scI;
    if (HASR) Res += zo * srO + zi * srI;

    const int m0 = blockIdx.y * 128;
    const int n0 = blockIdx.x * 128;
    A += (ll)m0 * lda;
    B += BT ? (ll)n0 * ldb : (ll)n0;

    const uint32_t smb = smem_u32(dynsm);

    auto issue = [&](int tile) {
        const int stage = tile % STAGES;
        const uint32_t sA = smb + (uint32_t)(stage * STAGE_F) * 4u;
        const uint32_t sB = sA + (uint32_t)A_F * 4u;
        const int k0 = tile * 32;
        #pragma unroll
        for (int i = 0; i < 8; i++) {            // A: 128x32, 8 float4/thread
            const int v = tid + i * 128;
            const int m = v >> 3, kc = (v & 7) * 4;
            cp16(sA + (uint32_t)(m * PA + kc) * 4u, A + (ll)m * lda + k0 + kc);
        }
        #pragma unroll
        for (int i = 0; i < 8; i++) {            // B: 128x32 (either orientation)
            const int v = tid + i * 128;
            if (BT) {
                const int n = v >> 3, kc = (v & 7) * 4;
                cp16(sB + (uint32_t)(n * PA + kc) * 4u, B + (ll)n * ldb + k0 + kc);
            } else {
                const int k = v >> 5, nc = (v & 31) * 4;
                cp16(sB + (uint32_t)(k * PB + nc) * 4u, B + (ll)(k0 + k) * ldb + nc);
            }
        }
        cp_commit();
    };

    float acc[4][8][4];
    #pragma unroll
    for (int mt = 0; mt < 4; mt++)
        #pragma unroll
        for (int nt = 0; nt < 8; nt++)
            #pragma unroll
            for (int rr = 0; rr < 4; rr++) acc[mt][nt][rr] = 0.f;

    const int T = K >> 5;
    issue(0); issue(1);

    for (int it = 0; it < T; ++it) {
        cp_wait<1>();
        __syncthreads();
        if (it + 2 < T) issue(it + 2);

        const uint32_t sA = smb + (uint32_t)((it % STAGES) * STAGE_F) * 4u;
        const uint32_t sB = sA + (uint32_t)A_F * 4u;
        const float* Bsm = dynsm + (it % STAGES) * STAGE_F + A_F;

        #pragma unroll
        for (int ksi = 0; ksi < 4; ksi++) {
            const int kk = ksi * 8 + tig;
            uint32_t a[4][4], b[8][2];
            #pragma unroll
            for (int mt = 0; mt < 4; mt++) {
                const int m = wm * 64 + mt * 16 + aRowOff;
                ldsm_x4(a[mt][0], a[mt][1], a[mt][2], a[mt][3],
                        sA + (uint32_t)(m * PA + ksi * 8 + aKOff) * 4u);
            }
            if (BT) {
                #pragma unroll
                for (int ntp = 0; ntp < 4; ntp++) {
                    const int n = wn * 64 + ntp * 16 + bRowOff;
                    ldsm_x4(b[2*ntp][0], b[2*ntp][1], b[2*ntp+1][0], b[2*ntp+1][1],
                            sB + (uint32_t)(n * PA + ksi * 8 + bKOff) * 4u);
                }
            } else {
                #pragma unroll
                for (int nt = 0; nt < 8; nt++) {
                    const int nB = wn * 64 + nt * 8 + g;
                    b[nt][0] = __float_as_uint(Bsm[(kk    ) * PB + nB]);
                    b[nt][1] = __float_as_uint(Bsm[(kk + 4) * PB + nB]);
                }
            }
            #pragma unroll
            for (int mt = 0; mt < 4; mt++)
                #pragma unroll
                for (int nt = 0; nt < 8; nt++)
                    mma_tf32(acc[mt][nt], a[mt][0], a[mt][1], a[mt][2], a[mt][3],
                             b[nt][0], b[nt][1]);
        }
    }

    // ---- epilogue ----
    #pragma unroll
    for (int mt = 0; mt < 4; mt++) {
        #pragma unroll
        for (int nt = 0; nt < 8; nt++) {
            const int n = n0 + wn * 64 + nt * 8 + tig * 2;
            float bv0 = 0.f, bv1 = 0.f;
            if (HASB) { bv0 = bias[n]; bv1 = bias[n + 1]; }
            #pragma unroll
            for (int h = 0; h < 2; h++) {
                const int m = m0 + wm * 64 + mt * 16 + g + h * 8;
                float x0 = alpha * acc[mt][nt][h * 2 + 0] + bv0;
                float x1 = alpha * acc[mt][nt][h * 2 + 1] + bv1;
                if (RELU) { x0 = fmaxf(x0, 0.f); x1 = fmaxf(x1, 0.f); }
                if (HASR) {
                    x0 += Res[(ll)m * ldr + n];
                    x1 += Res[(ll)m * ldr + n + 1];
                }
                if (ROUND) { x0 = to_tf32(x0); x1 = to_tf32(x1); }
                float2 w; w.x = x0; w.y = x1;
                *reinterpret_cast<float2*>(C + (ll)m * ldc + n) = w;
            }
        }
    }
}

// ---------------- split-K combine (3-way): out = P0 + P1 + P2 + bias + res ----------
__global__ void combine3_kernel(const float4* __restrict__ P0, const float4* __restrict__ P1,
                                const float4* __restrict__ P2,
                                const float* __restrict__ bias, const float4* __restrict__ res,
                                float4* __restrict__ out, int n4)
{
    const int i = blockIdx.x * blockDim.x + threadIdx.x;
    if (i >= n4) return;
    const int c = (i % (D_MODEL / 4)) * 4;
    const float4 p = P0[i], q = P1[i], s = P2[i], r = res[i];
    float4 o;
    o.x = p.x + q.x + s.x + bias[c + 0] + r.x;
    o.y = p.y + q.y + s.y + bias[c + 1] + r.y;
    o.z = p.z + q.z + s.z + bias[c + 2] + r.z;
    o.w = p.w + q.w + s.w + bias[c + 3] + r.w;
    out[i] = o;
}

// ---------------- layernorm (rounds output to tf32: it feeds GEMM A) ----------------
__global__ void layernorm_kernel(const float* __restrict__ x,
                                 const float* __restrict__ gm,
                                 const float* __restrict__ bt,
                                 float* __restrict__ y)
{
    const ll base = (ll)blockIdx.x * D_MODEL;
    const int t = threadIdx.x;
    float v[3];
    float lsum = 0.f, lsq = 0.f;
    #pragma unroll
    for (int i = 0; i < 3; i++) {
        v[i] = x[base + t + i * 256];
        lsum += v[i];
        lsq  += v[i] * v[i];
    }
    __shared__ float sh[16];
    #pragma unroll
    for (int o = 16; o; o >>= 1) {
        lsum += __shfl_xor_sync(0xffffffffu, lsum, o);
        lsq  += __shfl_xor_sync(0xffffffffu, lsq,  o);
    }
    const int wid = t >> 5, lane = t & 31;
    if (lane == 0) { sh[wid] = lsum; sh[8 + wid] = lsq; }
    __syncthreads();
    if (wid == 0) {
        float a = (lane < 8) ? sh[lane] : 0.f;
        float b = (lane < 8) ? sh[8 + lane] : 0.f;
        #pragma unroll
        for (int o = 4; o; o >>= 1) {
            a += __shfl_xor_sync(0xffffffffu, a, o);
            b += __shfl_xor_sync(0xffffffffu, b, o);
        }
        if (lane == 0) { sh[0] = a; sh[1] = b; }
    }
    __syncthreads();
    const float mu   = sh[0] * (1.f / D_MODEL);
    const float var  = sh[1] * (1.f / D_MODEL) - mu * mu;
    const float rstd = rsqrtf(var + LN_EPS);
    #pragma unroll
    for (int i = 0; i < 3; i++) {
        const int idx = t + i * 256;
        y[base + idx] = to_tf32((v[i] - mu) * rstd * gm[idx] + bt[idx]);
    }
}

// ---------------- row softmax over length-1024 rows (rounds output to tf32) --------
__global__ void softmax_kernel(float* __restrict__ S)
{
    float* p = S + (ll)blockIdx.x * SEQ;
    const int t = threadIdx.x;
    const int wid = t >> 5, lane = t & 31;
    __shared__ float sh[8];

    float v[4];
    float mx = -3.4e38f;
    #pragma unroll
    for (int i = 0; i < 4; i++) { v[i] = p[t + i * 256]; mx = fmaxf(mx, v[i]); }
    #pragma unroll
    for (int o = 16; o; o >>= 1) mx = fmaxf(mx, __shfl_xor_sync(0xffffffffu, mx, o));
    if (lane == 0) sh[wid] = mx;
    __syncthreads();
    if (wid == 0) {
        float a = (lane < 8) ? sh[lane] : -3.4e38f;
        #pragma unroll
        for (int o = 4; o; o >>= 1) a = fmaxf(a, __shfl_xor_sync(0xffffffffu, a, o));
        if (lane == 0) sh[0] = a;
    }
    __syncthreads();
    mx = sh[0];
    __syncthreads();

    float s = 0.f;
    #pragma unroll
    for (int i = 0; i < 4; i++) { v[i] = __expf(v[i] - mx); s += v[i]; }
    #pragma unroll
    for (int o = 16; o; o >>= 1) s += __shfl_xor_sync(0xffffffffu, s, o);
    if (lane == 0) sh[wid] = s;
    __syncthreads();
    if (wid == 0) {
        float a = (lane < 8) ? sh[lane] : 0.f;
        #pragma unroll
        for (int o = 4; o; o >>= 1) a += __shfl_xor_sync(0xffffffffu, a, o);
        if (lane == 0) sh[0] = a;
    }
    __syncthreads();
    const float inv = 1.f / sh[0];
    #pragma unroll
    for (int i = 0; i < 4; i++) p[t + i * 256] = to_tf32(v[i] * inv);
}

// ---------------- launch ----------------
#define SMEM_NN 107520   /* (128*36 + 32*136)*3st*4B */
#define SMEM_NT 110592   /* (128*36 + 128*36)*3st*4B */

extern "C" void kernel_launch(void* const* d_in, const int* in_sizes, int n_in,
                              void* d_out, int out_size)
{
    const float* x    = (const float*)d_in[0];
    const float* Wq   = (const float*)d_in[1];
    const float* Wk   = (const float*)d_in[2];
    const float* Wv   = (const float*)d_in[3];
    const float* Wu   = (const float*)d_in[4];
    const float* bu   = (const float*)d_in[5];
    const float* ln1g = (const float*)d_in[6];
    const float* ln1b = (const float*)d_in[7];
    const float* ln2g = (const float*)d_in[8];
    const float* ln2b = (const float*)d_in[9];
    const float* W1   = (const float*)d_in[10];
    const float* b1   = (const float*)d_in[11];
    const float* W2   = (const float*)d_in[12];
    const float* b2   = (const float*)d_in[13];
    float* out = (float*)d_out;

    float *Y, *Q, *Kp, *V, *S, *ATT, *X1, *H1;
    cudaGetSymbolAddress((void**)&Y,   g_Y);
    cudaGetSymbolAddress((void**)&Q,   g_Q);
    cudaGetSymbolAddress((void**)&Kp,  g_K);
    cudaGetSymbolAddress((void**)&V,   g_V);
    cudaGetSymbolAddress((void**)&S,   g_S);
    cudaGetSymbolAddress((void**)&ATT, g_ATT);
    cudaGetSymbolAddress((void**)&X1,  g_X1);
    cudaGetSymbolAddress((void**)&H1,  g_H1);

    // split-K partial buffers alias g_S (dead after PV GEMM)
    float* P0 = S;
    float* P1 = S + (size_t)NTOK * D_MODEL;
    float* P2 = S + (size_t)2 * NTOK * D_MODEL;

    cudaFuncSetAttribute(gemm_cp<false,false,false,false,true >, cudaFuncAttributeMaxDynamicSharedMemorySize, SMEM_NN);
    cudaFuncSetAttribute(gemm_cp<true ,false,false,false,false>, cudaFuncAttributeMaxDynamicSharedMemorySize, SMEM_NT);
    cudaFuncSetAttribute(gemm_cp<false,true ,true ,false,true >, cudaFuncAttributeMaxDynamicSharedMemorySize, SMEM_NN);
    cudaFuncSetAttribute(gemm_cp<false,false,false,false,false>, cudaFuncAttributeMaxDynamicSharedMemorySize, SMEM_NN);

    const float inv_sqrt_d = 0.03608439182435161f;   // 1/sqrt(768)

    // 0) LN1
    layernorm_kernel<<<NTOK, 256>>>(x, ln1g, ln1b, Y);

    // 1) Q/K/V = Y @ W{q,k,v}  (M=4096, N=9216, K=768)
    {
        dim3 grid(DH / 128, NTOK / 128, 1);
        gemm_cp<false,false,false,false,true><<<grid, 128, SMEM_NN>>>(Y, Wq, nullptr, nullptr, Q,
            D_MODEL, D_MODEL, DH, DH, 0, 1.f, 0,0,0,0,0,0,0,0, 1);
        gemm_cp<false,false,false,false,true><<<grid, 128, SMEM_NN>>>(Y, Wk, nullptr, nullptr, Kp,
            D_MODEL, D_MODEL, DH, DH, 0, 1.f, 0,0,0,0,0,0,0,0, 1);
        gemm_cp<false,false,false,false,true><<<grid, 128, SMEM_NN>>>(Y, Wv, nullptr, nullptr, V,
            D_MODEL, D_MODEL, DH, DH, 0, 1.f, 0,0,0,0,0,0,0,0, 1);
    }

    // 2) S[b,h] = (Q_bh @ K_bh^T)/sqrt(768)  (M=N=1024, K=768, batch=48; NT)
    {
        dim3 grid(SEQ / 128, SEQ / 128, BATCH * NHEAD);
        gemm_cp<true,false,false,false,false><<<grid, 128, SMEM_NT>>>(Q, Kp, nullptr, nullptr, S,
            D_MODEL, DH, DH, SEQ, 0, inv_sqrt_d,
            (ll)SEQ * DH, (ll)D_MODEL,
            (ll)SEQ * DH, (ll)D_MODEL,
            (ll)NHEAD * SEQ * SEQ, (ll)SEQ * SEQ,
            0, 0, NHEAD);
    }

    // 3) softmax (rounds P to tf32)
    softmax_kernel<<<BATCH * NHEAD * SEQ, 256>>>(S);

    // 4) ATT[b,:,h,:] = P_bh @ V_bh  (M=1024, N=768, K=1024, batch=48; NN)
    {
        dim3 grid(D_MODEL / 128, SEQ / 128, BATCH * NHEAD);
        gemm_cp<false,false,false,false,true><<<grid, 128, SMEM_NN>>>(S, V, nullptr, nullptr, ATT,
            SEQ, SEQ, DH, DH, 0, 1.f,
            (ll)NHEAD * SEQ * SEQ, (ll)SEQ * SEQ,
            (ll)SEQ * DH, (ll)D_MODEL,
            (ll)SEQ * DH, (ll)D_MODEL,
            0, 0, NHEAD);
    }

    // 5) Wu split-K=3: partials (batched via z), then X1 = P0+P1+P2 + bu + x
    {
        dim3 grid(D_MODEL / 128, NTOK / 128, 3);
        gemm_cp<false,false,false,false,false><<<grid, 128, SMEM_NN>>>(ATT, Wu,
            nullptr, nullptr, P0, DH/3, DH, D_MODEL, D_MODEL, 0, 1.f,
            0, (ll)(DH/3),
            0, (ll)(DH/3) * D_MODEL,
            0, (ll)NTOK * D_MODEL,
            0, 0, 3);
        const int n4 = NTOK * D_MODEL / 4;
        combine3_kernel<<<(n4 + 255) / 256, 256>>>((const float4*)P0, (const float4*)P1,
                                                   (const float4*)P2, bu,
                                                   (const float4*)x, (float4*)X1, n4);
    }

    // 6) LN2
    layernorm_kernel<<<NTOK, 256>>>(X1, ln2g, ln2b, Y);

    // 7) H1 = relu(Y @ W1 + b1)  (M=4096, N=3072, K=768)
    {
        dim3 grid(DFF / 128, NTOK / 128, 1);
        gemm_cp<false,true,true,false,true><<<grid, 128, SMEM_NN>>>(Y, W1, b1, nullptr, H1,
            D_MODEL, D_MODEL, DFF, DFF, 0, 1.f, 0,0,0,0,0,0,0,0, 1);
    }

    // 8) W2 split-K=3: partials, then out = P0+P1+P2 + b2 + X1
    {
        dim3 grid(D_MODEL / 128, NTOK / 128, 3);
        gemm_cp<false,false,false,false,false><<<grid, 128, SMEM_NN>>>(H1, W2,
            nullptr, nullptr, P0, DFF/3, DFF, D_MODEL, D_MODEL, 0, 1.f,
            0, (ll)(DFF/3),
            0, (ll)(DFF/3) * D_MODEL,
            0, (ll)NTOK * D_MODEL,
            0, 0, 3);
        const int n4 = NTOK * D_MODEL / 4;
        combine3_kernel<<<(n4 + 255) / 256, 256>>>((const float4*)P0, (const float4*)P1,
                                                   (const float4*)P2, b2,
                                                   (const float4*)X1, (float4*)out, n4);
    }

    (void)in_sizes; (void)n_in; (void)out_size;
}

// round 11
// speedup vs baseline: 1.1223x; 1.0012x over previous
#include <cuda_runtime.h>
#include <cstdint>

#define D_MODEL 768
#define NHEAD   12
#define SEQ     1024
#define BATCH   4
#define NTOK    (BATCH*SEQ)        /* 4096 */
#define DH      (D_MODEL*NHEAD)    /* 9216 */
#define DFF     (4*D_MODEL)        /* 3072 */
#define LN_EPS  1e-5f

typedef long long ll;

// ---------------- scratch (device globals; no allocation allowed) ----------------
__device__ float g_Y  [(size_t)NTOK * D_MODEL];
__device__ float g_Q  [(size_t)NTOK * DH];
__device__ float g_K  [(size_t)NTOK * DH];
__device__ float g_V  [(size_t)NTOK * DH];
__device__ float g_S  [(size_t)BATCH * NHEAD * SEQ * SEQ];   // scores; later aliased as split-K partials
__device__ float g_ATT[(size_t)NTOK * DH];
__device__ float g_X1 [(size_t)NTOK * D_MODEL];
__device__ float g_H1 [(size_t)NTOK * DFF];

// ---------------- helpers ----------------
__device__ __forceinline__ float to_tf32(float x) {
    uint32_t u;
    asm("cvt.rna.tf32.f32 %0, %1;" : "=r"(u) : "f"(x));
    return __uint_as_float(u);
}
__device__ __forceinline__ uint32_t smem_u32(const void* p) {
    uint32_t a;
    asm("{ .reg .u64 t; cvta.to.shared.u64 t, %1; cvt.u32.u64 %0, t; }" : "=r"(a) : "l"(p));
    return a;
}
__device__ __forceinline__ void cp16(uint32_t dst, const void* src) {
    asm volatile("cp.async.cg.shared.global [%0], [%1], 16;" :: "r"(dst), "l"(src) : "memory");
}
__device__ __forceinline__ void cp_commit() {
    asm volatile("cp.async.commit_group;" ::: "memory");
}
template<int N>
__device__ __forceinline__ void cp_wait() {
    asm volatile("cp.async.wait_group %0;" :: "n"(N) : "memory");
}
__device__ __forceinline__ void ldsm_x4(uint32_t& r0, uint32_t& r1, uint32_t& r2, uint32_t& r3,
                                        uint32_t addr) {
    asm volatile("ldmatrix.sync.aligned.m8n8.x4.shared.b16 {%0,%1,%2,%3}, [%4];"
                 : "=r"(r0), "=r"(r1), "=r"(r2), "=r"(r3) : "r"(addr));
}
__device__ __forceinline__ void mma_tf32(float c[4],
                                         uint32_t a0, uint32_t a1, uint32_t a2, uint32_t a3,
                                         uint32_t b0, uint32_t b1) {
    asm("mma.sync.aligned.m16n8k8.row.col.f32.tf32.tf32.f32 "
        "{%0,%1,%2,%3}, {%4,%5,%6,%7}, {%8,%9}, {%0,%1,%2,%3};"
        : "+f"(c[0]), "+f"(c[1]), "+f"(c[2]), "+f"(c[3])
        : "r"(a0), "r"(a1), "r"(a2), "r"(a3), "r"(b0), "r"(b1));
}

// ---------------- tf32 tensor-core GEMM, cp.async 3-stage, 2 CTAs/SM, ldmatrix -----
// (unchanged from R10 — committed win; do not touch)
template<bool BT, bool RELU, bool HASB, bool HASR, bool ROUND>
__global__ __launch_bounds__(128, 2)
void gemm_cp(const float* __restrict__ A, const float* __restrict__ B,
             const float* __restrict__ bias, const float* __restrict__ Res,
             float* __restrict__ C,
             int K, int lda, int ldb, int ldc, int ldr, float alpha,
             ll saO, ll saI, ll sbO, ll sbI, ll scO, ll scI, ll srO, ll srI,
             int innerCnt)
{
    constexpr int STAGES  = 3;
    constexpr int PA      = 36;                  // A / B-NT pitch
    constexpr int PB      = 136;                 // B-NN pitch
    constexpr int A_F     = 128 * PA;            // 4608 floats
    constexpr int B_F     = BT ? 128 * PA : 32 * PB;
    constexpr int STAGE_F = A_F + B_F;

    extern __shared__ float dynsm[];

    const int tid  = threadIdx.x;
    const int wid  = tid >> 5;
    const int lane = tid & 31;
    const int g    = lane >> 2;
    const int tig  = lane & 3;
    const int wm   = wid >> 1;                   // 0..1
    const int wn   = wid & 1;                    // 0..1

    const int mi = lane >> 3;
    const int r8 = lane & 7;
    const int aRowOff = (mi & 1) * 8 + r8;
    const int aKOff   = (mi >> 1) * 4;
    const int bRowOff = (mi >> 1) * 8 + r8;
    const int bKOff   = (mi & 1) * 4;

    const int z  = blockIdx.z;
    const int zo = z / innerCnt;
    const int zi = z - zo * innerCnt;
    A += zo * saO + zi * saI;
    B += zo * sbO + zi * sbI;
    C += zo * scO + zi * scI;
    if (HASR) Res += zo * srO + zi * srI;

    const int m0 = blockIdx.y * 128;
    const int n0 = blockIdx.x * 128;
    A += (ll)m0 * lda;
    B += BT ? (ll)n0 * ldb : (ll)n0;

    const uint32_t smb = smem_u32(dynsm);

    auto issue = [&](int tile) {
        const int stage = tile % STAGES;
        const uint32_t sA = smb + (uint32_t)(stage * STAGE_F) * 4u;
        const uint32_t sB = sA + (uint32_t)A_F * 4u;
        const int k0 = tile * 32;
        #pragma unroll
        for (int i = 0; i < 8; i++) {
            const int v = tid + i * 128;
            const int m = v >> 3, kc = (v & 7) * 4;
            cp16(sA + (uint32_t)(m * PA + kc) * 4u, A + (ll)m * lda + k0 + kc);
        }
        #pragma unroll
        for (int i = 0; i < 8; i++) {
            const int v = tid + i * 128;
            if (BT) {
                const int n = v >> 3, kc = (v & 7) * 4;
                cp16(sB + (uint32_t)(n * PA + kc) * 4u, B + (ll)n * ldb + k0 + kc);
            } else {
                const int k = v >> 5, nc = (v & 31) * 4;
                cp16(sB + (uint32_t)(k * PB + nc) * 4u, B + (ll)(k0 + k) * ldb + nc);
            }
        }
        cp_commit();
    };

    float acc[4][8][4];
    #pragma unroll
    for (int mt = 0; mt < 4; mt++)
        #pragma unroll
        for (int nt = 0; nt < 8; nt++)
            #pragma unroll
            for (int rr = 0; rr < 4; rr++) acc[mt][nt][rr] = 0.f;

    const int T = K >> 5;
    issue(0); issue(1);

    for (int it = 0; it < T; ++it) {
        cp_wait<1>();
        __syncthreads();
        if (it + 2 < T) issue(it + 2);

        const uint32_t sA = smb + (uint32_t)((it % STAGES) * STAGE_F) * 4u;
        const uint32_t sB = sA + (uint32_t)A_F * 4u;
        const float* Bsm = dynsm + (it % STAGES) * STAGE_F + A_F;

        #pragma unroll
        for (int ksi = 0; ksi < 4; ksi++) {
            const int kk = ksi * 8 + tig;
            uint32_t a[4][4], b[8][2];
            #pragma unroll
            for (int mt = 0; mt < 4; mt++) {
                const int m = wm * 64 + mt * 16 + aRowOff;
                ldsm_x4(a[mt][0], a[mt][1], a[mt][2], a[mt][3],
                        sA + (uint32_t)(m * PA + ksi * 8 + aKOff) * 4u);
            }
            if (BT) {
                #pragma unroll
                for (int ntp = 0; ntp < 4; ntp++) {
                    const int n = wn * 64 + ntp * 16 + bRowOff;
                    ldsm_x4(b[2*ntp][0], b[2*ntp][1], b[2*ntp+1][0], b[2*ntp+1][1],
                            sB + (uint32_t)(n * PA + ksi * 8 + bKOff) * 4u);
                }
            } else {
                #pragma unroll
                for (int nt = 0; nt < 8; nt++) {
                    const int nB = wn * 64 + nt * 8 + g;
                    b[nt][0] = __float_as_uint(Bsm[(kk    ) * PB + nB]);
                    b[nt][1] = __float_as_uint(Bsm[(kk + 4) * PB + nB]);
                }
            }
            #pragma unroll
            for (int mt = 0; mt < 4; mt++)
                #pragma unroll
                for (int nt = 0; nt < 8; nt++)
                    mma_tf32(acc[mt][nt], a[mt][0], a[mt][1], a[mt][2], a[mt][3],
                             b[nt][0], b[nt][1]);
        }
    }

    // ---- epilogue ----
    #pragma unroll
    for (int mt = 0; mt < 4; mt++) {
        #pragma unroll
        for (int nt = 0; nt < 8; nt++) {
            const int n = n0 + wn * 64 + nt * 8 + tig * 2;
            float bv0 = 0.f, bv1 = 0.f;
            if (HASB) { bv0 = bias[n]; bv1 = bias[n + 1]; }
            #pragma unroll
            for (int h = 0; h < 2; h++) {
                const int m = m0 + wm * 64 + mt * 16 + g + h * 8;
                float x0 = alpha * acc[mt][nt][h * 2 + 0] + bv0;
                float x1 = alpha * acc[mt][nt][h * 2 + 1] + bv1;
                if (RELU) { x0 = fmaxf(x0, 0.f); x1 = fmaxf(x1, 0.f); }
                if (HASR) {
                    x0 += Res[(ll)m * ldr + n];
                    x1 += Res[(ll)m * ldr + n + 1];
                }
                if (ROUND) { x0 = to_tf32(x0); x1 = to_tf32(x1); }
                float2 w; w.x = x0; w.y = x1;
                *reinterpret_cast<float2*>(C + (ll)m * ldc + n) = w;
            }
        }
    }
}

// ---------------- split-K combine (3-way): out = P0 + P1 + P2 + bias + res ----------
__global__ void combine3_kernel(const float4* __restrict__ P0, const float4* __restrict__ P1,
                                const float4* __restrict__ P2,
                                const float* __restrict__ bias, const float4* __restrict__ res,
                                float4* __restrict__ out, int n4)
{
    const int i = blockIdx.x * blockDim.x + threadIdx.x;
    if (i >= n4) return;
    const int c = (i % (D_MODEL / 4)) * 4;
    const float4 p = P0[i], q = P1[i], s = P2[i], r = res[i];
    float4 o;
    o.x = p.x + q.x + s.x + bias[c + 0] + r.x;
    o.y = p.y + q.y + s.y + bias[c + 1] + r.y;
    o.z = p.z + q.z + s.z + bias[c + 2] + r.z;
    o.w = p.w + q.w + s.w + bias[c + 3] + r.w;
    out[i] = o;
}

// ---------------- layernorm: 192 threads x float4 (D=768), rounds output to tf32 ----
__global__ void layernorm_kernel(const float4* __restrict__ x,
                                 const float4* __restrict__ gm,
                                 const float4* __restrict__ bt,
                                 float4* __restrict__ y)
{
    const ll base = (ll)blockIdx.x * (D_MODEL / 4);
    const int t = threadIdx.x;                    // 0..191
    const float4 v = x[base + t];
    float lsum = v.x + v.y + v.z + v.w;
    float lsq  = v.x * v.x + v.y * v.y + v.z * v.z + v.w * v.w;

    __shared__ float sh[12];
    #pragma unroll
    for (int o = 16; o; o >>= 1) {
        lsum += __shfl_xor_sync(0xffffffffu, lsum, o);
        lsq  += __shfl_xor_sync(0xffffffffu, lsq,  o);
    }
    const int wid = t >> 5, lane = t & 31;        // 6 warps
    if (lane == 0) { sh[wid] = lsum; sh[6 + wid] = lsq; }
    __syncthreads();
    if (wid == 0) {
        float a = (lane < 6) ? sh[lane] : 0.f;
        float b = (lane < 6) ? sh[6 + lane] : 0.f;
        #pragma unroll
        for (int o = 4; o; o >>= 1) {
            a += __shfl_xor_sync(0xffffffffu, a, o);
            b += __shfl_xor_sync(0xffffffffu, b, o);
        }
        if (lane == 0) { sh[0] = a; sh[1] = b; }
    }
    __syncthreads();
    const float mu   = sh[0] * (1.f / D_MODEL);
    const float var  = sh[1] * (1.f / D_MODEL) - mu * mu;
    const float rstd = rsqrtf(var + LN_EPS);

    const float4 gv = gm[t];
    const float4 bv = bt[t];
    float4 o;
    o.x = to_tf32((v.x - mu) * rstd * gv.x + bv.x);
    o.y = to_tf32((v.y - mu) * rstd * gv.y + bv.y);
    o.z = to_tf32((v.z - mu) * rstd * gv.z + bv.z);
    o.w = to_tf32((v.w - mu) * rstd * gv.w + bv.w);
    y[base + t] = o;
}

// ---------------- row softmax, 256 threads x float4 (rows of 1024), tf32 output ----
__global__ void softmax_kernel(float4* __restrict__ S)
{
    float4* p = S + (ll)blockIdx.x * (SEQ / 4);
    const int t = threadIdx.x;
    const int wid = t >> 5, lane = t & 31;
    __shared__ float sh[8];

    float4 v = p[t];
    float mx = fmaxf(fmaxf(v.x, v.y), fmaxf(v.z, v.w));
    #pragma unroll
    for (int o = 16; o; o >>= 1) mx = fmaxf(mx, __shfl_xor_sync(0xffffffffu, mx, o));
    if (lane == 0) sh[wid] = mx;
    __syncthreads();
    {
        float a = sh[lane & 7];
        #pragma unroll
        for (int o = 4; o; o >>= 1) a = fmaxf(a, __shfl_xor_sync(0xffffffffu, a, o));
        mx = a;
    }

    v.x = __expf(v.x - mx); v.y = __expf(v.y - mx);
    v.z = __expf(v.z - mx); v.w = __expf(v.w - mx);
    float s = v.x + v.y + v.z + v.w;
    #pragma unroll
    for (int o = 16; o; o >>= 1) s += __shfl_xor_sync(0xffffffffu, s, o);
    __syncthreads();                               // protect sh reuse
    if (lane == 0) sh[wid] = s;
    __syncthreads();
    {
        float a = sh[lane & 7];
        #pragma unroll
        for (int o = 4; o; o >>= 1) a += __shfl_xor_sync(0xffffffffu, a, o);
        s = a;
    }
    const float inv = 1.f / s;
    float4 o;
    o.x = to_tf32(v.x * inv); o.y = to_tf32(v.y * inv);
    o.z = to_tf32(v.z * inv); o.w = to_tf32(v.w * inv);
    p[t] = o;
}

// ---------------- launch ----------------
#define SMEM_NN 107520   /* (128*36 + 32*136)*3st*4B */
#define SMEM_NT 110592   /* (128*36 + 128*36)*3st*4B */

extern "C" void kernel_launch(void* const* d_in, const int* in_sizes, int n_in,
                              void* d_out, int out_size)
{
    const float* x    = (const float*)d_in[0];
    const float* Wq   = (const float*)d_in[1];
    const float* Wk   = (const float*)d_in[2];
    const float* Wv   = (const float*)d_in[3];
    const float* Wu   = (const float*)d_in[4];
    const float* bu   = (const float*)d_in[5];
    const float* ln1g = (const float*)d_in[6];
    const float* ln1b = (const float*)d_in[7];
    const float* ln2g = (const float*)d_in[8];
    const float* ln2b = (const float*)d_in[9];
    const float* W1   = (const float*)d_in[10];
    const float* b1   = (const float*)d_in[11];
    const float* W2   = (const float*)d_in[12];
    const float* b2   = (const float*)d_in[13];
    float* out = (float*)d_out;

    float *Y, *Q, *Kp, *V, *S, *ATT, *X1, *H1;
    cudaGetSymbolAddress((void**)&Y,   g_Y);
    cudaGetSymbolAddress((void**)&Q,   g_Q);
    cudaGetSymbolAddress((void**)&Kp,  g_K);
    cudaGetSymbolAddress((void**)&V,   g_V);
    cudaGetSymbolAddress((void**)&S,   g_S);
    cudaGetSymbolAddress((void**)&ATT, g_ATT);
    cudaGetSymbolAddress((void**)&X1,  g_X1);
    cudaGetSymbolAddress((void**)&H1,  g_H1);

    // split-K partial buffers alias g_S (dead after PV GEMM)
    float* P0 = S;
    float* P1 = S + (size_t)NTOK * D_MODEL;
    float* P2 = S + (size_t)2 * NTOK * D_MODEL;

    cudaFuncSetAttribute(gemm_cp<false,false,false,false,true >, cudaFuncAttributeMaxDynamicSharedMemorySize, SMEM_NN);
    cudaFuncSetAttribute(gemm_cp<true ,false,false,false,false>, cudaFuncAttributeMaxDynamicSharedMemorySize, SMEM_NT);
    cudaFuncSetAttribute(gemm_cp<false,true ,true ,false,true >, cudaFuncAttributeMaxDynamicSharedMemorySize, SMEM_NN);
    cudaFuncSetAttribute(gemm_cp<false,false,false,false,false>, cudaFuncAttributeMaxDynamicSharedMemorySize, SMEM_NN);

    const float inv_sqrt_d = 0.03608439182435161f;   // 1/sqrt(768)

    // 0) LN1
    layernorm_kernel<<<NTOK, 192>>>((const float4*)x, (const float4*)ln1g,
                                    (const float4*)ln1b, (float4*)Y);

    // 1) Q/K/V = Y @ W{q,k,v}  (M=4096, N=9216, K=768)
    {
        dim3 grid(DH / 128, NTOK / 128, 1);
        gemm_cp<false,false,false,false,true><<<grid, 128, SMEM_NN>>>(Y, Wq, nullptr, nullptr, Q,
            D_MODEL, D_MODEL, DH, DH, 0, 1.f, 0,0,0,0,0,0,0,0, 1);
        gemm_cp<false,false,false,false,true><<<grid, 128, SMEM_NN>>>(Y, Wk, nullptr, nullptr, Kp,
            D_MODEL, D_MODEL, DH, DH, 0, 1.f, 0,0,0,0,0,0,0,0, 1);
        gemm_cp<false,false,false,false,true><<<grid, 128, SMEM_NN>>>(Y, Wv, nullptr, nullptr, V,
            D_MODEL, D_MODEL, DH, DH, 0, 1.f, 0,0,0,0,0,0,0,0, 1);
    }

    // 2) S[b,h] = (Q_bh @ K_bh^T)/sqrt(768)  (M=N=1024, K=768, batch=48; NT)
    {
        dim3 grid(SEQ / 128, SEQ / 128, BATCH * NHEAD);
        gemm_cp<true,false,false,false,false><<<grid, 128, SMEM_NT>>>(Q, Kp, nullptr, nullptr, S,
            D_MODEL, DH, DH, SEQ, 0, inv_sqrt_d,
            (ll)SEQ * DH, (ll)D_MODEL,
            (ll)SEQ * DH, (ll)D_MODEL,
            (ll)NHEAD * SEQ * SEQ, (ll)SEQ * SEQ,
            0, 0, NHEAD);
    }

    // 3) softmax (float4, rounds P to tf32)
    softmax_kernel<<<BATCH * NHEAD * SEQ, 256>>>((float4*)S);

    // 4) ATT[b,:,h,:] = P_bh @ V_bh  (M=1024, N=768, K=1024, batch=48; NN)
    {
        dim3 grid(D_MODEL / 128, SEQ / 128, BATCH * NHEAD);
        gemm_cp<false,false,false,false,true><<<grid, 128, SMEM_NN>>>(S, V, nullptr, nullptr, ATT,
            SEQ, SEQ, DH, DH, 0, 1.f,
            (ll)NHEAD * SEQ * SEQ, (ll)SEQ * SEQ,
            (ll)SEQ * DH, (ll)D_MODEL,
            (ll)SEQ * DH, (ll)D_MODEL,
            0, 0, NHEAD);
    }

    // 5) Wu split-K=3: partials (batched via z), then X1 = P0+P1+P2 + bu + x
    {
        dim3 grid(D_MODEL / 128, NTOK / 128, 3);
        gemm_cp<false,false,false,false,false><<<grid, 128, SMEM_NN>>>(ATT, Wu,
            nullptr, nullptr, P0, DH/3, DH, D_MODEL, D_MODEL, 0, 1.f,
            0, (ll)(DH/3),
            0, (ll)(DH/3) * D_MODEL,
            0, (ll)NTOK * D_MODEL,
            0, 0, 3);
        const int n4 = NTOK * D_MODEL / 4;
        combine3_kernel<<<(n4 + 255) / 256, 256>>>((const float4*)P0, (const float4*)P1,
                                                   (const float4*)P2, bu,
                                                   (const float4*)x, (float4*)X1, n4);
    }

    // 6) LN2
    layernorm_kernel<<<NTOK, 192>>>((const float4*)X1, (const float4*)ln2g,
                                    (const float4*)ln2b, (float4*)Y);

    // 7) H1 = relu(Y @ W1 + b1)  (M=4096, N=3072, K=768)
    {
        dim3 grid(DFF / 128, NTOK / 128, 1);
        gemm_cp<false,true,true,false,true><<<grid, 128, SMEM_NN>>>(Y, W1, b1, nullptr, H1,
            D_MODEL, D_MODEL, DFF, DFF, 0, 1.f, 0,0,0,0,0,0,0,0, 1);
    }

    // 8) W2 split-K=3: partials, then out = P0+P1+P2 + b2 + X1
    {
        dim3 grid(D_MODEL / 128, NTOK / 128, 3);
        gemm_cp<false,false,false,false,false><<<grid, 128, SMEM_NN>>>(H1, W2,
            nullptr, nullptr, P0, DFF/3, DFF, D_MODEL, D_MODEL, 0, 1.f,
            0, (ll)(DFF/3),
            0, (ll)(DFF/3) * D_MODEL,
            0, (ll)NTOK * D_MODEL,
            0, 0, 3);
        const int n4 = NTOK * D_MODEL / 4;
        combine3_kernel<<<(n4 + 255) / 256, 256>>>((const float4*)P0, (const float4*)P1,
                                                   (const float4*)P2, b2,
                                                   (const float4*)X1, (float4*)out, n4);
    }

    (void)in_sizes; (void)n_in; (void)out_size;
}

// round 12
// speedup vs baseline: 1.9104x; 1.7022x over previous
#include <cuda_runtime.h>
#include <cuda_fp16.h>
#include <cstdint>

#define D_MODEL 768
#define NHEAD   12
#define SEQ     1024
#define BATCH   4
#define NTOK    (BATCH*SEQ)        /* 4096 */
#define DH      (D_MODEL*NHEAD)    /* 9216 */
#define DFF     (4*D_MODEL)        /* 3072 */
#define LN_EPS  1e-5f

typedef long long ll;

// ---------------- scratch (device globals; no allocation allowed) ----------------
__device__ __half g_Yh  [(size_t)NTOK * D_MODEL];
__device__ __half g_Qh  [(size_t)NTOK * DH];
__device__ __half g_Kh  [(size_t)NTOK * DH];
__device__ __half g_Vh  [(size_t)NTOK * DH];
__device__ __half g_Sh  [(size_t)BATCH * NHEAD * SEQ * SEQ];
__device__ __half g_ATTh[(size_t)NTOK * DH];
__device__ __half g_H1h [(size_t)NTOK * DFF];
__device__ float  g_X1  [(size_t)NTOK * D_MODEL];
__device__ float  g_P   [(size_t)3 * NTOK * D_MODEL];     // split-K partials
__device__ __half g_WqH [(size_t)D_MODEL * DH];
__device__ __half g_WkH [(size_t)D_MODEL * DH];
__device__ __half g_WvH [(size_t)D_MODEL * DH];
__device__ __half g_WuH [(size_t)DH * D_MODEL];
__device__ __half g_W1H [(size_t)D_MODEL * DFF];
__device__ __half g_W2H [(size_t)DFF * D_MODEL];

// ---------------- helpers ----------------
__device__ __forceinline__ uint32_t smem_u32(const void* p) {
    uint32_t a;
    asm("{ .reg .u64 t; cvta.to.shared.u64 t, %1; cvt.u32.u64 %0, t; }" : "=r"(a) : "l"(p));
    return a;
}
__device__ __forceinline__ void cp16(uint32_t dst, const void* src) {
    asm volatile("cp.async.cg.shared.global [%0], [%1], 16;" :: "r"(dst), "l"(src) : "memory");
}
__device__ __forceinline__ void cp_commit() {
    asm volatile("cp.async.commit_group;" ::: "memory");
}
template<int N>
__device__ __forceinline__ void cp_wait() {
    asm volatile("cp.async.wait_group %0;" :: "n"(N) : "memory");
}
__device__ __forceinline__ void ldsm_x4(uint32_t& r0, uint32_t& r1, uint32_t& r2, uint32_t& r3,
                                        uint32_t addr) {
    asm volatile("ldmatrix.sync.aligned.m8n8.x4.shared.b16 {%0,%1,%2,%3}, [%4];"
                 : "=r"(r0), "=r"(r1), "=r"(r2), "=r"(r3) : "r"(addr));
}
__device__ __forceinline__ void ldsm_x4_t(uint32_t& r0, uint32_t& r1, uint32_t& r2, uint32_t& r3,
                                          uint32_t addr) {
    asm volatile("ldmatrix.sync.aligned.m8n8.x4.trans.shared.b16 {%0,%1,%2,%3}, [%4];"
                 : "=r"(r0), "=r"(r1), "=r"(r2), "=r"(r3) : "r"(addr));
}
__device__ __forceinline__ void mma_f16(float c[4],
                                        uint32_t a0, uint32_t a1, uint32_t a2, uint32_t a3,
                                        uint32_t b0, uint32_t b1) {
    asm("mma.sync.aligned.m16n8k16.row.col.f32.f16.f16.f32 "
        "{%0,%1,%2,%3}, {%4,%5,%6,%7}, {%8,%9}, {%0,%1,%2,%3};"
        : "+f"(c[0]), "+f"(c[1]), "+f"(c[2]), "+f"(c[3])
        : "r"(a0), "r"(a1), "r"(a2), "r"(a3), "r"(b0), "r"(b1));
}

// ---------------- fp16 tensor-core GEMM, cp.async 3-stage, 2 CTAs/SM, ldmatrix -----
// C[m,n] = epi( alpha * sum_k A[m,k] * B(k,n) ), fp16 operands, fp32 accumulate.
//   BT=false: B is K x N row-major (ldmatrix.trans).  BT=true: B is N x K (A @ B^T).
// CTA tile 128x128x64(halves), 128 threads (4 warps 2x2), warp tile 64x64,
// mma.m16n8k16. smem rows 16B-aligned, 4-word bank stride -> conflict-free LDSM.
// smem A / B-NT: [m|n][k] pitch 72 halves (144B). B-NN: [k][n] pitch 136 halves.
// OUT_HALF: write __half2 (activations); else float2 (split-K partials).
template<bool BT, bool RELU, bool HASB, bool OUT_HALF>
__global__ __launch_bounds__(128, 2)
void gemm_h(const __half* __restrict__ A, const __half* __restrict__ B,
            const float* __restrict__ bias, void* __restrict__ Cv,
            int K, int lda, int ldb, int ldc, float alpha,
            ll saO, ll saI, ll sbO, ll sbI, ll scO, ll scI, int innerCnt)
{
    constexpr int STAGES  = 3;
    constexpr int PAH     = 72;                   // A / B-NT pitch (halves)
    constexpr int PBH     = 136;                  // B-NN pitch (halves)
    constexpr int A_H     = 128 * PAH;            // 9216 halves
    constexpr int B_H     = BT ? 128 * PAH : 64 * PBH;
    constexpr int STAGE_H = A_H + B_H;

    extern __shared__ __half dynsm[];

    const int tid  = threadIdx.x;
    const int wid  = tid >> 5;
    const int lane = tid & 31;
    const int g    = lane >> 2;
    const int tig  = lane & 3;
    const int wm   = wid >> 1;                    // 0..1
    const int wn   = wid & 1;                     // 0..1

    const int mi = lane >> 3;
    const int r8 = lane & 7;
    const int aRowOff = (mi & 1) * 8 + r8;        // A: m-row within 16-block
    const int aK8     = (mi >> 1) * 8;            // A: k-offset (halves)
    const int bRowOff = (mi >> 1) * 8 + r8;       // B-NT: n-row within 16-block
    const int bK8     = (mi & 1) * 8;             // B-NT: k-offset
    const int cKRow   = (mi & 1) * 8 + r8;        // B-NN: k-row within 16-block
    const int cN8     = (mi >> 1) * 8;            // B-NN: n-offset

    const int z  = blockIdx.z;
    const int zo = z / innerCnt;
    const int zi = z - zo * innerCnt;
    A += zo * saO + zi * saI;
    B += zo * sbO + zi * sbI;
    __half* Ch = (__half*)Cv + zo * scO + zi * scI;
    float*  Cf = (float*) Cv + zo * scO + zi * scI;

    const int m0 = blockIdx.y * 128;
    const int n0 = blockIdx.x * 128;
    A += (ll)m0 * lda;
    B += BT ? (ll)n0 * ldb : (ll)n0;

    const uint32_t smb = smem_u32(dynsm);

    auto issue = [&](int tile) {
        const int stage = tile % STAGES;
        const uint32_t sA = smb + (uint32_t)(stage * STAGE_H) * 2u;
        const uint32_t sB = sA + (uint32_t)A_H * 2u;
        const int k0 = tile * 64;
        #pragma unroll
        for (int i = 0; i < 8; i++) {             // A: 128 rows x 64 halves, 8 chunks/thr
            const int v = tid + i * 128;
            const int m = v >> 3, c = (v & 7) * 8;
            cp16(sA + (uint32_t)(m * PAH + c) * 2u, A + (ll)m * lda + k0 + c);
        }
        #pragma unroll
        for (int i = 0; i < 8; i++) {
            const int v = tid + i * 128;
            if (BT) {                              // B: 128 n-rows x 64 halves
                const int n = v >> 3, c = (v & 7) * 8;
                cp16(sB + (uint32_t)(n * PAH + c) * 2u, B + (ll)n * ldb + k0 + c);
            } else {                               // B: 64 k-rows x 128 halves
                const int k = v >> 4, c = (v & 15) * 8;
                cp16(sB + (uint32_t)(k * PBH + c) * 2u, B + (ll)(k0 + k) * ldb + c);
            }
        }
        cp_commit();
    };

    float acc[4][8][4];
    #pragma unroll
    for (int mt = 0; mt < 4; mt++)
        #pragma unroll
        for (int nt = 0; nt < 8; nt++)
            #pragma unroll
            for (int rr = 0; rr < 4; rr++) acc[mt][nt][rr] = 0.f;

    const int T = K >> 6;
    issue(0); issue(1);

    for (int it = 0; it < T; ++it) {
        cp_wait<1>();
        __syncthreads();
        if (it + 2 < T) issue(it + 2);

        const uint32_t sA = smb + (uint32_t)((it % STAGES) * STAGE_H) * 2u;
        const uint32_t sB = sA + (uint32_t)A_H * 2u;

        #pragma unroll
        for (int ksi = 0; ksi < 4; ksi++) {        // k16 per step
            uint32_t a[4][4], b[8][2];
            #pragma unroll
            for (int mt = 0; mt < 4; mt++) {
                const int m = wm * 64 + mt * 16 + aRowOff;
                ldsm_x4(a[mt][0], a[mt][1], a[mt][2], a[mt][3],
                        sA + (uint32_t)(m * PAH + ksi * 16 + aK8) * 2u);
            }
            if (BT) {
                #pragma unroll
                for (int ntp = 0; ntp < 4; ntp++) {
                    const int n = wn * 64 + ntp * 16 + bRowOff;
                    ldsm_x4(b[2*ntp][0], b[2*ntp][1], b[2*ntp+1][0], b[2*ntp+1][1],
                            sB + (uint32_t)(n * PAH + ksi * 16 + bK8) * 2u);
                }
            } else {
                #pragma unroll
                for (int ntp = 0; ntp < 4; ntp++) {
                    const int kR = ksi * 16 + cKRow;
                    const int nO = wn * 64 + ntp * 16 + cN8;
                    ldsm_x4_t(b[2*ntp][0], b[2*ntp][1], b[2*ntp+1][0], b[2*ntp+1][1],
                              sB + (uint32_t)(kR * PBH + nO) * 2u);
                }
            }
            #pragma unroll
            for (int mt = 0; mt < 4; mt++)
                #pragma unroll
                for (int nt = 0; nt < 8; nt++)
                    mma_f16(acc[mt][nt], a[mt][0], a[mt][1], a[mt][2], a[mt][3],
                            b[nt][0], b[nt][1]);
        }
    }

    // ---- epilogue ----
    #pragma unroll
    for (int mt = 0; mt < 4; mt++) {
        #pragma unroll
        for (int nt = 0; nt < 8; nt++) {
            const int n = n0 + wn * 64 + nt * 8 + tig * 2;
            float bv0 = 0.f, bv1 = 0.f;
            if (HASB) { bv0 = bias[n]; bv1 = bias[n + 1]; }
            #pragma unroll
            for (int h = 0; h < 2; h++) {
                const int m = m0 + wm * 64 + mt * 16 + g + h * 8;
                float x0 = alpha * acc[mt][nt][h * 2 + 0] + bv0;
                float x1 = alpha * acc[mt][nt][h * 2 + 1] + bv1;
                if (RELU) { x0 = fmaxf(x0, 0.f); x1 = fmaxf(x1, 0.f); }
                if (OUT_HALF) {
                    __half2 w = __floats2half2_rn(x0, x1);
                    *reinterpret_cast<__half2*>(Ch + (ll)m * ldc + n) = w;
                } else {
                    float2 w; w.x = x0; w.y = x1;
                    *reinterpret_cast<float2*>(Cf + (ll)m * ldc + n) = w;
                }
            }
        }
    }
}

// ---------------- fp32 -> fp16 conversion (weights) ----------------
__global__ void h_convert(const float4* __restrict__ in, uint2* __restrict__ out, int n4)
{
    const int i = blockIdx.x * blockDim.x + threadIdx.x;
    if (i >= n4) return;
    const float4 v = in[i];
    __half2 lo = __floats2half2_rn(v.x, v.y);
    __half2 hi = __floats2half2_rn(v.z, v.w);
    uint2 o;
    o.x = *reinterpret_cast<uint32_t*>(&lo);
    o.y = *reinterpret_cast<uint32_t*>(&hi);
    out[i] = o;
}

// ---------------- split-K combine (3-way): out = P0 + P1 + P2 + bias + res ----------
__global__ void combine3_kernel(const float4* __restrict__ P0, const float4* __restrict__ P1,
                                const float4* __restrict__ P2,
                                const float* __restrict__ bias, const float4* __restrict__ res,
                                float4* __restrict__ out, int n4)
{
    const int i = blockIdx.x * blockDim.x + threadIdx.x;
    if (i >= n4) return;
    const int c = (i % (D_MODEL / 4)) * 4;
    const float4 p = P0[i], q = P1[i], s = P2[i], r = res[i];
    float4 o;
    o.x = p.x + q.x + s.x + bias[c + 0] + r.x;
    o.y = p.y + q.y + s.y + bias[c + 1] + r.y;
    o.z = p.z + q.z + s.z + bias[c + 2] + r.z;
    o.w = p.w + q.w + s.w + bias[c + 3] + r.w;
    out[i] = o;
}

// ---------------- layernorm: fp32 in, fp16 out (192 threads x float4) ----------------
__global__ void layernorm_kernel(const float4* __restrict__ x,
                                 const float4* __restrict__ gm,
                                 const float4* __restrict__ bt,
                                 uint2* __restrict__ y)
{
    const ll base = (ll)blockIdx.x * (D_MODEL / 4);
    const int t = threadIdx.x;                    // 0..191
    const float4 v = x[base + t];
    float lsum = v.x + v.y + v.z + v.w;
    float lsq  = v.x * v.x + v.y * v.y + v.z * v.z + v.w * v.w;

    __shared__ float sh[12];
    #pragma unroll
    for (int o = 16; o; o >>= 1) {
        lsum += __shfl_xor_sync(0xffffffffu, lsum, o);
        lsq  += __shfl_xor_sync(0xffffffffu, lsq,  o);
    }
    const int wid = t >> 5, lane = t & 31;        // 6 warps
    if (lane == 0) { sh[wid] = lsum; sh[6 + wid] = lsq; }
    __syncthreads();
    if (wid == 0) {
        float a = (lane < 6) ? sh[lane] : 0.f;
        float b = (lane < 6) ? sh[6 + lane] : 0.f;
        #pragma unroll
        for (int o = 4; o; o >>= 1) {
            a += __shfl_xor_sync(0xffffffffu, a, o);
            b += __shfl_xor_sync(0xffffffffu, b, o);
        }
        if (lane == 0) { sh[0] = a; sh[1] = b; }
    }
    __syncthreads();
    const float mu   = sh[0] * (1.f / D_MODEL);
    const float var  = sh[1] * (1.f / D_MODEL) - mu * mu;
    const float rstd = rsqrtf(var + LN_EPS);

    const float4 gv = gm[t];
    const float4 bv = bt[t];
    __half2 lo = __floats2half2_rn((v.x - mu) * rstd * gv.x + bv.x,
                                   (v.y - mu) * rstd * gv.y + bv.y);
    __half2 hi = __floats2half2_rn((v.z - mu) * rstd * gv.z + bv.z,
                                   (v.w - mu) * rstd * gv.w + bv.w);
    uint2 o;
    o.x = *reinterpret_cast<uint32_t*>(&lo);
    o.y = *reinterpret_cast<uint32_t*>(&hi);
    y[base + t] = o;
}

// ---------------- row softmax over length-1024 half rows ----------------
__global__ void softmax_kernel(__half* __restrict__ S)
{
    uint2* p = reinterpret_cast<uint2*>(S + (ll)blockIdx.x * SEQ);
    const int t = threadIdx.x;                    // 256 threads x 4 halves
    const int wid = t >> 5, lane = t & 31;
    __shared__ float sh[8];

    const uint2 u = p[t];
    const __half2 h0 = *reinterpret_cast<const __half2*>(&u.x);
    const __half2 h1 = *reinterpret_cast<const __half2*>(&u.y);
    float4 v;
    v.x = __low2float(h0);  v.y = __high2float(h0);
    v.z = __low2float(h1);  v.w = __high2float(h1);

    float mx = fmaxf(fmaxf(v.x, v.y), fmaxf(v.z, v.w));
    #pragma unroll
    for (int o = 16; o; o >>= 1) mx = fmaxf(mx, __shfl_xor_sync(0xffffffffu, mx, o));
    if (lane == 0) sh[wid] = mx;
    __syncthreads();
    {
        float a = sh[lane & 7];
        #pragma unroll
        for (int o = 4; o; o >>= 1) a = fmaxf(a, __shfl_xor_sync(0xffffffffu, a, o));
        mx = a;
    }

    v.x = __expf(v.x - mx); v.y = __expf(v.y - mx);
    v.z = __expf(v.z - mx); v.w = __expf(v.w - mx);
    float s = v.x + v.y + v.z + v.w;
    #pragma unroll
    for (int o = 16; o; o >>= 1) s += __shfl_xor_sync(0xffffffffu, s, o);
    __syncthreads();
    if (lane == 0) sh[wid] = s;
    __syncthreads();
    {
        float a = sh[lane & 7];
        #pragma unroll
        for (int o = 4; o; o >>= 1) a += __shfl_xor_sync(0xffffffffu, a, o);
        s = a;
    }
    const float inv = 1.f / s;
    __half2 o0 = __floats2half2_rn(v.x * inv, v.y * inv);
    __half2 o1 = __floats2half2_rn(v.z * inv, v.w * inv);
    uint2 o;
    o.x = *reinterpret_cast<uint32_t*>(&o0);
    o.y = *reinterpret_cast<uint32_t*>(&o1);
    p[t] = o;
}

// ---------------- launch ----------------
#define SMEM_NN 107520   /* (9216 + 8704) halves * 3st * 2B */
#define SMEM_NT 110592   /* (9216 + 9216) halves * 3st * 2B */

extern "C" void kernel_launch(void* const* d_in, const int* in_sizes, int n_in,
                              void* d_out, int out_size)
{
    const float* x    = (const float*)d_in[0];
    const float* Wq   = (const float*)d_in[1];
    const float* Wk   = (const float*)d_in[2];
    const float* Wv   = (const float*)d_in[3];
    const float* Wu   = (const float*)d_in[4];
    const float* bu   = (const float*)d_in[5];
    const float* ln1g = (const float*)d_in[6];
    const float* ln1b = (const float*)d_in[7];
    const float* ln2g = (const float*)d_in[8];
    const float* ln2b = (const float*)d_in[9];
    const float* W1   = (const float*)d_in[10];
    const float* b1   = (const float*)d_in[11];
    const float* W2   = (const float*)d_in[12];
    const float* b2   = (const float*)d_in[13];
    float* out = (float*)d_out;

    __half *Y, *Q, *Kp, *V, *S, *ATT, *H1, *WqH, *WkH, *WvH, *WuH, *W1H, *W2H;
    float *X1, *P;
    cudaGetSymbolAddress((void**)&Y,   g_Yh);
    cudaGetSymbolAddress((void**)&Q,   g_Qh);
    cudaGetSymbolAddress((void**)&Kp,  g_Kh);
    cudaGetSymbolAddress((void**)&V,   g_Vh);
    cudaGetSymbolAddress((void**)&S,   g_Sh);
    cudaGetSymbolAddress((void**)&ATT, g_ATTh);
    cudaGetSymbolAddress((void**)&H1,  g_H1h);
    cudaGetSymbolAddress((void**)&X1,  g_X1);
    cudaGetSymbolAddress((void**)&P,   g_P);
    cudaGetSymbolAddress((void**)&WqH, g_WqH);
    cudaGetSymbolAddress((void**)&WkH, g_WkH);
    cudaGetSymbolAddress((void**)&WvH, g_WvH);
    cudaGetSymbolAddress((void**)&WuH, g_WuH);
    cudaGetSymbolAddress((void**)&W1H, g_W1H);
    cudaGetSymbolAddress((void**)&W2H, g_W2H);

    float* P0 = P;
    float* P1 = P + (size_t)NTOK * D_MODEL;
    float* P2 = P + (size_t)2 * NTOK * D_MODEL;

    cudaFuncSetAttribute(gemm_h<false,false,false,true >, cudaFuncAttributeMaxDynamicSharedMemorySize, SMEM_NN);
    cudaFuncSetAttribute(gemm_h<true ,false,false,true >, cudaFuncAttributeMaxDynamicSharedMemorySize, SMEM_NT);
    cudaFuncSetAttribute(gemm_h<false,true ,true ,true >, cudaFuncAttributeMaxDynamicSharedMemorySize, SMEM_NN);
    cudaFuncSetAttribute(gemm_h<false,false,false,false>, cudaFuncAttributeMaxDynamicSharedMemorySize, SMEM_NN);

    const float inv_sqrt_d = 0.03608439182435161f;   // 1/sqrt(768)

    // 0) weight conversions + LN1
    {
        const int nqkv = D_MODEL * DH / 4, nmlp = D_MODEL * DFF / 4;
        h_convert<<<(nqkv + 255) / 256, 256>>>((const float4*)Wq, (uint2*)WqH, nqkv);
        h_convert<<<(nqkv + 255) / 256, 256>>>((const float4*)Wk, (uint2*)WkH, nqkv);
        h_convert<<<(nqkv + 255) / 256, 256>>>((const float4*)Wv, (uint2*)WvH, nqkv);
        h_convert<<<(nqkv + 255) / 256, 256>>>((const float4*)Wu, (uint2*)WuH, nqkv);
        h_convert<<<(nmlp + 255) / 256, 256>>>((const float4*)W1, (uint2*)W1H, nmlp);
        h_convert<<<(nmlp + 255) / 256, 256>>>((const float4*)W2, (uint2*)W2H, nmlp);
    }
    layernorm_kernel<<<NTOK, 192>>>((const float4*)x, (const float4*)ln1g,
                                    (const float4*)ln1b, (uint2*)Y);

    // 1) Q/K/V = Y @ W{q,k,v}  (M=4096, N=9216, K=768; NN)
    {
        dim3 grid(DH / 128, NTOK / 128, 1);
        gemm_h<false,false,false,true><<<grid, 128, SMEM_NN>>>(Y, WqH, nullptr, Q,
            D_MODEL, D_MODEL, DH, DH, 1.f, 0,0,0,0,0,0, 1);
        gemm_h<false,false,false,true><<<grid, 128, SMEM_NN>>>(Y, WkH, nullptr, Kp,
            D_MODEL, D_MODEL, DH, DH, 1.f, 0,0,0,0,0,0, 1);
        gemm_h<false,false,false,true><<<grid, 128, SMEM_NN>>>(Y, WvH, nullptr, V,
            D_MODEL, D_MODEL, DH, DH, 1.f, 0,0,0,0,0,0, 1);
    }

    // 2) S[b,h] = (Q_bh @ K_bh^T)/sqrt(768)  (M=N=1024, K=768, batch=48; NT)
    {
        dim3 grid(SEQ / 128, SEQ / 128, BATCH * NHEAD);
        gemm_h<true,false,false,true><<<grid, 128, SMEM_NT>>>(Q, Kp, nullptr, S,
            D_MODEL, DH, DH, SEQ, inv_sqrt_d,
            (ll)SEQ * DH, (ll)D_MODEL,
            (ll)SEQ * DH, (ll)D_MODEL,
            (ll)NHEAD * SEQ * SEQ, (ll)SEQ * SEQ,
            NHEAD);
    }

    // 3) softmax (fp32 math, fp16 in/out)
    softmax_kernel<<<BATCH * NHEAD * SEQ, 256>>>(S);

    // 4) ATT[b,:,h,:] = P_bh @ V_bh  (M=1024, N=768, K=1024, batch=48; NN)
    {
        dim3 grid(D_MODEL / 128, SEQ / 128, BATCH * NHEAD);
        gemm_h<false,false,false,true><<<grid, 128, SMEM_NN>>>(S, V, nullptr, ATT,
            SEQ, SEQ, DH, DH, 1.f,
            (ll)NHEAD * SEQ * SEQ, (ll)SEQ * SEQ,
            (ll)SEQ * DH, (ll)D_MODEL,
            (ll)SEQ * DH, (ll)D_MODEL,
            NHEAD);
    }

    // 5) Wu split-K=3 (z-batched), then X1 = P0+P1+P2 + bu + x
    {
        dim3 grid(D_MODEL / 128, NTOK / 128, 3);
        gemm_h<false,false,false,false><<<grid, 128, SMEM_NN>>>(ATT, WuH, nullptr, P0,
            DH / 3, DH, D_MODEL, D_MODEL, 1.f,
            0, (ll)(DH / 3),
            0, (ll)(DH / 3) * D_MODEL,
            0, (ll)NTOK * D_MODEL,
            3);
        const int n4 = NTOK * D_MODEL / 4;
        combine3_kernel<<<(n4 + 255) / 256, 256>>>((const float4*)P0, (const float4*)P1,
                                                   (const float4*)P2, bu,
                                                   (const float4*)x, (float4*)X1, n4);
    }

    // 6) LN2
    layernorm_kernel<<<NTOK, 192>>>((const float4*)X1, (const float4*)ln2g,
                                    (const float4*)ln2b, (uint2*)Y);

    // 7) H1 = relu(Y @ W1 + b1)  (M=4096, N=3072, K=768; NN)
    {
        dim3 grid(DFF / 128, NTOK / 128, 1);
        gemm_h<false,true,true,true><<<grid, 128, SMEM_NN>>>(Y, W1H, b1, H1,
            D_MODEL, D_MODEL, DFF, DFF, 1.f, 0,0,0,0,0,0, 1);
    }

    // 8) W2 split-K=3, then out = P0+P1+P2 + b2 + X1
    {
        dim3 grid(D_MODEL / 128, NTOK / 128, 3);
        gemm_h<false,false,false,false><<<grid, 128, SMEM_NN>>>(H1, W2H, nullptr, P0,
            DFF / 3, DFF, D_MODEL, D_MODEL, 1.f,
            0, (ll)(DFF / 3),
            0, (ll)(DFF / 3) * D_MODEL,
            0, (ll)NTOK * D_MODEL,
            3);
        const int n4 = NTOK * D_MODEL / 4;
        combine3_kernel<<<(n4 + 255) / 256, 256>>>((const float4*)P0, (const float4*)P1,
                                                   (const float4*)P2, b2,
                                                   (const float4*)X1, (float4*)out, n4);
    }

    (void)in_sizes; (void)n_in; (void)out_size;
}

// round 13
// speedup vs baseline: 1.9590x; 1.0254x over previous
#include <cuda_runtime.h>
#include <cuda_fp16.h>
#include <cstdint>

#define D_MODEL 768
#define NHEAD   12
#define SEQ     1024
#define BATCH   4
#define NTOK    (BATCH*SEQ)        /* 4096 */
#define DH      (D_MODEL*NHEAD)    /* 9216 */
#define DFF     (4*D_MODEL)        /* 3072 */
#define LN_EPS  1e-5f

typedef long long ll;

// ---------------- scratch (device globals; no allocation allowed) ----------------
__device__ __half g_Yh   [(size_t)NTOK * D_MODEL];
__device__ __half g_QKVh [(size_t)3 * NTOK * DH];          // Q | K | V slabs
__device__ __half g_Sh   [(size_t)BATCH * NHEAD * SEQ * SEQ];
__device__ __half g_ATTh [(size_t)NTOK * DH];
__device__ __half g_H1h  [(size_t)NTOK * DFF];
__device__ float  g_X1   [(size_t)NTOK * D_MODEL];
__device__ float  g_P    [(size_t)3 * NTOK * D_MODEL];     // split-K partials
__device__ __half g_WqkvH[(size_t)3 * D_MODEL * DH];       // Wq | Wk | Wv slabs
__device__ __half g_WuH  [(size_t)DH * D_MODEL];
__device__ __half g_W1H  [(size_t)D_MODEL * DFF];
__device__ __half g_W2H  [(size_t)DFF * D_MODEL];

// ---------------- helpers ----------------
__device__ __forceinline__ uint32_t smem_u32(const void* p) {
    uint32_t a;
    asm("{ .reg .u64 t; cvta.to.shared.u64 t, %1; cvt.u32.u64 %0, t; }" : "=r"(a) : "l"(p));
    return a;
}
__device__ __forceinline__ void cp16(uint32_t dst, const void* src) {
    asm volatile("cp.async.cg.shared.global [%0], [%1], 16;" :: "r"(dst), "l"(src) : "memory");
}
__device__ __forceinline__ void cp_commit() {
    asm volatile("cp.async.commit_group;" ::: "memory");
}
template<int N>
__device__ __forceinline__ void cp_wait() {
    asm volatile("cp.async.wait_group %0;" :: "n"(N) : "memory");
}
__device__ __forceinline__ void ldsm_x4(uint32_t& r0, uint32_t& r1, uint32_t& r2, uint32_t& r3,
                                        uint32_t addr) {
    asm volatile("ldmatrix.sync.aligned.m8n8.x4.shared.b16 {%0,%1,%2,%3}, [%4];"
                 : "=r"(r0), "=r"(r1), "=r"(r2), "=r"(r3) : "r"(addr));
}
__device__ __forceinline__ void ldsm_x4_t(uint32_t& r0, uint32_t& r1, uint32_t& r2, uint32_t& r3,
                                          uint32_t addr) {
    asm volatile("ldmatrix.sync.aligned.m8n8.x4.trans.shared.b16 {%0,%1,%2,%3}, [%4];"
                 : "=r"(r0), "=r"(r1), "=r"(r2), "=r"(r3) : "r"(addr));
}
__device__ __forceinline__ void mma_f16(float c[4],
                                        uint32_t a0, uint32_t a1, uint32_t a2, uint32_t a3,
                                        uint32_t b0, uint32_t b1) {
    asm("mma.sync.aligned.m16n8k16.row.col.f32.f16.f16.f32 "
        "{%0,%1,%2,%3}, {%4,%5,%6,%7}, {%8,%9}, {%0,%1,%2,%3};"
        : "+f"(c[0]), "+f"(c[1]), "+f"(c[2]), "+f"(c[3])
        : "r"(a0), "r"(a1), "r"(a2), "r"(a3), "r"(b0), "r"(b1));
}

// ---------------- fp16 tensor-core GEMM (unchanged from R12 win — do not touch) ----
template<bool BT, bool RELU, bool HASB, bool OUT_HALF>
__global__ __launch_bounds__(128, 2)
void gemm_h(const __half* __restrict__ A, const __half* __restrict__ B,
            const float* __restrict__ bias, void* __restrict__ Cv,
            int K, int lda, int ldb, int ldc, float alpha,
            ll saO, ll saI, ll sbO, ll sbI, ll scO, ll scI, int innerCnt)
{
    constexpr int STAGES  = 3;
    constexpr int PAH     = 72;                   // A / B-NT pitch (halves)
    constexpr int PBH     = 136;                  // B-NN pitch (halves)
    constexpr int A_H     = 128 * PAH;            // 9216 halves
    constexpr int B_H     = BT ? 128 * PAH : 64 * PBH;
    constexpr int STAGE_H = A_H + B_H;

    extern __shared__ __half dynsm[];

    const int tid  = threadIdx.x;
    const int wid  = tid >> 5;
    const int lane = tid & 31;
    const int g    = lane >> 2;
    const int tig  = lane & 3;
    const int wm   = wid >> 1;                    // 0..1
    const int wn   = wid & 1;                     // 0..1

    const int mi = lane >> 3;
    const int r8 = lane & 7;
    const int aRowOff = (mi & 1) * 8 + r8;
    const int aK8     = (mi >> 1) * 8;
    const int bRowOff = (mi >> 1) * 8 + r8;
    const int bK8     = (mi & 1) * 8;
    const int cKRow   = (mi & 1) * 8 + r8;
    const int cN8     = (mi >> 1) * 8;

    const int z  = blockIdx.z;
    const int zo = z / innerCnt;
    const int zi = z - zo * innerCnt;
    A += zo * saO + zi * saI;
    B += zo * sbO + zi * sbI;
    __half* Ch = (__half*)Cv + zo * scO + zi * scI;
    float*  Cf = (float*) Cv + zo * scO + zi * scI;

    const int m0 = blockIdx.y * 128;
    const int n0 = blockIdx.x * 128;
    A += (ll)m0 * lda;
    B += BT ? (ll)n0 * ldb : (ll)n0;

    const uint32_t smb = smem_u32(dynsm);

    auto issue = [&](int tile) {
        const int stage = tile % STAGES;
        const uint32_t sA = smb + (uint32_t)(stage * STAGE_H) * 2u;
        const uint32_t sB = sA + (uint32_t)A_H * 2u;
        const int k0 = tile * 64;
        #pragma unroll
        for (int i = 0; i < 8; i++) {
            const int v = tid + i * 128;
            const int m = v >> 3, c = (v & 7) * 8;
            cp16(sA + (uint32_t)(m * PAH + c) * 2u, A + (ll)m * lda + k0 + c);
        }
        #pragma unroll
        for (int i = 0; i < 8; i++) {
            const int v = tid + i * 128;
            if (BT) {
                const int n = v >> 3, c = (v & 7) * 8;
                cp16(sB + (uint32_t)(n * PAH + c) * 2u, B + (ll)n * ldb + k0 + c);
            } else {
                const int k = v >> 4, c = (v & 15) * 8;
                cp16(sB + (uint32_t)(k * PBH + c) * 2u, B + (ll)(k0 + k) * ldb + c);
            }
        }
        cp_commit();
    };

    float acc[4][8][4];
    #pragma unroll
    for (int mt = 0; mt < 4; mt++)
        #pragma unroll
        for (int nt = 0; nt < 8; nt++)
            #pragma unroll
            for (int rr = 0; rr < 4; rr++) acc[mt][nt][rr] = 0.f;

    const int T = K >> 6;
    issue(0); issue(1);

    for (int it = 0; it < T; ++it) {
        cp_wait<1>();
        __syncthreads();
        if (it + 2 < T) issue(it + 2);

        const uint32_t sA = smb + (uint32_t)((it % STAGES) * STAGE_H) * 2u;
        const uint32_t sB = sA + (uint32_t)A_H * 2u;

        #pragma unroll
        for (int ksi = 0; ksi < 4; ksi++) {
            uint32_t a[4][4], b[8][2];
            #pragma unroll
            for (int mt = 0; mt < 4; mt++) {
                const int m = wm * 64 + mt * 16 + aRowOff;
                ldsm_x4(a[mt][0], a[mt][1], a[mt][2], a[mt][3],
                        sA + (uint32_t)(m * PAH + ksi * 16 + aK8) * 2u);
            }
            if (BT) {
                #pragma unroll
                for (int ntp = 0; ntp < 4; ntp++) {
                    const int n = wn * 64 + ntp * 16 + bRowOff;
                    ldsm_x4(b[2*ntp][0], b[2*ntp][1], b[2*ntp+1][0], b[2*ntp+1][1],
                            sB + (uint32_t)(n * PAH + ksi * 16 + bK8) * 2u);
                }
            } else {
                #pragma unroll
                for (int ntp = 0; ntp < 4; ntp++) {
                    const int kR = ksi * 16 + cKRow;
                    const int nO = wn * 64 + ntp * 16 + cN8;
                    ldsm_x4_t(b[2*ntp][0], b[2*ntp][1], b[2*ntp+1][0], b[2*ntp+1][1],
                              sB + (uint32_t)(kR * PBH + nO) * 2u);
                }
            }
            #pragma unroll
            for (int mt = 0; mt < 4; mt++)
                #pragma unroll
                for (int nt = 0; nt < 8; nt++)
                    mma_f16(acc[mt][nt], a[mt][0], a[mt][1], a[mt][2], a[mt][3],
                            b[nt][0], b[nt][1]);
        }
    }

    // ---- epilogue ----
    #pragma unroll
    for (int mt = 0; mt < 4; mt++) {
        #pragma unroll
        for (int nt = 0; nt < 8; nt++) {
            const int n = n0 + wn * 64 + nt * 8 + tig * 2;
            float bv0 = 0.f, bv1 = 0.f;
            if (HASB) { bv0 = bias[n]; bv1 = bias[n + 1]; }
            #pragma unroll
            for (int h = 0; h < 2; h++) {
                const int m = m0 + wm * 64 + mt * 16 + g + h * 8;
                float x0 = alpha * acc[mt][nt][h * 2 + 0] + bv0;
                float x1 = alpha * acc[mt][nt][h * 2 + 1] + bv1;
                if (RELU) { x0 = fmaxf(x0, 0.f); x1 = fmaxf(x1, 0.f); }
                if (OUT_HALF) {
                    __half2 w = __floats2half2_rn(x0, x1);
                    *reinterpret_cast<__half2*>(Ch + (ll)m * ldc + n) = w;
                } else {
                    float2 w; w.x = x0; w.y = x1;
                    *reinterpret_cast<float2*>(Cf + (ll)m * ldc + n) = w;
                }
            }
        }
    }
}

// ---------------- fused fp32 -> fp16 conversion: 6 weight segments, one launch ------
__global__ void h_convert_all(const float4* s0, const float4* s1, const float4* s2,
                              const float4* s3, const float4* s4, const float4* s5,
                              uint2* d0, uint2* d1, uint2* d2,
                              uint2* d3, uint2* d4, uint2* d5,
                              int nbig, int nsmall)
{
    const int seg = blockIdx.y;
    const float4* src; uint2* dst; int n4;
    switch (seg) {
        case 0: src = s0; dst = d0; n4 = nbig;   break;
        case 1: src = s1; dst = d1; n4 = nbig;   break;
        case 2: src = s2; dst = d2; n4 = nbig;   break;
        case 3: src = s3; dst = d3; n4 = nbig;   break;
        case 4: src = s4; dst = d4; n4 = nsmall; break;
        default: src = s5; dst = d5; n4 = nsmall; break;
    }
    const int i = blockIdx.x * blockDim.x + threadIdx.x;
    if (i >= n4) return;
    const float4 v = src[i];
    __half2 lo = __floats2half2_rn(v.x, v.y);
    __half2 hi = __floats2half2_rn(v.z, v.w);
    uint2 o;
    o.x = *reinterpret_cast<uint32_t*>(&lo);
    o.y = *reinterpret_cast<uint32_t*>(&hi);
    dst[i] = o;
}

// ---------------- split-K combine (3-way): out = P0 + P1 + P2 + bias + res ----------
__global__ void combine3_kernel(const float4* __restrict__ P0, const float4* __restrict__ P1,
                                const float4* __restrict__ P2,
                                const float* __restrict__ bias, const float4* __restrict__ res,
                                float4* __restrict__ out, int n4)
{
    const int i = blockIdx.x * blockDim.x + threadIdx.x;
    if (i >= n4) return;
    const int c = (i % (D_MODEL / 4)) * 4;
    const float4 p = P0[i], q = P1[i], s = P2[i], r = res[i];
    float4 o;
    o.x = p.x + q.x + s.x + bias[c + 0] + r.x;
    o.y = p.y + q.y + s.y + bias[c + 1] + r.y;
    o.z = p.z + q.z + s.z + bias[c + 2] + r.z;
    o.w = p.w + q.w + s.w + bias[c + 3] + r.w;
    out[i] = o;
}

// ---------------- layernorm: fp32 in, fp16 out (192 threads x float4) ----------------
__global__ void layernorm_kernel(const float4* __restrict__ x,
                                 const float4* __restrict__ gm,
                                 const float4* __restrict__ bt,
                                 uint2* __restrict__ y)
{
    const ll base = (ll)blockIdx.x * (D_MODEL / 4);
    const int t = threadIdx.x;                    // 0..191
    const float4 v = x[base + t];
    float lsum = v.x + v.y + v.z + v.w;
    float lsq  = v.x * v.x + v.y * v.y + v.z * v.z + v.w * v.w;

    __shared__ float sh[12];
    #pragma unroll
    for (int o = 16; o; o >>= 1) {
        lsum += __shfl_xor_sync(0xffffffffu, lsum, o);
        lsq  += __shfl_xor_sync(0xffffffffu, lsq,  o);
    }
    const int wid = t >> 5, lane = t & 31;        // 6 warps
    if (lane == 0) { sh[wid] = lsum; sh[6 + wid] = lsq; }
    __syncthreads();
    if (wid == 0) {
        float a = (lane < 6) ? sh[lane] : 0.f;
        float b = (lane < 6) ? sh[6 + lane] : 0.f;
        #pragma unroll
        for (int o = 4; o; o >>= 1) {
            a += __shfl_xor_sync(0xffffffffu, a, o);
            b += __shfl_xor_sync(0xffffffffu, b, o);
        }
        if (lane == 0) { sh[0] = a; sh[1] = b; }
    }
    __syncthreads();
    const float mu   = sh[0] * (1.f / D_MODEL);
    const float var  = sh[1] * (1.f / D_MODEL) - mu * mu;
    const float rstd = rsqrtf(var + LN_EPS);

    const float4 gv = gm[t];
    const float4 bv = bt[t];
    __half2 lo = __floats2half2_rn((v.x - mu) * rstd * gv.x + bv.x,
                                   (v.y - mu) * rstd * gv.y + bv.y);
    __half2 hi = __floats2half2_rn((v.z - mu) * rstd * gv.z + bv.z,
                                   (v.w - mu) * rstd * gv.w + bv.w);
    uint2 o;
    o.x = *reinterpret_cast<uint32_t*>(&lo);
    o.y = *reinterpret_cast<uint32_t*>(&hi);
    y[base + t] = o;
}

// ---------------- row softmax over length-1024 half rows ----------------
__global__ void softmax_kernel(__half* __restrict__ S)
{
    uint2* p = reinterpret_cast<uint2*>(S + (ll)blockIdx.x * SEQ);
    const int t = threadIdx.x;                    // 256 threads x 4 halves
    const int wid = t >> 5, lane = t & 31;
    __shared__ float sh[8];

    const uint2 u = p[t];
    const __half2 h0 = *reinterpret_cast<const __half2*>(&u.x);
    const __half2 h1 = *reinterpret_cast<const __half2*>(&u.y);
    float4 v;
    v.x = __low2float(h0);  v.y = __high2float(h0);
    v.z = __low2float(h1);  v.w = __high2float(h1);

    float mx = fmaxf(fmaxf(v.x, v.y), fmaxf(v.z, v.w));
    #pragma unroll
    for (int o = 16; o; o >>= 1) mx = fmaxf(mx, __shfl_xor_sync(0xffffffffu, mx, o));
    if (lane == 0) sh[wid] = mx;
    __syncthreads();
    {
        float a = sh[lane & 7];
        #pragma unroll
        for (int o = 4; o; o >>= 1) a = fmaxf(a, __shfl_xor_sync(0xffffffffu, a, o));
        mx = a;
    }

    v.x = __expf(v.x - mx); v.y = __expf(v.y - mx);
    v.z = __expf(v.z - mx); v.w = __expf(v.w - mx);
    float s = v.x + v.y + v.z + v.w;
    #pragma unroll
    for (int o = 16; o; o >>= 1) s += __shfl_xor_sync(0xffffffffu, s, o);
    __syncthreads();
    if (lane == 0) sh[wid] = s;
    __syncthreads();
    {
        float a = sh[lane & 7];
        #pragma unroll
        for (int o = 4; o; o >>= 1) a += __shfl_xor_sync(0xffffffffu, a, o);
        s = a;
    }
    const float inv = 1.f / s;
    __half2 o0 = __floats2half2_rn(v.x * inv, v.y * inv);
    __half2 o1 = __floats2half2_rn(v.z * inv, v.w * inv);
    uint2 o;
    o.x = *reinterpret_cast<uint32_t*>(&o0);
    o.y = *reinterpret_cast<uint32_t*>(&o1);
    p[t] = o;
}

// ---------------- launch ----------------
#define SMEM_NN 107520   /* (9216 + 8704) halves * 3st * 2B */
#define SMEM_NT 110592   /* (9216 + 9216) halves * 3st * 2B */

extern "C" void kernel_launch(void* const* d_in, const int* in_sizes, int n_in,
                              void* d_out, int out_size)
{
    const float* x    = (const float*)d_in[0];
    const float* Wq   = (const float*)d_in[1];
    const float* Wk   = (const float*)d_in[2];
    const float* Wv   = (const float*)d_in[3];
    const float* Wu   = (const float*)d_in[4];
    const float* bu   = (const float*)d_in[5];
    const float* ln1g = (const float*)d_in[6];
    const float* ln1b = (const float*)d_in[7];
    const float* ln2g = (const float*)d_in[8];
    const float* ln2b = (const float*)d_in[9];
    const float* W1   = (const float*)d_in[10];
    const float* b1   = (const float*)d_in[11];
    const float* W2   = (const float*)d_in[12];
    const float* b2   = (const float*)d_in[13];
    float* out = (float*)d_out;

    __half *Y, *QKV, *S, *ATT, *H1, *Wqkv, *WuH, *W1H, *W2H;
    float *X1, *P;
    cudaGetSymbolAddress((void**)&Y,    g_Yh);
    cudaGetSymbolAddress((void**)&QKV,  g_QKVh);
    cudaGetSymbolAddress((void**)&S,    g_Sh);
    cudaGetSymbolAddress((void**)&ATT,  g_ATTh);
    cudaGetSymbolAddress((void**)&H1,   g_H1h);
    cudaGetSymbolAddress((void**)&X1,   g_X1);
    cudaGetSymbolAddress((void**)&P,    g_P);
    cudaGetSymbolAddress((void**)&Wqkv, g_WqkvH);
    cudaGetSymbolAddress((void**)&WuH,  g_WuH);
    cudaGetSymbolAddress((void**)&W1H,  g_W1H);
    cudaGetSymbolAddress((void**)&W2H,  g_W2H);

    __half* Q  = QKV;
    __half* Kp = QKV + (size_t)NTOK * DH;
    __half* V  = QKV + (size_t)2 * NTOK * DH;

    float* P0 = P;
    float* P1 = P + (size_t)NTOK * D_MODEL;
    float* P2 = P + (size_t)2 * NTOK * D_MODEL;

    cudaFuncSetAttribute(gemm_h<false,false,false,true >, cudaFuncAttributeMaxDynamicSharedMemorySize, SMEM_NN);
    cudaFuncSetAttribute(gemm_h<true ,false,false,true >, cudaFuncAttributeMaxDynamicSharedMemorySize, SMEM_NT);
    cudaFuncSetAttribute(gemm_h<false,true ,true ,true >, cudaFuncAttributeMaxDynamicSharedMemorySize, SMEM_NN);
    cudaFuncSetAttribute(gemm_h<false,false,false,false>, cudaFuncAttributeMaxDynamicSharedMemorySize, SMEM_NN);

    const float inv_sqrt_d = 0.03608439182435161f;   // 1/sqrt(768)

    // 0) all weight conversions in ONE launch + LN1
    {
        const int nbig = D_MODEL * DH / 4;           // Wq/Wk/Wv/Wu segments
        const int nsmall = D_MODEL * DFF / 4;        // W1/W2 segments
        dim3 grid((nbig + 255) / 256, 6, 1);
        h_convert_all<<<grid, 256>>>(
            (const float4*)Wq, (const float4*)Wk, (const float4*)Wv,
            (const float4*)Wu, (const float4*)W1, (const float4*)W2,
            (uint2*)Wqkv,
            (uint2*)(Wqkv + (size_t)D_MODEL * DH),
            (uint2*)(Wqkv + (size_t)2 * D_MODEL * DH),
            (uint2*)WuH, (uint2*)W1H, (uint2*)W2H,
            nbig, nsmall);
    }
    layernorm_kernel<<<NTOK, 192>>>((const float4*)x, (const float4*)ln1g,
                                    (const float4*)ln1b, (uint2*)Y);

    // 1) QKV = Y @ [Wq|Wk|Wv] in ONE launch (M=4096, N=9216, K=768, z=3; NN)
    {
        dim3 grid(DH / 128, NTOK / 128, 3);
        gemm_h<false,false,false,true><<<grid, 128, SMEM_NN>>>(Y, Wqkv, nullptr, QKV,
            D_MODEL, D_MODEL, DH, DH, 1.f,
            0, 0,                                     // A: same for all z
            0, (ll)D_MODEL * DH,                      // B: weight slab per z
            0, (ll)NTOK * DH,                         // C: output slab per z
            3);
    }

    // 2) S[b,h] = (Q_bh @ K_bh^T)/sqrt(768)  (M=N=1024, K=768, batch=48; NT)
    {
        dim3 grid(SEQ / 128, SEQ / 128, BATCH * NHEAD);
        gemm_h<true,false,false,true><<<grid, 128, SMEM_NT>>>(Q, Kp, nullptr, S,
            D_MODEL, DH, DH, SEQ, inv_sqrt_d,
            (ll)SEQ * DH, (ll)D_MODEL,
            (ll)SEQ * DH, (ll)D_MODEL,
            (ll)NHEAD * SEQ * SEQ, (ll)SEQ * SEQ,
            NHEAD);
    }

    // 3) softmax (fp32 math, fp16 in/out)
    softmax_kernel<<<BATCH * NHEAD * SEQ, 256>>>(S);

    // 4) ATT[b,:,h,:] = P_bh @ V_bh  (M=1024, N=768, K=1024, batch=48; NN)
    {
        dim3 grid(D_MODEL / 128, SEQ / 128, BATCH * NHEAD);
        gemm_h<false,false,false,true><<<grid, 128, SMEM_NN>>>(S, V, nullptr, ATT,
            SEQ, SEQ, DH, DH, 1.f,
            (ll)NHEAD * SEQ * SEQ, (ll)SEQ * SEQ,
            (ll)SEQ * DH, (ll)D_MODEL,
            (ll)SEQ * DH, (ll)D_MODEL,
            NHEAD);
    }

    // 5) Wu split-K=3 (z-batched), then X1 = P0+P1+P2 + bu + x
    {
        dim3 grid(D_MODEL / 128, NTOK / 128, 3);
        gemm_h<false,false,false,false><<<grid, 128, SMEM_NN>>>(ATT, WuH, nullptr, P0,
            DH / 3, DH, D_MODEL, D_MODEL, 1.f,
            0, (ll)(DH / 3),
            0, (ll)(DH / 3) * D_MODEL,
            0, (ll)NTOK * D_MODEL,
            3);
        const int n4 = NTOK * D_MODEL / 4;
        combine3_kernel<<<(n4 + 255) / 256, 256>>>((const float4*)P0, (const float4*)P1,
                                                   (const float4*)P2, bu,
                                                   (const float4*)x, (float4*)X1, n4);
    }

    // 6) LN2
    layernorm_kernel<<<NTOK, 192>>>((const float4*)X1, (const float4*)ln2g,
                                    (const float4*)ln2b, (uint2*)Y);

    // 7) H1 = relu(Y @ W1 + b1)  (M=4096, N=3072, K=768; NN)
    {
        dim3 grid(DFF / 128, NTOK / 128, 1);
        gemm_h<false,true,true,true><<<grid, 128, SMEM_NN>>>(Y, W1H, b1, H1,
            D_MODEL, D_MODEL, DFF, DFF, 1.f, 0,0,0,0,0,0, 1);
    }

    // 8) W2 split-K=3, then out = P0+P1+P2 + b2 + X1
    {
        dim3 grid(D_MODEL / 128, NTOK / 128, 3);
        gemm_h<false,false,false,false><<<grid, 128, SMEM_NN>>>(H1, W2H, nullptr, P0,
            DFF / 3, DFF, D_MODEL, D_MODEL, 1.f,
            0, (ll)(DFF / 3),
            0, (ll)(DFF / 3) * D_MODEL,
            0, (ll)NTOK * D_MODEL,
            3);
        const int n4 = NTOK * D_MODEL / 4;
        combine3_kernel<<<(n4 + 255) / 256, 256>>>((const float4*)P0, (const float4*)P1,
                                                   (const float4*)P2, b2,
                                                   (const float4*)X1, (float4*)out, n4);
    }

    (void)in_sizes; (void)n_in; (void)out_size;
}

// round 14
// speedup vs baseline: 2.0154x; 1.0288x over previous
#include <cuda_runtime.h>
#include <cuda_fp16.h>
#include <cstdint>

#define D_MODEL 768
#define NHEAD   12
#define SEQ     1024
#define BATCH   4
#define NTOK    (BATCH*SEQ)        /* 4096 */
#define DH      (D_MODEL*NHEAD)    /* 9216 */
#define DFF     (4*D_MODEL)        /* 3072 */
#define LN_EPS  1e-5f

typedef long long ll;

// ---------------- scratch (device globals; no allocation allowed) ----------------
__device__ __half g_Yh   [(size_t)NTOK * D_MODEL];
__device__ __half g_QKVh [(size_t)3 * NTOK * DH];          // Q | K | V slabs
__device__ __half g_Sh   [(size_t)BATCH * NHEAD * SEQ * SEQ];   // exp(scores)
__device__ __half g_ATTh [(size_t)NTOK * DH];
__device__ __half g_H1h  [(size_t)NTOK * DFF];
__device__ float  g_X1   [(size_t)NTOK * D_MODEL];
__device__ float  g_P    [(size_t)3 * NTOK * D_MODEL];     // split-K partials / rowsum partials
__device__ float  g_RS   [(size_t)BATCH * NHEAD * SEQ];    // 1/rowsum
__device__ __half g_WqkvH[(size_t)3 * D_MODEL * DH];
__device__ __half g_WuH  [(size_t)DH * D_MODEL];
__device__ __half g_W1H  [(size_t)D_MODEL * DFF];
__device__ __half g_W2H  [(size_t)DFF * D_MODEL];

// ---------------- helpers ----------------
__device__ __forceinline__ uint32_t smem_u32(const void* p) {
    uint32_t a;
    asm("{ .reg .u64 t; cvta.to.shared.u64 t, %1; cvt.u32.u64 %0, t; }" : "=r"(a) : "l"(p));
    return a;
}
__device__ __forceinline__ void cp16(uint32_t dst, const void* src) {
    asm volatile("cp.async.cg.shared.global [%0], [%1], 16;" :: "r"(dst), "l"(src) : "memory");
}
__device__ __forceinline__ void cp_commit() {
    asm volatile("cp.async.commit_group;" ::: "memory");
}
template<int N>
__device__ __forceinline__ void cp_wait() {
    asm volatile("cp.async.wait_group %0;" :: "n"(N) : "memory");
}
__device__ __forceinline__ void ldsm_x4(uint32_t& r0, uint32_t& r1, uint32_t& r2, uint32_t& r3,
                                        uint32_t addr) {
    asm volatile("ldmatrix.sync.aligned.m8n8.x4.shared.b16 {%0,%1,%2,%3}, [%4];"
                 : "=r"(r0), "=r"(r1), "=r"(r2), "=r"(r3) : "r"(addr));
}
__device__ __forceinline__ void ldsm_x4_t(uint32_t& r0, uint32_t& r1, uint32_t& r2, uint32_t& r3,
                                          uint32_t addr) {
    asm volatile("ldmatrix.sync.aligned.m8n8.x4.trans.shared.b16 {%0,%1,%2,%3}, [%4];"
                 : "=r"(r0), "=r"(r1), "=r"(r2), "=r"(r3) : "r"(addr));
}
__device__ __forceinline__ void mma_f16(float c[4],
                                        uint32_t a0, uint32_t a1, uint32_t a2, uint32_t a3,
                                        uint32_t b0, uint32_t b1) {
    asm("mma.sync.aligned.m16n8k16.row.col.f32.f16.f16.f32 "
        "{%0,%1,%2,%3}, {%4,%5,%6,%7}, {%8,%9}, {%0,%1,%2,%3};"
        : "+f"(c[0]), "+f"(c[1]), "+f"(c[2]), "+f"(c[3])
        : "r"(a0), "r"(a1), "r"(a2), "r"(a3), "r"(b0), "r"(b1));
}

// ---------------- fp16 tensor-core GEMM (R12 mainloop unchanged) -------------------
// MODE 0: plain.  MODE 1: epilogue x=exp(alpha*acc), emit per-slice row partial sums
//   to rsPtr[(bz*16 + bx*2+wn)*1024 + m] (deterministic, no atomics).
// MODE 2: epilogue scales by rsPtr[bz*1024 + m] (1/rowsum, deferred softmax norm).
template<bool BT, bool RELU, bool HASB, bool OUT_HALF, int MODE>
__global__ __launch_bounds__(128, 2)
void gemm_h(const __half* __restrict__ A, const __half* __restrict__ B,
            const float* __restrict__ bias, void* __restrict__ Cv,
            float* __restrict__ rsPtr,
            int K, int lda, int ldb, int ldc, float alpha,
            ll saO, ll saI, ll sbO, ll sbI, ll scO, ll scI, int innerCnt)
{
    constexpr int STAGES  = 3;
    constexpr int PAH     = 72;
    constexpr int PBH     = 136;
    constexpr int A_H     = 128 * PAH;
    constexpr int B_H     = BT ? 128 * PAH : 64 * PBH;
    constexpr int STAGE_H = A_H + B_H;

    extern __shared__ __half dynsm[];

    const int tid  = threadIdx.x;
    const int wid  = tid >> 5;
    const int lane = tid & 31;
    const int g    = lane >> 2;
    const int tig  = lane & 3;
    const int wm   = wid >> 1;
    const int wn   = wid & 1;

    const int mi = lane >> 3;
    const int r8 = lane & 7;
    const int aRowOff = (mi & 1) * 8 + r8;
    const int aK8     = (mi >> 1) * 8;
    const int bRowOff = (mi >> 1) * 8 + r8;
    const int bK8     = (mi & 1) * 8;
    const int cKRow   = (mi & 1) * 8 + r8;
    const int cN8     = (mi >> 1) * 8;

    const int z  = blockIdx.z;
    const int zo = z / innerCnt;
    const int zi = z - zo * innerCnt;
    A += zo * saO + zi * saI;
    B += zo * sbO + zi * sbI;
    __half* Ch = (__half*)Cv + zo * scO + zi * scI;
    float*  Cf = (float*) Cv + zo * scO + zi * scI;
    float*       rsOut = (MODE == 1) ? rsPtr + (ll)z * 16384 : nullptr;
    const float* rsIn  = (MODE == 2) ? rsPtr + (ll)z * 1024  : nullptr;

    const int m0 = blockIdx.y * 128;
    const int n0 = blockIdx.x * 128;
    A += (ll)m0 * lda;
    B += BT ? (ll)n0 * ldb : (ll)n0;

    const uint32_t smb = smem_u32(dynsm);

    auto issue = [&](int tile) {
        const int stage = tile % STAGES;
        const uint32_t sA = smb + (uint32_t)(stage * STAGE_H) * 2u;
        const uint32_t sB = sA + (uint32_t)A_H * 2u;
        const int k0 = tile * 64;
        #pragma unroll
        for (int i = 0; i < 8; i++) {
            const int v = tid + i * 128;
            const int m = v >> 3, c = (v & 7) * 8;
            cp16(sA + (uint32_t)(m * PAH + c) * 2u, A + (ll)m * lda + k0 + c);
        }
        #pragma unroll
        for (int i = 0; i < 8; i++) {
            const int v = tid + i * 128;
            if (BT) {
                const int n = v >> 3, c = (v & 7) * 8;
                cp16(sB + (uint32_t)(n * PAH + c) * 2u, B + (ll)n * ldb + k0 + c);
            } else {
                const int k = v >> 4, c = (v & 15) * 8;
                cp16(sB + (uint32_t)(k * PBH + c) * 2u, B + (ll)(k0 + k) * ldb + c);
            }
        }
        cp_commit();
    };

    float acc[4][8][4];
    #pragma unroll
    for (int mt = 0; mt < 4; mt++)
        #pragma unroll
        for (int nt = 0; nt < 8; nt++)
            #pragma unroll
            for (int rr = 0; rr < 4; rr++) acc[mt][nt][rr] = 0.f;

    const int T = K >> 6;
    issue(0); issue(1);

    for (int it = 0; it < T; ++it) {
        cp_wait<1>();
        __syncthreads();
        if (it + 2 < T) issue(it + 2);

        const uint32_t sA = smb + (uint32_t)((it % STAGES) * STAGE_H) * 2u;
        const uint32_t sB = sA + (uint32_t)A_H * 2u;

        #pragma unroll
        for (int ksi = 0; ksi < 4; ksi++) {
            uint32_t a[4][4], b[8][2];
            #pragma unroll
            for (int mt = 0; mt < 4; mt++) {
                const int m = wm * 64 + mt * 16 + aRowOff;
                ldsm_x4(a[mt][0], a[mt][1], a[mt][2], a[mt][3],
                        sA + (uint32_t)(m * PAH + ksi * 16 + aK8) * 2u);
            }
            if (BT) {
                #pragma unroll
                for (int ntp = 0; ntp < 4; ntp++) {
                    const int n = wn * 64 + ntp * 16 + bRowOff;
                    ldsm_x4(b[2*ntp][0], b[2*ntp][1], b[2*ntp+1][0], b[2*ntp+1][1],
                            sB + (uint32_t)(n * PAH + ksi * 16 + bK8) * 2u);
                }
            } else {
                #pragma unroll
                for (int ntp = 0; ntp < 4; ntp++) {
                    const int kR = ksi * 16 + cKRow;
                    const int nO = wn * 64 + ntp * 16 + cN8;
                    ldsm_x4_t(b[2*ntp][0], b[2*ntp][1], b[2*ntp+1][0], b[2*ntp+1][1],
                              sB + (uint32_t)(kR * PBH + nO) * 2u);
                }
            }
            #pragma unroll
            for (int mt = 0; mt < 4; mt++)
                #pragma unroll
                for (int nt = 0; nt < 8; nt++)
                    mma_f16(acc[mt][nt], a[mt][0], a[mt][1], a[mt][2], a[mt][3],
                            b[nt][0], b[nt][1]);
        }
    }

    // ---- epilogue ----
    float rs[4][2];
    if (MODE == 1) {
        #pragma unroll
        for (int mt = 0; mt < 4; mt++) { rs[mt][0] = 0.f; rs[mt][1] = 0.f; }
    }
    #pragma unroll
    for (int mt = 0; mt < 4; mt++) {
        #pragma unroll
        for (int nt = 0; nt < 8; nt++) {
            const int n = n0 + wn * 64 + nt * 8 + tig * 2;
            float bv0 = 0.f, bv1 = 0.f;
            if (HASB) { bv0 = bias[n]; bv1 = bias[n + 1]; }
            #pragma unroll
            for (int h = 0; h < 2; h++) {
                const int m = m0 + wm * 64 + mt * 16 + g + h * 8;
                float x0 = alpha * acc[mt][nt][h * 2 + 0] + bv0;
                float x1 = alpha * acc[mt][nt][h * 2 + 1] + bv1;
                if (MODE == 1) {
                    x0 = __expf(x0); x1 = __expf(x1);
                    rs[mt][h] += x0 + x1;
                }
                if (MODE == 2) {
                    const float iv = rsIn[m];
                    x0 *= iv; x1 *= iv;
                }
                if (RELU) { x0 = fmaxf(x0, 0.f); x1 = fmaxf(x1, 0.f); }
                if (OUT_HALF) {
                    __half2 w = __floats2half2_rn(x0, x1);
                    *reinterpret_cast<__half2*>(Ch + (ll)m * ldc + n) = w;
                } else {
                    float2 w; w.x = x0; w.y = x1;
                    *reinterpret_cast<float2*>(Cf + (ll)m * ldc + n) = w;
                }
            }
        }
    }
    if (MODE == 1) {
        const int slot = blockIdx.x * 2 + wn;
        #pragma unroll
        for (int mt = 0; mt < 4; mt++)
            #pragma unroll
            for (int h = 0; h < 2; h++) {
                float v = rs[mt][h];
                v += __shfl_xor_sync(0xffffffffu, v, 1);
                v += __shfl_xor_sync(0xffffffffu, v, 2);
                if (tig == 0) {
                    const int m = m0 + wm * 64 + mt * 16 + g + h * 8;
                    rsOut[slot * 1024 + m] = v;
                }
            }
    }
}

// ---------------- reduce 16 row partials -> 1/rowsum ----------------
__global__ void rowsum_inv_kernel(const float* __restrict__ pr, float* __restrict__ inv,
                                  int nrows)
{
    const int t = blockIdx.x * blockDim.x + threadIdx.x;
    if (t >= nrows) return;
    const int z = t >> 10, m = t & 1023;
    const float* p = pr + (ll)z * 16384 + m;
    float s = 0.f;
    #pragma unroll
    for (int nb = 0; nb < 16; nb++) s += p[nb * 1024];
    inv[t] = 1.f / s;
}

// ---------------- fused fp32 -> fp16 conversion: 6 weight segments, one launch ------
__global__ void h_convert_all(const float4* s0, const float4* s1, const float4* s2,
                              const float4* s3, const float4* s4, const float4* s5,
                              uint2* d0, uint2* d1, uint2* d2,
                              uint2* d3, uint2* d4, uint2* d5,
                              int nbig, int nsmall)
{
    const int seg = blockIdx.y;
    const float4* src; uint2* dst; int n4;
    switch (seg) {
        case 0: src = s0; dst = d0; n4 = nbig;   break;
        case 1: src = s1; dst = d1; n4 = nbig;   break;
        case 2: src = s2; dst = d2; n4 = nbig;   break;
        case 3: src = s3; dst = d3; n4 = nbig;   break;
        case 4: src = s4; dst = d4; n4 = nsmall; break;
        default: src = s5; dst = d5; n4 = nsmall; break;
    }
    const int i = blockIdx.x * blockDim.x + threadIdx.x;
    if (i >= n4) return;
    const float4 v = src[i];
    __half2 lo = __floats2half2_rn(v.x, v.y);
    __half2 hi = __floats2half2_rn(v.z, v.w);
    uint2 o;
    o.x = *reinterpret_cast<uint32_t*>(&lo);
    o.y = *reinterpret_cast<uint32_t*>(&hi);
    dst[i] = o;
}

// ---------------- final split-K combine: out = P0 + P1 + P2 + bias + res ------------
__global__ void combine3_kernel(const float4* __restrict__ P0, const float4* __restrict__ P1,
                                const float4* __restrict__ P2,
                                const float* __restrict__ bias, const float4* __restrict__ res,
                                float4* __restrict__ out, int n4)
{
    const int i = blockIdx.x * blockDim.x + threadIdx.x;
    if (i >= n4) return;
    const int c = (i % (D_MODEL / 4)) * 4;
    const float4 p = P0[i], q = P1[i], s = P2[i], r = res[i];
    float4 o;
    o.x = p.x + q.x + s.x + bias[c + 0] + r.x;
    o.y = p.y + q.y + s.y + bias[c + 1] + r.y;
    o.z = p.z + q.z + s.z + bias[c + 2] + r.z;
    o.w = p.w + q.w + s.w + bias[c + 3] + r.w;
    out[i] = o;
}

// ---------------- fused split-K combine + LN2: one block per row --------------------
// X1 = P0+P1+P2 + bias + res (fp32, kept as final residual); Y = LN(X1) in fp16.
__global__ void combine_ln_kernel(const float4* __restrict__ P0, const float4* __restrict__ P1,
                                  const float4* __restrict__ P2,
                                  const float* __restrict__ bias, const float4* __restrict__ res,
                                  float4* __restrict__ X1out,
                                  const float4* __restrict__ gm, const float4* __restrict__ bt,
                                  uint2* __restrict__ y)
{
    const ll base = (ll)blockIdx.x * (D_MODEL / 4);
    const int t = threadIdx.x;                    // 0..191
    const ll i = base + t;

    const float4 p = P0[i], q = P1[i], s2 = P2[i], r = res[i];
    const float4 b4 = reinterpret_cast<const float4*>(bias)[t];
    float4 v;
    v.x = p.x + q.x + s2.x + b4.x + r.x;
    v.y = p.y + q.y + s2.y + b4.y + r.y;
    v.z = p.z + q.z + s2.z + b4.z + r.z;
    v.w = p.w + q.w + s2.w + b4.w + r.w;
    X1out[i] = v;

    float lsum = v.x + v.y + v.z + v.w;
    float lsq  = v.x * v.x + v.y * v.y + v.z * v.z + v.w * v.w;

    __shared__ float sh[12];
    #pragma unroll
    for (int o = 16; o; o >>= 1) {
        lsum += __shfl_xor_sync(0xffffffffu, lsum, o);
        lsq  += __shfl_xor_sync(0xffffffffu, lsq,  o);
    }
    const int wid = t >> 5, lane = t & 31;
    if (lane == 0) { sh[wid] = lsum; sh[6 + wid] = lsq; }
    __syncthreads();
    if (wid == 0) {
        float a = (lane < 6) ? sh[lane] : 0.f;
        float b = (lane < 6) ? sh[6 + lane] : 0.f;
        #pragma unroll
        for (int o = 4; o; o >>= 1) {
            a += __shfl_xor_sync(0xffffffffu, a, o);
            b += __shfl_xor_sync(0xffffffffu, b, o);
        }
        if (lane == 0) { sh[0] = a; sh[1] = b; }
    }
    __syncthreads();
    const float mu   = sh[0] * (1.f / D_MODEL);
    const float var  = sh[1] * (1.f / D_MODEL) - mu * mu;
    const float rstd = rsqrtf(var + LN_EPS);

    const float4 gv = gm[t];
    const float4 bv = bt[t];
    __half2 lo = __floats2half2_rn((v.x - mu) * rstd * gv.x + bv.x,
                                   (v.y - mu) * rstd * gv.y + bv.y);
    __half2 hi = __floats2half2_rn((v.z - mu) * rstd * gv.z + bv.z,
                                   (v.w - mu) * rstd * gv.w + bv.w);
    uint2 o;
    o.x = *reinterpret_cast<uint32_t*>(&lo);
    o.y = *reinterpret_cast<uint32_t*>(&hi);
    y[i] = o;
}

// ---------------- layernorm (LN1): fp32 in, fp16 out -------------------------------
__global__ void layernorm_kernel(const float4* __restrict__ x,
                                 const float4* __restrict__ gm,
                                 const float4* __restrict__ bt,
                                 uint2* __restrict__ y)
{
    const ll base = (ll)blockIdx.x * (D_MODEL / 4);
    const int t = threadIdx.x;
    const float4 v = x[base + t];
    float lsum = v.x + v.y + v.z + v.w;
    float lsq  = v.x * v.x + v.y * v.y + v.z * v.z + v.w * v.w;

    __shared__ float sh[12];
    #pragma unroll
    for (int o = 16; o; o >>= 1) {
        lsum += __shfl_xor_sync(0xffffffffu, lsum, o);
        lsq  += __shfl_xor_sync(0xffffffffu, lsq,  o);
    }
    const int wid = t >> 5, lane = t & 31;
    if (lane == 0) { sh[wid] = lsum; sh[6 + wid] = lsq; }
    __syncthreads();
    if (wid == 0) {
        float a = (lane < 6) ? sh[lane] : 0.f;
        float b = (lane < 6) ? sh[6 + lane] : 0.f;
        #pragma unroll
        for (int o = 4; o; o >>= 1) {
            a += __shfl_xor_sync(0xffffffffu, a, o);
            b += __shfl_xor_sync(0xffffffffu, b, o);
        }
        if (lane == 0) { sh[0] = a; sh[1] = b; }
    }
    __syncthreads();
    const float mu   = sh[0] * (1.f / D_MODEL);
    const float var  = sh[1] * (1.f / D_MODEL) - mu * mu;
    const float rstd = rsqrtf(var + LN_EPS);

    const float4 gv = gm[t];
    const float4 bv = bt[t];
    __half2 lo = __floats2half2_rn((v.x - mu) * rstd * gv.x + bv.x,
                                   (v.y - mu) * rstd * gv.y + bv.y);
    __half2 hi = __floats2half2_rn((v.z - mu) * rstd * gv.z + bv.z,
                                   (v.w - mu) * rstd * gv.w + bv.w);
    uint2 o;
    o.x = *reinterpret_cast<uint32_t*>(&lo);
    o.y = *reinterpret_cast<uint32_t*>(&hi);
    y[base + t] = o;
}

// ---------------- launch ----------------
#define SMEM_NN 107520
#define SMEM_NT 110592

extern "C" void kernel_launch(void* const* d_in, const int* in_sizes, int n_in,
                              void* d_out, int out_size)
{
    const float* x    = (const float*)d_in[0];
    const float* Wq   = (const float*)d_in[1];
    const float* Wk   = (const float*)d_in[2];
    const float* Wv   = (const float*)d_in[3];
    const float* Wu   = (const float*)d_in[4];
    const float* bu   = (const float*)d_in[5];
    const float* ln1g = (const float*)d_in[6];
    const float* ln1b = (const float*)d_in[7];
    const float* ln2g = (const float*)d_in[8];
    const float* ln2b = (const float*)d_in[9];
    const float* W1   = (const float*)d_in[10];
    const float* b1   = (const float*)d_in[11];
    const float* W2   = (const float*)d_in[12];
    const float* b2   = (const float*)d_in[13];
    float* out = (float*)d_out;

    __half *Y, *QKV, *S, *ATT, *H1, *Wqkv, *WuH, *W1H, *W2H;
    float *X1, *P, *RS;
    cudaGetSymbolAddress((void**)&Y,    g_Yh);
    cudaGetSymbolAddress((void**)&QKV,  g_QKVh);
    cudaGetSymbolAddress((void**)&S,    g_Sh);
    cudaGetSymbolAddress((void**)&ATT,  g_ATTh);
    cudaGetSymbolAddress((void**)&H1,   g_H1h);
    cudaGetSymbolAddress((void**)&X1,   g_X1);
    cudaGetSymbolAddress((void**)&P,    g_P);
    cudaGetSymbolAddress((void**)&RS,   g_RS);
    cudaGetSymbolAddress((void**)&Wqkv, g_WqkvH);
    cudaGetSymbolAddress((void**)&WuH,  g_WuH);
    cudaGetSymbolAddress((void**)&W1H,  g_W1H);
    cudaGetSymbolAddress((void**)&W2H,  g_W2H);

    __half* Q  = QKV;
    __half* Kp = QKV + (size_t)NTOK * DH;
    __half* V  = QKV + (size_t)2 * NTOK * DH;

    float* P0 = P;
    float* P1 = P + (size_t)NTOK * D_MODEL;
    float* P2 = P + (size_t)2 * NTOK * D_MODEL;

    cudaFuncSetAttribute(gemm_h<false,false,false,true ,0>, cudaFuncAttributeMaxDynamicSharedMemorySize, SMEM_NN);
    cudaFuncSetAttribute(gemm_h<true ,false,false,true ,1>, cudaFuncAttributeMaxDynamicSharedMemorySize, SMEM_NT);
    cudaFuncSetAttribute(gemm_h<false,false,false,true ,2>, cudaFuncAttributeMaxDynamicSharedMemorySize, SMEM_NN);
    cudaFuncSetAttribute(gemm_h<false,true ,true ,true ,0>, cudaFuncAttributeMaxDynamicSharedMemorySize, SMEM_NN);
    cudaFuncSetAttribute(gemm_h<false,false,false,false,0>, cudaFuncAttributeMaxDynamicSharedMemorySize, SMEM_NN);

    const float inv_sqrt_d = 0.03608439182435161f;   // 1/sqrt(768)

    // 0) weight conversions (one launch) + LN1
    {
        const int nbig = D_MODEL * DH / 4, nsmall = D_MODEL * DFF / 4;
        dim3 grid((nbig + 255) / 256, 6, 1);
        h_convert_all<<<grid, 256>>>(
            (const float4*)Wq, (const float4*)Wk, (const float4*)Wv,
            (const float4*)Wu, (const float4*)W1, (const float4*)W2,
            (uint2*)Wqkv,
            (uint2*)(Wqkv + (size_t)D_MODEL * DH),
            (uint2*)(Wqkv + (size_t)2 * D_MODEL * DH),
            (uint2*)WuH, (uint2*)W1H, (uint2*)W2H,
            nbig, nsmall);
    }
    layernorm_kernel<<<NTOK, 192>>>((const float4*)x, (const float4*)ln1g,
                                    (const float4*)ln1b, (uint2*)Y);

    // 1) QKV = Y @ [Wq|Wk|Wv] (one launch, z=3)
    {
        dim3 grid(DH / 128, NTOK / 128, 3);
        gemm_h<false,false,false,true,0><<<grid, 128, SMEM_NN>>>(Y, Wqkv, nullptr, QKV, nullptr,
            D_MODEL, D_MODEL, DH, DH, 1.f,
            0, 0, 0, (ll)D_MODEL * DH, 0, (ll)NTOK * DH, 3);
    }

    // 2) expS[b,h] = exp(Q_bh @ K_bh^T / sqrt(768)) + row partial sums (MODE 1)
    {
        dim3 grid(SEQ / 128, SEQ / 128, BATCH * NHEAD);
        gemm_h<true,false,false,true,1><<<grid, 128, SMEM_NT>>>(Q, Kp, nullptr, S, P,
            D_MODEL, DH, DH, SEQ, inv_sqrt_d,
            (ll)SEQ * DH, (ll)D_MODEL,
            (ll)SEQ * DH, (ll)D_MODEL,
            (ll)NHEAD * SEQ * SEQ, (ll)SEQ * SEQ,
            NHEAD);
    }

    // 3) 1/rowsum from 16 partials per row
    {
        const int nrows = BATCH * NHEAD * SEQ;
        rowsum_inv_kernel<<<(nrows + 255) / 256, 256>>>(P, RS, nrows);
    }

    // 4) ATT = (expS @ V) * (1/rowsum)  (MODE 2 — deferred softmax normalization)
    {
        dim3 grid(D_MODEL / 128, SEQ / 128, BATCH * NHEAD);
        gemm_h<false,false,false,true,2><<<grid, 128, SMEM_NN>>>(S, V, nullptr, ATT, RS,
            SEQ, SEQ, DH, DH, 1.f,
            (ll)NHEAD * SEQ * SEQ, (ll)SEQ * SEQ,
            (ll)SEQ * DH, (ll)D_MODEL,
            (ll)SEQ * DH, (ll)D_MODEL,
            NHEAD);
    }

    // 5) Wu split-K=3 (overwrites g_P — rowsum partials dead), then fused combine+LN2
    {
        dim3 grid(D_MODEL / 128, NTOK / 128, 3);
        gemm_h<false,false,false,false,0><<<grid, 128, SMEM_NN>>>(ATT, WuH, nullptr, P0, nullptr,
            DH / 3, DH, D_MODEL, D_MODEL, 1.f,
            0, (ll)(DH / 3),
            0, (ll)(DH / 3) * D_MODEL,
            0, (ll)NTOK * D_MODEL,
            3);
        combine_ln_kernel<<<NTOK, 192>>>((const float4*)P0, (const float4*)P1,
                                         (const float4*)P2, bu, (const float4*)x,
                                         (float4*)X1,
                                         (const float4*)ln2g, (const float4*)ln2b,
                                         (uint2*)Y);
    }

    // 6) H1 = relu(Y @ W1 + b1)
    {
        dim3 grid(DFF / 128, NTOK / 128, 1);
        gemm_h<false,true,true,true,0><<<grid, 128, SMEM_NN>>>(Y, W1H, b1, H1, nullptr,
            D_MODEL, D_MODEL, DFF, DFF, 1.f, 0,0,0,0,0,0, 1);
    }

    // 7) W2 split-K=3, then out = P0+P1+P2 + b2 + X1
    {
        dim3 grid(D_MODEL / 128, NTOK / 128, 3);
        gemm_h<false,false,false,false,0><<<grid, 128, SMEM_NN>>>(H1, W2H, nullptr, P0, nullptr,
            DFF / 3, DFF, D_MODEL, D_MODEL, 1.f,
            0, (ll)(DFF / 3),
            0, (ll)(DFF / 3) * D_MODEL,
            0, (ll)NTOK * D_MODEL,
            3);
        const int n4 = NTOK * D_MODEL / 4;
        combine3_kernel<<<(n4 + 255) / 256, 256>>>((const float4*)P0, (const float4*)P1,
                                                   (const float4*)P2, b2,
                                                   (const float4*)X1, (float4*)out, n4);
    }

    (void)in_sizes; (void)n_in; (void)out_size;
}

// round 15
// speedup vs baseline: 2.0312x; 1.0079x over previous
#include <cuda_runtime.h>
#include <cuda_fp16.h>
#include <cstdint>

#define D_MODEL 768
#define NHEAD   12
#define SEQ     1024
#define BATCH   4
#define NTOK    (BATCH*SEQ)        /* 4096 */
#define DH      (D_MODEL*NHEAD)    /* 9216 */
#define DFF     (4*D_MODEL)        /* 3072 */
#define LN_EPS  1e-5f

typedef long long ll;

// ---------------- scratch (device globals; no allocation allowed) ----------------
__device__ __half g_Yh   [(size_t)NTOK * D_MODEL];
__device__ __half g_QKVh [(size_t)3 * NTOK * DH];          // Q | K | V slabs
__device__ __half g_Sh   [(size_t)BATCH * NHEAD * SEQ * SEQ];   // exp(scores)
__device__ __half g_ATTh [(size_t)NTOK * DH];
__device__ __half g_H1h  [(size_t)NTOK * DFF];
__device__ float  g_X1   [(size_t)NTOK * D_MODEL];
__device__ float  g_P    [(size_t)3 * NTOK * D_MODEL];     // split-K partials / rowsum partials
__device__ float  g_RS   [(size_t)BATCH * NHEAD * SEQ];    // 1/rowsum
__device__ __half g_WqkvH[(size_t)3 * D_MODEL * DH];
__device__ __half g_WuH  [(size_t)DH * D_MODEL];
__device__ __half g_W1H  [(size_t)D_MODEL * DFF];
__device__ __half g_W2H  [(size_t)DFF * D_MODEL];

// ---------------- helpers ----------------
__device__ __forceinline__ uint32_t smem_u32(const void* p) {
    uint32_t a;
    asm("{ .reg .u64 t; cvta.to.shared.u64 t, %1; cvt.u32.u64 %0, t; }" : "=r"(a) : "l"(p));
    return a;
}
__device__ __forceinline__ void cp16(uint32_t dst, const void* src) {
    asm volatile("cp.async.cg.shared.global [%0], [%1], 16;" :: "r"(dst), "l"(src) : "memory");
}
__device__ __forceinline__ void cp_commit() {
    asm volatile("cp.async.commit_group;" ::: "memory");
}
template<int N>
__device__ __forceinline__ void cp_wait() {
    asm volatile("cp.async.wait_group %0;" :: "n"(N) : "memory");
}
__device__ __forceinline__ void ldsm_x4(uint32_t& r0, uint32_t& r1, uint32_t& r2, uint32_t& r3,
                                        uint32_t addr) {
    asm volatile("ldmatrix.sync.aligned.m8n8.x4.shared.b16 {%0,%1,%2,%3}, [%4];"
                 : "=r"(r0), "=r"(r1), "=r"(r2), "=r"(r3) : "r"(addr));
}
__device__ __forceinline__ void ldsm_x4_t(uint32_t& r0, uint32_t& r1, uint32_t& r2, uint32_t& r3,
                                          uint32_t addr) {
    asm volatile("ldmatrix.sync.aligned.m8n8.x4.trans.shared.b16 {%0,%1,%2,%3}, [%4];"
                 : "=r"(r0), "=r"(r1), "=r"(r2), "=r"(r3) : "r"(addr));
}
__device__ __forceinline__ float ex2f(float x) {          // 2^x via MUFU.EX2 (same unit __expf uses)
    float r;
    asm("ex2.approx.ftz.f32 %0, %1;" : "=f"(r) : "f"(x));
    return r;
}
__device__ __forceinline__ void mma_f16(float c[4],
                                        uint32_t a0, uint32_t a1, uint32_t a2, uint32_t a3,
                                        uint32_t b0, uint32_t b1) {
    asm("mma.sync.aligned.m16n8k16.row.col.f32.f16.f16.f32 "
        "{%0,%1,%2,%3}, {%4,%5,%6,%7}, {%8,%9}, {%0,%1,%2,%3};"
        : "+f"(c[0]), "+f"(c[1]), "+f"(c[2]), "+f"(c[3])
        : "r"(a0), "r"(a1), "r"(a2), "r"(a3), "r"(b0), "r"(b1));
}

// ---------------- fp16 tensor-core GEMM (R12 mainloop unchanged) -------------------
// MODE 0: plain.
// MODE 1: epilogue x = 2^(alpha*acc)  [alpha carries 1/sqrt(d)*log2(e)], emit
//   per-slice row partial sums to rsPtr[(z*16 + bx*2+wn)*1024 + m] (deterministic).
// MODE 2: epilogue scales by rsPtr[z*1024 + m] (1/rowsum, deferred softmax norm);
//   the 8 per-thread row values are hoisted into registers before the store loop.
template<bool BT, bool RELU, bool HASB, bool OUT_HALF, int MODE>
__global__ __launch_bounds__(128, 2)
void gemm_h(const __half* __restrict__ A, const __half* __restrict__ B,
            const float* __restrict__ bias, void* __restrict__ Cv,
            float* __restrict__ rsPtr,
            int K, int lda, int ldb, int ldc, float alpha,
            ll saO, ll saI, ll sbO, ll sbI, ll scO, ll scI, int innerCnt)
{
    constexpr int STAGES  = 3;
    constexpr int PAH     = 72;
    constexpr int PBH     = 136;
    constexpr int A_H     = 128 * PAH;
    constexpr int B_H     = BT ? 128 * PAH : 64 * PBH;
    constexpr int STAGE_H = A_H + B_H;

    extern __shared__ __half dynsm[];

    const int tid  = threadIdx.x;
    const int wid  = tid >> 5;
    const int lane = tid & 31;
    const int g    = lane >> 2;
    const int tig  = lane & 3;
    const int wm   = wid >> 1;
    const int wn   = wid & 1;

    const int mi = lane >> 3;
    const int r8 = lane & 7;
    const int aRowOff = (mi & 1) * 8 + r8;
    const int aK8     = (mi >> 1) * 8;
    const int bRowOff = (mi >> 1) * 8 + r8;
    const int bK8     = (mi & 1) * 8;
    const int cKRow   = (mi & 1) * 8 + r8;
    const int cN8     = (mi >> 1) * 8;

    const int z  = blockIdx.z;
    const int zo = z / innerCnt;
    const int zi = z - zo * innerCnt;
    A += zo * saO + zi * saI;
    B += zo * sbO + zi * sbI;
    __half* Ch = (__half*)Cv + zo * scO + zi * scI;
    float*  Cf = (float*) Cv + zo * scO + zi * scI;
    float*       rsOut = (MODE == 1) ? rsPtr + (ll)z * 16384 : nullptr;
    const float* rsIn  = (MODE == 2) ? rsPtr + (ll)z * 1024  : nullptr;

    const int m0 = blockIdx.y * 128;
    const int n0 = blockIdx.x * 128;
    A += (ll)m0 * lda;
    B += BT ? (ll)n0 * ldb : (ll)n0;

    const uint32_t smb = smem_u32(dynsm);

    auto issue = [&](int tile) {
        const int stage = tile % STAGES;
        const uint32_t sA = smb + (uint32_t)(stage * STAGE_H) * 2u;
        const uint32_t sB = sA + (uint32_t)A_H * 2u;
        const int k0 = tile * 64;
        #pragma unroll
        for (int i = 0; i < 8; i++) {
            const int v = tid + i * 128;
            const int m = v >> 3, c = (v & 7) * 8;
            cp16(sA + (uint32_t)(m * PAH + c) * 2u, A + (ll)m * lda + k0 + c);
        }
        #pragma unroll
        for (int i = 0; i < 8; i++) {
            const int v = tid + i * 128;
            if (BT) {
                const int n = v >> 3, c = (v & 7) * 8;
                cp16(sB + (uint32_t)(n * PAH + c) * 2u, B + (ll)n * ldb + k0 + c);
            } else {
                const int k = v >> 4, c = (v & 15) * 8;
                cp16(sB + (uint32_t)(k * PBH + c) * 2u, B + (ll)(k0 + k) * ldb + c);
            }
        }
        cp_commit();
    };

    float acc[4][8][4];
    #pragma unroll
    for (int mt = 0; mt < 4; mt++)
        #pragma unroll
        for (int nt = 0; nt < 8; nt++)
            #pragma unroll
            for (int rr = 0; rr < 4; rr++) acc[mt][nt][rr] = 0.f;

    const int T = K >> 6;
    issue(0); issue(1);

    for (int it = 0; it < T; ++it) {
        cp_wait<1>();
        __syncthreads();
        if (it + 2 < T) issue(it + 2);

        const uint32_t sA = smb + (uint32_t)((it % STAGES) * STAGE_H) * 2u;
        const uint32_t sB = sA + (uint32_t)A_H * 2u;

        #pragma unroll
        for (int ksi = 0; ksi < 4; ksi++) {
            uint32_t a[4][4], b[8][2];
            #pragma unroll
            for (int mt = 0; mt < 4; mt++) {
                const int m = wm * 64 + mt * 16 + aRowOff;
                ldsm_x4(a[mt][0], a[mt][1], a[mt][2], a[mt][3],
                        sA + (uint32_t)(m * PAH + ksi * 16 + aK8) * 2u);
            }
            if (BT) {
                #pragma unroll
                for (int ntp = 0; ntp < 4; ntp++) {
                    const int n = wn * 64 + ntp * 16 + bRowOff;
                    ldsm_x4(b[2*ntp][0], b[2*ntp][1], b[2*ntp+1][0], b[2*ntp+1][1],
                            sB + (uint32_t)(n * PAH + ksi * 16 + bK8) * 2u);
                }
            } else {
                #pragma unroll
                for (int ntp = 0; ntp < 4; ntp++) {
                    const int kR = ksi * 16 + cKRow;
                    const int nO = wn * 64 + ntp * 16 + cN8;
                    ldsm_x4_t(b[2*ntp][0], b[2*ntp][1], b[2*ntp+1][0], b[2*ntp+1][1],
                              sB + (uint32_t)(kR * PBH + nO) * 2u);
                }
            }
            #pragma unroll
            for (int mt = 0; mt < 4; mt++)
                #pragma unroll
                for (int nt = 0; nt < 8; nt++)
                    mma_f16(acc[mt][nt], a[mt][0], a[mt][1], a[mt][2], a[mt][3],
                            b[nt][0], b[nt][1]);
        }
    }

    // ---- epilogue ----
    float rs[4][2];
    if (MODE == 1) {
        #pragma unroll
        for (int mt = 0; mt < 4; mt++) { rs[mt][0] = 0.f; rs[mt][1] = 0.f; }
    }
    float inv[4][2];
    if (MODE == 2) {
        #pragma unroll
        for (int mt = 0; mt < 4; mt++)
            #pragma unroll
            for (int h = 0; h < 2; h++)
                inv[mt][h] = rsIn[m0 + wm * 64 + mt * 16 + g + h * 8];
    }
    #pragma unroll
    for (int mt = 0; mt < 4; mt++) {
        #pragma unroll
        for (int nt = 0; nt < 8; nt++) {
            const int n = n0 + wn * 64 + nt * 8 + tig * 2;
            float bv0 = 0.f, bv1 = 0.f;
            if (HASB) { bv0 = bias[n]; bv1 = bias[n + 1]; }
            #pragma unroll
            for (int h = 0; h < 2; h++) {
                const int m = m0 + wm * 64 + mt * 16 + g + h * 8;
                float x0 = alpha * acc[mt][nt][h * 2 + 0] + bv0;
                float x1 = alpha * acc[mt][nt][h * 2 + 1] + bv1;
                if (MODE == 1) {
                    x0 = ex2f(x0); x1 = ex2f(x1);      // alpha carries log2(e) factor
                    rs[mt][h] += x0 + x1;
                }
                if (MODE == 2) {
                    x0 *= inv[mt][h]; x1 *= inv[mt][h];
                }
                if (RELU) { x0 = fmaxf(x0, 0.f); x1 = fmaxf(x1, 0.f); }
                if (OUT_HALF) {
                    __half2 w = __floats2half2_rn(x0, x1);
                    *reinterpret_cast<__half2*>(Ch + (ll)m * ldc + n) = w;
                } else {
                    float2 w; w.x = x0; w.y = x1;
                    *reinterpret_cast<float2*>(Cf + (ll)m * ldc + n) = w;
                }
            }
        }
    }
    if (MODE == 1) {
        const int slot = blockIdx.x * 2 + wn;
        #pragma unroll
        for (int mt = 0; mt < 4; mt++)
            #pragma unroll
            for (int h = 0; h < 2; h++) {
                float v = rs[mt][h];
                v += __shfl_xor_sync(0xffffffffu, v, 1);
                v += __shfl_xor_sync(0xffffffffu, v, 2);
                if (tig == 0) {
                    const int m = m0 + wm * 64 + mt * 16 + g + h * 8;
                    rsOut[slot * 1024 + m] = v;
                }
            }
    }
}

// ---------------- reduce 16 row partials -> 1/rowsum (float4 reads) ----------------
__global__ void rowsum_inv_kernel(const float4* __restrict__ pr, float* __restrict__ inv,
                                  int nrows)
{
    const int t = blockIdx.x * blockDim.x + threadIdx.x;
    if (t >= nrows) return;
    const int z = t >> 10, m = t & 1023;
    // partials laid out [z][16][1024]; gather 16 strided values for row m.
    const float* p = reinterpret_cast<const float*>(pr) + (ll)z * 16384 + m;
    float s = 0.f;
    #pragma unroll
    for (int nb = 0; nb < 16; nb++) s += p[nb * 1024];
    inv[t] = 1.f / s;
}

// ---------------- fused fp32 -> fp16 conversion: 6 weight segments, one launch ------
__global__ void h_convert_all(const float4* s0, const float4* s1, const float4* s2,
                              const float4* s3, const float4* s4, const float4* s5,
                              uint2* d0, uint2* d1, uint2* d2,
                              uint2* d3, uint2* d4, uint2* d5,
                              int nbig, int nsmall)
{
    const int seg = blockIdx.y;
    const float4* src; uint2* dst; int n4;
    switch (seg) {
        case 0: src = s0; dst = d0; n4 = nbig;   break;
        case 1: src = s1; dst = d1; n4 = nbig;   break;
        case 2: src = s2; dst = d2; n4 = nbig;   break;
        case 3: src = s3; dst = d3; n4 = nbig;   break;
        case 4: src = s4; dst = d4; n4 = nsmall; break;
        default: src = s5; dst = d5; n4 = nsmall; break;
    }
    const int i = blockIdx.x * blockDim.x + threadIdx.x;
    if (i >= n4) return;
    const float4 v = src[i];
    __half2 lo = __floats2half2_rn(v.x, v.y);
    __half2 hi = __floats2half2_rn(v.z, v.w);
    uint2 o;
    o.x = *reinterpret_cast<uint32_t*>(&lo);
    o.y = *reinterpret_cast<uint32_t*>(&hi);
    dst[i] = o;
}

// ---------------- final split-K combine: out = P0 + P1 + P2 + bias + res ------------
__global__ void combine3_kernel(const float4* __restrict__ P0, const float4* __restrict__ P1,
                                const float4* __restrict__ P2,
                                const float* __restrict__ bias, const float4* __restrict__ res,
                                float4* __restrict__ out, int n4)
{
    const int i = blockIdx.x * blockDim.x + threadIdx.x;
    if (i >= n4) return;
    const int c = (i % (D_MODEL / 4)) * 4;
    const float4 p = P0[i], q = P1[i], s = P2[i], r = res[i];
    float4 o;
    o.x = p.x + q.x + s.x + bias[c + 0] + r.x;
    o.y = p.y + q.y + s.y + bias[c + 1] + r.y;
    o.z = p.z + q.z + s.z + bias[c + 2] + r.z;
    o.w = p.w + q.w + s.w + bias[c + 3] + r.w;
    out[i] = o;
}

// ---------------- fused split-K combine + LN2: one block per row --------------------
__global__ void combine_ln_kernel(const float4* __restrict__ P0, const float4* __restrict__ P1,
                                  const float4* __restrict__ P2,
                                  const float* __restrict__ bias, const float4* __restrict__ res,
                                  float4* __restrict__ X1out,
                                  const float4* __restrict__ gm, const float4* __restrict__ bt,
                                  uint2* __restrict__ y)
{
    const ll base = (ll)blockIdx.x * (D_MODEL / 4);
    const int t = threadIdx.x;                    // 0..191
    const ll i = base + t;

    const float4 p = P0[i], q = P1[i], s2 = P2[i], r = res[i];
    const float4 b4 = reinterpret_cast<const float4*>(bias)[t];
    float4 v;
    v.x = p.x + q.x + s2.x + b4.x + r.x;
    v.y = p.y + q.y + s2.y + b4.y + r.y;
    v.z = p.z + q.z + s2.z + b4.z + r.z;
    v.w = p.w + q.w + s2.w + b4.w + r.w;
    X1out[i] = v;

    float lsum = v.x + v.y + v.z + v.w;
    float lsq  = v.x * v.x + v.y * v.y + v.z * v.z + v.w * v.w;

    __shared__ float sh[12];
    #pragma unroll
    for (int o = 16; o; o >>= 1) {
        lsum += __shfl_xor_sync(0xffffffffu, lsum, o);
        lsq  += __shfl_xor_sync(0xffffffffu, lsq,  o);
    }
    const int wid = t >> 5, lane = t & 31;
    if (lane == 0) { sh[wid] = lsum; sh[6 + wid] = lsq; }
    __syncthreads();
    if (wid == 0) {
        float a = (lane < 6) ? sh[lane] : 0.f;
        float b = (lane < 6) ? sh[6 + lane] : 0.f;
        #pragma unroll
        for (int o = 4; o; o >>= 1) {
            a += __shfl_xor_sync(0xffffffffu, a, o);
            b += __shfl_xor_sync(0xffffffffu, b, o);
        }
        if (lane == 0) { sh[0] = a; sh[1] = b; }
    }
    __syncthreads();
    const float mu   = sh[0] * (1.f / D_MODEL);
    const float var  = sh[1] * (1.f / D_MODEL) - mu * mu;
    const float rstd = rsqrtf(var + LN_EPS);

    const float4 gv = gm[t];
    const float4 bv = bt[t];
    __half2 lo = __floats2half2_rn((v.x - mu) * rstd * gv.x + bv.x,
                                   (v.y - mu) * rstd * gv.y + bv.y);
    __half2 hi = __floats2half2_rn((v.z - mu) * rstd * gv.z + bv.z,
                                   (v.w - mu) * rstd * gv.w + bv.w);
    uint2 o;
    o.x = *reinterpret_cast<uint32_t*>(&lo);
    o.y = *reinterpret_cast<uint32_t*>(&hi);
    y[i] = o;
}

// ---------------- layernorm (LN1): fp32 in, fp16 out -------------------------------
__global__ void layernorm_kernel(const float4* __restrict__ x,
                                 const float4* __restrict__ gm,
                                 const float4* __restrict__ bt,
                                 uint2* __restrict__ y)
{
    const ll base = (ll)blockIdx.x * (D_MODEL / 4);
    const int t = threadIdx.x;
    const float4 v = x[base + t];
    float lsum = v.x + v.y + v.z + v.w;
    float lsq  = v.x * v.x + v.y * v.y + v.z * v.z + v.w * v.w;

    __shared__ float sh[12];
    #pragma unroll
    for (int o = 16; o; o >>= 1) {
        lsum += __shfl_xor_sync(0xffffffffu, lsum, o);
        lsq  += __shfl_xor_sync(0xffffffffu, lsq,  o);
    }
    const int wid = t >> 5, lane = t & 31;
    if (lane == 0) { sh[wid] = lsum; sh[6 + wid] = lsq; }
    __syncthreads();
    if (wid == 0) {
        float a = (lane < 6) ? sh[lane] : 0.f;
        float b = (lane < 6) ? sh[6 + lane] : 0.f;
        #pragma unroll
        for (int o = 4; o; o >>= 1) {
            a += __shfl_xor_sync(0xffffffffu, a, o);
            b += __shfl_xor_sync(0xffffffffu, b, o);
        }
        if (lane == 0) { sh[0] = a; sh[1] = b; }
    }
    __syncthreads();
    const float mu   = sh[0] * (1.f / D_MODEL);
    const float var  = sh[1] * (1.f / D_MODEL) - mu * mu;
    const float rstd = rsqrtf(var + LN_EPS);

    const float4 gv = gm[t];
    const float4 bv = bt[t];
    __half2 lo = __floats2half2_rn((v.x - mu) * rstd * gv.x + bv.x,
                                   (v.y - mu) * rstd * gv.y + bv.y);
    __half2 hi = __floats2half2_rn((v.z - mu) * rstd * gv.z + bv.z,
                                   (v.w - mu) * rstd * gv.w + bv.w);
    uint2 o;
    o.x = *reinterpret_cast<uint32_t*>(&lo);
    o.y = *reinterpret_cast<uint32_t*>(&hi);
    y[base + t] = o;
}

// ---------------- launch ----------------
#define SMEM_NN 107520
#define SMEM_NT 110592

extern "C" void kernel_launch(void* const* d_in, const int* in_sizes, int n_in,
                              void* d_out, int out_size)
{
    const float* x    = (const float*)d_in[0];
    const float* Wq   = (const float*)d_in[1];
    const float* Wk   = (const float*)d_in[2];
    const float* Wv   = (const float*)d_in[3];
    const float* Wu   = (const float*)d_in[4];
    const float* bu   = (const float*)d_in[5];
    const float* ln1g = (const float*)d_in[6];
    const float* ln1b = (const float*)d_in[7];
    const float* ln2g = (const float*)d_in[8];
    const float* ln2b = (const float*)d_in[9];
    const float* W1   = (const float*)d_in[10];
    const float* b1   = (const float*)d_in[11];
    const float* W2   = (const float*)d_in[12];
    const float* b2   = (const float*)d_in[13];
    float* out = (float*)d_out;

    __half *Y, *QKV, *S, *ATT, *H1, *Wqkv, *WuH, *W1H, *W2H;
    float *X1, *P, *RS;
    cudaGetSymbolAddress((void**)&Y,    g_Yh);
    cudaGetSymbolAddress((void**)&QKV,  g_QKVh);
    cudaGetSymbolAddress((void**)&S,    g_Sh);
    cudaGetSymbolAddress((void**)&ATT,  g_ATTh);
    cudaGetSymbolAddress((void**)&H1,   g_H1h);
    cudaGetSymbolAddress((void**)&X1,   g_X1);
    cudaGetSymbolAddress((void**)&P,    g_P);
    cudaGetSymbolAddress((void**)&RS,   g_RS);
    cudaGetSymbolAddress((void**)&Wqkv, g_WqkvH);
    cudaGetSymbolAddress((void**)&WuH,  g_WuH);
    cudaGetSymbolAddress((void**)&W1H,  g_W1H);
    cudaGetSymbolAddress((void**)&W2H,  g_W2H);

    __half* Q  = QKV;
    __half* Kp = QKV + (size_t)NTOK * DH;
    __half* V  = QKV + (size_t)2 * NTOK * DH;

    float* P0 = P;
    float* P1 = P + (size_t)NTOK * D_MODEL;
    float* P2 = P + (size_t)2 * NTOK * D_MODEL;

    cudaFuncSetAttribute(gemm_h<false,false,false,true ,0>, cudaFuncAttributeMaxDynamicSharedMemorySize, SMEM_NN);
    cudaFuncSetAttribute(gemm_h<true ,false,false,true ,1>, cudaFuncAttributeMaxDynamicSharedMemorySize, SMEM_NT);
    cudaFuncSetAttribute(gemm_h<false,false,false,true ,2>, cudaFuncAttributeMaxDynamicSharedMemorySize, SMEM_NN);
    cudaFuncSetAttribute(gemm_h<false,true ,true ,true ,0>, cudaFuncAttributeMaxDynamicSharedMemorySize, SMEM_NN);
    cudaFuncSetAttribute(gemm_h<false,false,false,false,0>, cudaFuncAttributeMaxDynamicSharedMemorySize, SMEM_NN);

    // alpha for MODE 1 carries both 1/sqrt(768) and log2(e): exp(s) = 2^(s*log2e)
    const float alpha_exp2 = 0.03608439182435161f * 1.4426950408889634f;

    // 0) weight conversions (one launch) + LN1
    {
        const int nbig = D_MODEL * DH / 4, nsmall = D_MODEL * DFF / 4;
        dim3 grid((nbig + 255) / 256, 6, 1);
        h_convert_all<<<grid, 256>>>(
            (const float4*)Wq, (const float4*)Wk, (const float4*)Wv,
            (const float4*)Wu, (const float4*)W1, (const float4*)W2,
            (uint2*)Wqkv,
            (uint2*)(Wqkv + (size_t)D_MODEL * DH),
            (uint2*)(Wqkv + (size_t)2 * D_MODEL * DH),
            (uint2*)WuH, (uint2*)W1H, (uint2*)W2H,
            nbig, nsmall);
    }
    layernorm_kernel<<<NTOK, 192>>>((const float4*)x, (const float4*)ln1g,
                                    (const float4*)ln1b, (uint2*)Y);

    // 1) QKV = Y @ [Wq|Wk|Wv] (one launch, z=3)
    {
        dim3 grid(DH / 128, NTOK / 128, 3);
        gemm_h<false,false,false,true,0><<<grid, 128, SMEM_NN>>>(Y, Wqkv, nullptr, QKV, nullptr,
            D_MODEL, D_MODEL, DH, DH, 1.f,
            0, 0, 0, (ll)D_MODEL * DH, 0, (ll)NTOK * DH, 3);
    }

    // 2) expS[b,h] = 2^(alpha_exp2 * Q_bh @ K_bh^T) + row partial sums (MODE 1)
    {
        dim3 grid(SEQ / 128, SEQ / 128, BATCH * NHEAD);
        gemm_h<true,false,false,true,1><<<grid, 128, SMEM_NT>>>(Q, Kp, nullptr, S, P,
            D_MODEL, DH, DH, SEQ, alpha_exp2,
            (ll)SEQ * DH, (ll)D_MODEL,
            (ll)SEQ * DH, (ll)D_MODEL,
            (ll)NHEAD * SEQ * SEQ, (ll)SEQ * SEQ,
            NHEAD);
    }

    // 3) 1/rowsum from 16 partials per row
    {
        const int nrows = BATCH * NHEAD * SEQ;
        rowsum_inv_kernel<<<(nrows + 255) / 256, 256>>>((const float4*)P, RS, nrows);
    }

    // 4) ATT = (expS @ V) * (1/rowsum)  (MODE 2 — deferred softmax normalization)
    {
        dim3 grid(D_MODEL / 128, SEQ / 128, BATCH * NHEAD);
        gemm_h<false,false,false,true,2><<<grid, 128, SMEM_NN>>>(S, V, nullptr, ATT, RS,
            SEQ, SEQ, DH, DH, 1.f,
            (ll)NHEAD * SEQ * SEQ, (ll)SEQ * SEQ,
            (ll)SEQ * DH, (ll)D_MODEL,
            (ll)SEQ * DH, (ll)D_MODEL,
            NHEAD);
    }

    // 5) Wu split-K=3 (overwrites g_P — rowsum partials dead), then fused combine+LN2
    {
        dim3 grid(D_MODEL / 128, NTOK / 128, 3);
        gemm_h<false,false,false,false,0><<<grid, 128, SMEM_NN>>>(ATT, WuH, nullptr, P0, nullptr,
            DH / 3, DH, D_MODEL, D_MODEL, 1.f,
            0, (ll)(DH / 3),
            0, (ll)(DH / 3) * D_MODEL,
            0, (ll)NTOK * D_MODEL,
            3);
        combine_ln_kernel<<<NTOK, 192>>>((const float4*)P0, (const float4*)P1,
                                         (const float4*)P2, bu, (const float4*)x,
                                         (float4*)X1,
                                         (const float4*)ln2g, (const float4*)ln2b,
                                         (uint2*)Y);
    }

    // 6) H1 = relu(Y @ W1 + b1)
    {
        dim3 grid(DFF / 128, NTOK / 128, 1);
        gemm_h<false,true,true,true,0><<<grid, 128, SMEM_NN>>>(Y, W1H, b1, H1, nullptr,
            D_MODEL, D_MODEL, DFF, DFF, 1.f, 0,0,0,0,0,0, 1);
    }

    // 7) W2 split-K=3, then out = P0+P1+P2 + b2 + X1
    {
        dim3 grid(D_MODEL / 128, NTOK / 128, 3);
        gemm_h<false,false,false,false,0><<<grid, 128, SMEM_NN>>>(H1, W2H, nullptr, P0, nullptr,
            DFF / 3, DFF, D_MODEL, D_MODEL, 1.f,
            0, (ll)(DFF / 3),
            0, (ll)(DFF / 3) * D_MODEL,
            0, (ll)NTOK * D_MODEL,
            3);
        const int n4 = NTOK * D_MODEL / 4;
        combine3_kernel<<<(n4 + 255) / 256, 256>>>((const float4*)P0, (const float4*)P1,
                                                   (const float4*)P2, b2,
                                                   (const float4*)X1, (float4*)out, n4);
    }

    (void)in_sizes; (void)n_in; (void)out_size;
}

// round 16
// speedup vs baseline: 2.2155x; 1.0907x over previous
#include <cuda_runtime.h>
#include <cuda_fp16.h>
#include <cstdint>

#define D_MODEL 768
#define NHEAD   12
#define SEQ     1024
#define BATCH   4
#define NTOK    (BATCH*SEQ)        /* 4096 */
#define DH      (D_MODEL*NHEAD)    /* 9216 */
#define DFF     (4*D_MODEL)        /* 3072 */
#define LN_EPS  1e-5f

typedef long long ll;

// ---------------- scratch (device globals; no allocation allowed) ----------------
__device__ __half g_Yh   [(size_t)NTOK * D_MODEL];
__device__ __half g_QKVh [(size_t)3 * NTOK * DH];   // slab0: Q' [12][4096][768]; slab1: M [12][768][768]; slab2: V
__device__ __half g_Sh   [(size_t)BATCH * NHEAD * SEQ * SEQ];   // exp(scores)
__device__ __half g_ATTh [(size_t)NTOK * DH];
__device__ __half g_H1h  [(size_t)NTOK * DFF];
__device__ float  g_X1   [(size_t)NTOK * D_MODEL];
__device__ float  g_P    [(size_t)3 * NTOK * D_MODEL];     // split-K partials / rowsum partials
__device__ float  g_RS   [(size_t)BATCH * NHEAD * SEQ];    // 1/rowsum
__device__ __half g_WqkvH[(size_t)3 * D_MODEL * DH];
__device__ __half g_WuH  [(size_t)DH * D_MODEL];
__device__ __half g_W1H  [(size_t)D_MODEL * DFF];
__device__ __half g_W2H  [(size_t)DFF * D_MODEL];

// ---------------- helpers ----------------
__device__ __forceinline__ uint32_t smem_u32(const void* p) {
    uint32_t a;
    asm("{ .reg .u64 t; cvta.to.shared.u64 t, %1; cvt.u32.u64 %0, t; }" : "=r"(a) : "l"(p));
    return a;
}
__device__ __forceinline__ void cp16(uint32_t dst, const void* src) {
    asm volatile("cp.async.cg.shared.global [%0], [%1], 16;" :: "r"(dst), "l"(src) : "memory");
}
__device__ __forceinline__ void cp_commit() {
    asm volatile("cp.async.commit_group;" ::: "memory");
}
template<int N>
__device__ __forceinline__ void cp_wait() {
    asm volatile("cp.async.wait_group %0;" :: "n"(N) : "memory");
}
__device__ __forceinline__ void ldsm_x4(uint32_t& r0, uint32_t& r1, uint32_t& r2, uint32_t& r3,
                                        uint32_t addr) {
    asm volatile("ldmatrix.sync.aligned.m8n8.x4.shared.b16 {%0,%1,%2,%3}, [%4];"
                 : "=r"(r0), "=r"(r1), "=r"(r2), "=r"(r3) : "r"(addr));
}
__device__ __forceinline__ void ldsm_x4_t(uint32_t& r0, uint32_t& r1, uint32_t& r2, uint32_t& r3,
                                          uint32_t addr) {
    asm volatile("ldmatrix.sync.aligned.m8n8.x4.trans.shared.b16 {%0,%1,%2,%3}, [%4];"
                 : "=r"(r0), "=r"(r1), "=r"(r2), "=r"(r3) : "r"(addr));
}
__device__ __forceinline__ float ex2f(float x) {
    float r;
    asm("ex2.approx.ftz.f32 %0, %1;" : "=f"(r) : "f"(x));
    return r;
}
__device__ __forceinline__ void mma_f16(float c[4],
                                        uint32_t a0, uint32_t a1, uint32_t a2, uint32_t a3,
                                        uint32_t b0, uint32_t b1) {
    asm("mma.sync.aligned.m16n8k16.row.col.f32.f16.f16.f32 "
        "{%0,%1,%2,%3}, {%4,%5,%6,%7}, {%8,%9}, {%0,%1,%2,%3};"
        : "+f"(c[0]), "+f"(c[1]), "+f"(c[2]), "+f"(c[3])
        : "r"(a0), "r"(a1), "r"(a2), "r"(a3), "r"(b0), "r"(b1));
}

// ---------------- fp16 tensor-core GEMM (R12 mainloop unchanged) -------------------
// MODE 0: plain.
// MODE 1: epilogue x = 2^(alpha*acc), emit per-slice row partial sums (deterministic).
// MODE 2: epilogue scales by 1/rowsum (deferred softmax norm), rows hoisted to regs.
template<bool BT, bool RELU, bool HASB, bool OUT_HALF, int MODE>
__global__ __launch_bounds__(128, 2)
void gemm_h(const __half* __restrict__ A, const __half* __restrict__ B,
            const float* __restrict__ bias, void* __restrict__ Cv,
            float* __restrict__ rsPtr,
            int K, int lda, int ldb, int ldc, float alpha,
            ll saO, ll saI, ll sbO, ll sbI, ll scO, ll scI, int innerCnt)
{
    constexpr int STAGES  = 3;
    constexpr int PAH     = 72;
    constexpr int PBH     = 136;
    constexpr int A_H     = 128 * PAH;
    constexpr int B_H     = BT ? 128 * PAH : 64 * PBH;
    constexpr int STAGE_H = A_H + B_H;

    extern __shared__ __half dynsm[];

    const int tid  = threadIdx.x;
    const int wid  = tid >> 5;
    const int lane = tid & 31;
    const int g    = lane >> 2;
    const int tig  = lane & 3;
    const int wm   = wid >> 1;
    const int wn   = wid & 1;

    const int mi = lane >> 3;
    const int r8 = lane & 7;
    const int aRowOff = (mi & 1) * 8 + r8;
    const int aK8     = (mi >> 1) * 8;
    const int bRowOff = (mi >> 1) * 8 + r8;
    const int bK8     = (mi & 1) * 8;
    const int cKRow   = (mi & 1) * 8 + r8;
    const int cN8     = (mi >> 1) * 8;

    const int z  = blockIdx.z;
    const int zo = z / innerCnt;
    const int zi = z - zo * innerCnt;
    A += zo * saO + zi * saI;
    B += zo * sbO + zi * sbI;
    __half* Ch = (__half*)Cv + zo * scO + zi * scI;
    float*  Cf = (float*) Cv + zo * scO + zi * scI;
    float*       rsOut = (MODE == 1) ? rsPtr + (ll)z * 16384 : nullptr;
    const float* rsIn  = (MODE == 2) ? rsPtr + (ll)z * 1024  : nullptr;

    const int m0 = blockIdx.y * 128;
    const int n0 = blockIdx.x * 128;
    A += (ll)m0 * lda;
    B += BT ? (ll)n0 * ldb : (ll)n0;

    const uint32_t smb = smem_u32(dynsm);

    auto issue = [&](int tile) {
        const int stage = tile % STAGES;
        const uint32_t sA = smb + (uint32_t)(stage * STAGE_H) * 2u;
        const uint32_t sB = sA + (uint32_t)A_H * 2u;
        const int k0 = tile * 64;
        #pragma unroll
        for (int i = 0; i < 8; i++) {
            const int v = tid + i * 128;
            const int m = v >> 3, c = (v & 7) * 8;
            cp16(sA + (uint32_t)(m * PAH + c) * 2u, A + (ll)m * lda + k0 + c);
        }
        #pragma unroll
        for (int i = 0; i < 8; i++) {
            const int v = tid + i * 128;
            if (BT) {
                const int n = v >> 3, c = (v & 7) * 8;
                cp16(sB + (uint32_t)(n * PAH + c) * 2u, B + (ll)n * ldb + k0 + c);
            } else {
                const int k = v >> 4, c = (v & 15) * 8;
                cp16(sB + (uint32_t)(k * PBH + c) * 2u, B + (ll)(k0 + k) * ldb + c);
            }
        }
        cp_commit();
    };

    float acc[4][8][4];
    #pragma unroll
    for (int mt = 0; mt < 4; mt++)
        #pragma unroll
        for (int nt = 0; nt < 8; nt++)
            #pragma unroll
            for (int rr = 0; rr < 4; rr++) acc[mt][nt][rr] = 0.f;

    const int T = K >> 6;
    issue(0); issue(1);

    for (int it = 0; it < T; ++it) {
        cp_wait<1>();
        __syncthreads();
        if (it + 2 < T) issue(it + 2);

        const uint32_t sA = smb + (uint32_t)((it % STAGES) * STAGE_H) * 2u;
        const uint32_t sB = sA + (uint32_t)A_H * 2u;

        #pragma unroll
        for (int ksi = 0; ksi < 4; ksi++) {
            uint32_t a[4][4], b[8][2];
            #pragma unroll
            for (int mt = 0; mt < 4; mt++) {
                const int m = wm * 64 + mt * 16 + aRowOff;
                ldsm_x4(a[mt][0], a[mt][1], a[mt][2], a[mt][3],
                        sA + (uint32_t)(m * PAH + ksi * 16 + aK8) * 2u);
            }
            if (BT) {
                #pragma unroll
                for (int ntp = 0; ntp < 4; ntp++) {
                    const int n = wn * 64 + ntp * 16 + bRowOff;
                    ldsm_x4(b[2*ntp][0], b[2*ntp][1], b[2*ntp+1][0], b[2*ntp+1][1],
                            sB + (uint32_t)(n * PAH + ksi * 16 + bK8) * 2u);
                }
            } else {
                #pragma unroll
                for (int ntp = 0; ntp < 4; ntp++) {
                    const int kR = ksi * 16 + cKRow;
                    const int nO = wn * 64 + ntp * 16 + cN8;
                    ldsm_x4_t(b[2*ntp][0], b[2*ntp][1], b[2*ntp+1][0], b[2*ntp+1][1],
                              sB + (uint32_t)(kR * PBH + nO) * 2u);
                }
            }
            #pragma unroll
            for (int mt = 0; mt < 4; mt++)
                #pragma unroll
                for (int nt = 0; nt < 8; nt++)
                    mma_f16(acc[mt][nt], a[mt][0], a[mt][1], a[mt][2], a[mt][3],
                            b[nt][0], b[nt][1]);
        }
    }

    // ---- epilogue ----
    float rs[4][2];
    if (MODE == 1) {
        #pragma unroll
        for (int mt = 0; mt < 4; mt++) { rs[mt][0] = 0.f; rs[mt][1] = 0.f; }
    }
    float inv[4][2];
    if (MODE == 2) {
        #pragma unroll
        for (int mt = 0; mt < 4; mt++)
            #pragma unroll
            for (int h = 0; h < 2; h++)
                inv[mt][h] = rsIn[m0 + wm * 64 + mt * 16 + g + h * 8];
    }
    #pragma unroll
    for (int mt = 0; mt < 4; mt++) {
        #pragma unroll
        for (int nt = 0; nt < 8; nt++) {
            const int n = n0 + wn * 64 + nt * 8 + tig * 2;
            float bv0 = 0.f, bv1 = 0.f;
            if (HASB) { bv0 = bias[n]; bv1 = bias[n + 1]; }
            #pragma unroll
            for (int h = 0; h < 2; h++) {
                const int m = m0 + wm * 64 + mt * 16 + g + h * 8;
                float x0 = alpha * acc[mt][nt][h * 2 + 0] + bv0;
                float x1 = alpha * acc[mt][nt][h * 2 + 1] + bv1;
                if (MODE == 1) {
                    x0 = ex2f(x0); x1 = ex2f(x1);
                    rs[mt][h] += x0 + x1;
                }
                if (MODE == 2) {
                    x0 *= inv[mt][h]; x1 *= inv[mt][h];
                }
                if (RELU) { x0 = fmaxf(x0, 0.f); x1 = fmaxf(x1, 0.f); }
                if (OUT_HALF) {
                    __half2 w = __floats2half2_rn(x0, x1);
                    *reinterpret_cast<__half2*>(Ch + (ll)m * ldc + n) = w;
                } else {
                    float2 w; w.x = x0; w.y = x1;
                    *reinterpret_cast<float2*>(Cf + (ll)m * ldc + n) = w;
                }
            }
        }
    }
    if (MODE == 1) {
        const int slot = blockIdx.x * 2 + wn;
        #pragma unroll
        for (int mt = 0; mt < 4; mt++)
            #pragma unroll
            for (int h = 0; h < 2; h++) {
                float v = rs[mt][h];
                v += __shfl_xor_sync(0xffffffffu, v, 1);
                v += __shfl_xor_sync(0xffffffffu, v, 2);
                if (tig == 0) {
                    const int m = m0 + wm * 64 + mt * 16 + g + h * 8;
                    rsOut[slot * 1024 + m] = v;
                }
            }
    }
}

// ---------------- reduce 16 row partials -> 1/rowsum ----------------
__global__ void rowsum_inv_kernel(const float* __restrict__ pr, float* __restrict__ inv,
                                  int nrows)
{
    const int t = blockIdx.x * blockDim.x + threadIdx.x;
    if (t >= nrows) return;
    const int z = t >> 10, m = t & 1023;
    const float* p = pr + (ll)z * 16384 + m;
    float s = 0.f;
    #pragma unroll
    for (int nb = 0; nb < 16; nb++) s += p[nb * 1024];
    inv[t] = 1.f / s;
}

// ---------------- fused fp32 -> fp16 conversion: 6 weight segments, one launch ------
__global__ void h_convert_all(const float4* s0, const float4* s1, const float4* s2,
                              const float4* s3, const float4* s4, const float4* s5,
                              uint2* d0, uint2* d1, uint2* d2,
                              uint2* d3, uint2* d4, uint2* d5,
                              int nbig, int nsmall)
{
    const int seg = blockIdx.y;
    const float4* src; uint2* dst; int n4;
    switch (seg) {
        case 0: src = s0; dst = d0; n4 = nbig;   break;
        case 1: src = s1; dst = d1; n4 = nbig;   break;
        case 2: src = s2; dst = d2; n4 = nbig;   break;
        case 3: src = s3; dst = d3; n4 = nbig;   break;
        case 4: src = s4; dst = d4; n4 = nsmall; break;
        default: src = s5; dst = d5; n4 = nsmall; break;
    }
    const int i = blockIdx.x * blockDim.x + threadIdx.x;
    if (i >= n4) return;
    const float4 v = src[i];
    __half2 lo = __floats2half2_rn(v.x, v.y);
    __half2 hi = __floats2half2_rn(v.z, v.w);
    uint2 o;
    o.x = *reinterpret_cast<uint32_t*>(&lo);
    o.y = *reinterpret_cast<uint32_t*>(&hi);
    dst[i] = o;
}

// ---------------- final split-K combine: out = P0 + P1 + P2 + bias + res ------------
__global__ void combine3_kernel(const float4* __restrict__ P0, const float4* __restrict__ P1,
                                const float4* __restrict__ P2,
                                const float* __restrict__ bias, const float4* __restrict__ res,
                                float4* __restrict__ out, int n4)
{
    const int i = blockIdx.x * blockDim.x + threadIdx.x;
    if (i >= n4) return;
    const int c = (i % (D_MODEL / 4)) * 4;
    const float4 p = P0[i], q = P1[i], s = P2[i], r = res[i];
    float4 o;
    o.x = p.x + q.x + s.x + bias[c + 0] + r.x;
    o.y = p.y + q.y + s.y + bias[c + 1] + r.y;
    o.z = p.z + q.z + s.z + bias[c + 2] + r.z;
    o.w = p.w + q.w + s.w + bias[c + 3] + r.w;
    out[i] = o;
}

// ---------------- fused split-K combine + LN2: one block per row --------------------
__global__ void combine_ln_kernel(const float4* __restrict__ P0, const float4* __restrict__ P1,
                                  const float4* __restrict__ P2,
                                  const float* __restrict__ bias, const float4* __restrict__ res,
                                  float4* __restrict__ X1out,
                                  const float4* __restrict__ gm, const float4* __restrict__ bt,
                                  uint2* __restrict__ y)
{
    const ll base = (ll)blockIdx.x * (D_MODEL / 4);
    const int t = threadIdx.x;                    // 0..191
    const ll i = base + t;

    const float4 p = P0[i], q = P1[i], s2 = P2[i], r = res[i];
    const float4 b4 = reinterpret_cast<const float4*>(bias)[t];
    float4 v;
    v.x = p.x + q.x + s2.x + b4.x + r.x;
    v.y = p.y + q.y + s2.y + b4.y + r.y;
    v.z = p.z + q.z + s2.z + b4.z + r.z;
    v.w = p.w + q.w + s2.w + b4.w + r.w;
    X1out[i] = v;

    float lsum = v.x + v.y + v.z + v.w;
    float lsq  = v.x * v.x + v.y * v.y + v.z * v.z + v.w * v.w;

    __shared__ float sh[12];
    #pragma unroll
    for (int o = 16; o; o >>= 1) {
        lsum += __shfl_xor_sync(0xffffffffu, lsum, o);
        lsq  += __shfl_xor_sync(0xffffffffu, lsq,  o);
    }
    const int wid = t >> 5, lane = t & 31;
    if (lane == 0) { sh[wid] = lsum; sh[6 + wid] = lsq; }
    __syncthreads();
    if (wid == 0) {
        float a = (lane < 6) ? sh[lane] : 0.f;
        float b = (lane < 6) ? sh[6 + lane] : 0.f;
        #pragma unroll
        for (int o = 4; o; o >>= 1) {
            a += __shfl_xor_sync(0xffffffffu, a, o);
            b += __shfl_xor_sync(0xffffffffu, b, o);
        }
        if (lane == 0) { sh[0] = a; sh[1] = b; }
    }
    __syncthreads();
    const float mu   = sh[0] * (1.f / D_MODEL);
    const float var  = sh[1] * (1.f / D_MODEL) - mu * mu;
    const float rstd = rsqrtf(var + LN_EPS);

    const float4 gv = gm[t];
    const float4 bv = bt[t];
    __half2 lo = __floats2half2_rn((v.x - mu) * rstd * gv.x + bv.x,
                                   (v.y - mu) * rstd * gv.y + bv.y);
    __half2 hi = __floats2half2_rn((v.z - mu) * rstd * gv.z + bv.z,
                                   (v.w - mu) * rstd * gv.w + bv.w);
    uint2 o;
    o.x = *reinterpret_cast<uint32_t*>(&lo);
    o.y = *reinterpret_cast<uint32_t*>(&hi);
    y[i] = o;
}

// ---------------- layernorm (LN1): fp32 in, fp16 out -------------------------------
__global__ void layernorm_kernel(const float4* __restrict__ x,
                                 const float4* __restrict__ gm,
                                 const float4* __restrict__ bt,
                                 uint2* __restrict__ y)
{
    const ll base = (ll)blockIdx.x * (D_MODEL / 4);
    const int t = threadIdx.x;
    const float4 v = x[base + t];
    float lsum = v.x + v.y + v.z + v.w;
    float lsq  = v.x * v.x + v.y * v.y + v.z * v.z + v.w * v.w;

    __shared__ float sh[12];
    #pragma unroll
    for (int o = 16; o; o >>= 1) {
        lsum += __shfl_xor_sync(0xffffffffu, lsum, o);
        lsq  += __shfl_xor_sync(0xffffffffu, lsq,  o);
    }
    const int wid = t >> 5, lane = t & 31;
    if (lane == 0) { sh[wid] = lsum; sh[6 + wid] = lsq; }
    __syncthreads();
    if (wid == 0) {
        float a = (lane < 6) ? sh[lane] : 0.f;
        float b = (lane < 6) ? sh[6 + lane] : 0.f;
        #pragma unroll
        for (int o = 4; o; o >>= 1) {
            a += __shfl_xor_sync(0xffffffffu, a, o);
            b += __shfl_xor_sync(0xffffffffu, b, o);
        }
        if (lane == 0) { sh[0] = a; sh[1] = b; }
    }
    __syncthreads();
    const float mu   = sh[0] * (1.f / D_MODEL);
    const float var  = sh[1] * (1.f / D_MODEL) - mu * mu;
    const float rstd = rsqrtf(var + LN_EPS);

    const float4 gv = gm[t];
    const float4 bv = bt[t];
    __half2 lo = __floats2half2_rn((v.x - mu) * rstd * gv.x + bv.x,
                                   (v.y - mu) * rstd * gv.y + bv.y);
    __half2 hi = __floats2half2_rn((v.z - mu) * rstd * gv.z + bv.z,
                                   (v.w - mu) * rstd * gv.w + bv.w);
    uint2 o;
    o.x = *reinterpret_cast<uint32_t*>(&lo);
    o.y = *reinterpret_cast<uint32_t*>(&hi);
    y[base + t] = o;
}

// ---------------- launch ----------------
#define SMEM_NN 107520
#define SMEM_NT 110592

extern "C" void kernel_launch(void* const* d_in, const int* in_sizes, int n_in,
                              void* d_out, int out_size)
{
    const float* x    = (const float*)d_in[0];
    const float* Wq   = (const float*)d_in[1];
    const float* Wk   = (const float*)d_in[2];
    const float* Wv   = (const float*)d_in[3];
    const float* Wu   = (const float*)d_in[4];
    const float* bu   = (const float*)d_in[5];
    const float* ln1g = (const float*)d_in[6];
    const float* ln1b = (const float*)d_in[7];
    const float* ln2g = (const float*)d_in[8];
    const float* ln2b = (const float*)d_in[9];
    const float* W1   = (const float*)d_in[10];
    const float* b1   = (const float*)d_in[11];
    const float* W2   = (const float*)d_in[12];
    const float* b2   = (const float*)d_in[13];
    float* out = (float*)d_out;

    __half *Y, *QKV, *S, *ATT, *H1, *Wqkv, *WuH, *W1H, *W2H;
    float *X1, *P, *RS;
    cudaGetSymbolAddress((void**)&Y,    g_Yh);
    cudaGetSymbolAddress((void**)&QKV,  g_QKVh);
    cudaGetSymbolAddress((void**)&S,    g_Sh);
    cudaGetSymbolAddress((void**)&ATT,  g_ATTh);
    cudaGetSymbolAddress((void**)&H1,   g_H1h);
    cudaGetSymbolAddress((void**)&X1,   g_X1);
    cudaGetSymbolAddress((void**)&P,    g_P);
    cudaGetSymbolAddress((void**)&RS,   g_RS);
    cudaGetSymbolAddress((void**)&Wqkv, g_WqkvH);
    cudaGetSymbolAddress((void**)&WuH,  g_WuH);
    cudaGetSymbolAddress((void**)&W1H,  g_W1H);
    cudaGetSymbolAddress((void**)&W2H,  g_W2H);

    __half* QP = QKV;                                   // Q' [12][4096][768]
    __half* MH = QKV + (size_t)NTOK * DH;               // M  [12][768][768]
    __half* V  = QKV + (size_t)2 * NTOK * DH;           // V  [4096][9216]
    __half* WqH = Wqkv;
    __half* WkH = Wqkv + (size_t)D_MODEL * DH;
    __half* WvH = Wqkv + (size_t)2 * D_MODEL * DH;

    float* P0 = P;
    float* P1 = P + (size_t)NTOK * D_MODEL;
    float* P2 = P + (size_t)2 * NTOK * D_MODEL;

    cudaFuncSetAttribute(gemm_h<false,false,false,true ,0>, cudaFuncAttributeMaxDynamicSharedMemorySize, SMEM_NN);
    cudaFuncSetAttribute(gemm_h<true ,false,false,true ,0>, cudaFuncAttributeMaxDynamicSharedMemorySize, SMEM_NT);
    cudaFuncSetAttribute(gemm_h<true ,false,false,true ,1>, cudaFuncAttributeMaxDynamicSharedMemorySize, SMEM_NT);
    cudaFuncSetAttribute(gemm_h<false,false,false,true ,2>, cudaFuncAttributeMaxDynamicSharedMemorySize, SMEM_NN);
    cudaFuncSetAttribute(gemm_h<false,true ,true ,true ,0>, cudaFuncAttributeMaxDynamicSharedMemorySize, SMEM_NN);
    cudaFuncSetAttribute(gemm_h<false,false,false,false,0>, cudaFuncAttributeMaxDynamicSharedMemorySize, SMEM_NN);

    // alpha for MODE 1 carries both 1/sqrt(768) and log2(e)
    const float alpha_exp2 = 0.03608439182435161f * 1.4426950408889634f;

    // 0) weight conversions (one launch) + LN1
    {
        const int nbig = D_MODEL * DH / 4, nsmall = D_MODEL * DFF / 4;
        dim3 grid((nbig + 255) / 256, 6, 1);
        h_convert_all<<<grid, 256>>>(
            (const float4*)Wq, (const float4*)Wk, (const float4*)Wv,
            (const float4*)Wu, (const float4*)W1, (const float4*)W2,
            (uint2*)WqH, (uint2*)WkH, (uint2*)WvH,
            (uint2*)WuH, (uint2*)W1H, (uint2*)W2H,
            nbig, nsmall);
    }
    layernorm_kernel<<<NTOK, 192>>>((const float4*)x, (const float4*)ln1g,
                                    (const float4*)ln1b, (uint2*)Y);

    // 1a) M_h = Wq_h @ Wk_h^T  (768x768x768, batch 12; NT)
    {
        dim3 grid(D_MODEL / 128, D_MODEL / 128, NHEAD);
        gemm_h<true,false,false,true,0><<<grid, 128, SMEM_NT>>>(WqH, WkH, nullptr, MH, nullptr,
            D_MODEL, DH, DH, D_MODEL, 1.f,
            0, (ll)D_MODEL,                    // A: h-column slab of Wq
            0, (ll)D_MODEL,                    // B: h-column slab of Wk
            0, (ll)D_MODEL * D_MODEL,          // C: M_h slab
            NHEAD);
    }

    // 1b) V = Y @ Wv  (M=4096, N=9216, K=768; NN)
    {
        dim3 grid(DH / 128, NTOK / 128, 1);
        gemm_h<false,false,false,true,0><<<grid, 128, SMEM_NN>>>(Y, WvH, nullptr, V, nullptr,
            D_MODEL, D_MODEL, DH, DH, 1.f, 0,0,0,0,0,0, 1);
    }

    // 1c) Q'_h = Y @ M_h  (M=4096, N=768, K=768, z=h; NN)  -> QP[h][tok][768]
    {
        dim3 grid(D_MODEL / 128, NTOK / 128, NHEAD);
        gemm_h<false,false,false,true,0><<<grid, 128, SMEM_NN>>>(Y, MH, nullptr, QP, nullptr,
            D_MODEL, D_MODEL, D_MODEL, D_MODEL, 1.f,
            0, 0,
            0, (ll)D_MODEL * D_MODEL,
            0, (ll)NTOK * D_MODEL,
            NHEAD);
    }

    // 2) expS[b,h] = 2^(alpha * Q'_bh @ Y_b^T) + row partial sums (MODE 1; NT)
    {
        dim3 grid(SEQ / 128, SEQ / 128, BATCH * NHEAD);
        gemm_h<true,false,false,true,1><<<grid, 128, SMEM_NT>>>(QP, Y, nullptr, S, P,
            D_MODEL, D_MODEL, D_MODEL, SEQ, alpha_exp2,
            (ll)SEQ * D_MODEL, (ll)NTOK * D_MODEL,   // A(Q'): b-slab, h-slab
            (ll)SEQ * D_MODEL, 0,                    // B(Y): b-slab only
            (ll)NHEAD * SEQ * SEQ, (ll)SEQ * SEQ,
            NHEAD);
    }

    // 3) 1/rowsum from 16 partials per row
    {
        const int nrows = BATCH * NHEAD * SEQ;
        rowsum_inv_kernel<<<(nrows + 255) / 256, 256>>>(P, RS, nrows);
    }

    // 4) ATT = (expS @ V) * (1/rowsum)  (MODE 2)
    {
        dim3 grid(D_MODEL / 128, SEQ / 128, BATCH * NHEAD);
        gemm_h<false,false,false,true,2><<<grid, 128, SMEM_NN>>>(S, V, nullptr, ATT, RS,
            SEQ, SEQ, DH, DH, 1.f,
            (ll)NHEAD * SEQ * SEQ, (ll)SEQ * SEQ,
            (ll)SEQ * DH, (ll)D_MODEL,
            (ll)SEQ * DH, (ll)D_MODEL,
            NHEAD);
    }

    // 5) Wu split-K=3 (overwrites g_P), then fused combine+LN2
    {
        dim3 grid(D_MODEL / 128, NTOK / 128, 3);
        gemm_h<false,false,false,false,0><<<grid, 128, SMEM_NN>>>(ATT, WuH, nullptr, P0, nullptr,
            DH / 3, DH, D_MODEL, D_MODEL, 1.f,
            0, (ll)(DH / 3),
            0, (ll)(DH / 3) * D_MODEL,
            0, (ll)NTOK * D_MODEL,
            3);
        combine_ln_kernel<<<NTOK, 192>>>((const float4*)P0, (const float4*)P1,
                                         (const float4*)P2, bu, (const float4*)x,
                                         (float4*)X1,
                                         (const float4*)ln2g, (const float4*)ln2b,
                                         (uint2*)Y);
    }

    // 6) H1 = relu(Y @ W1 + b1)
    {
        dim3 grid(DFF / 128, NTOK / 128, 1);
        gemm_h<false,true,true,true,0><<<grid, 128, SMEM_NN>>>(Y, W1H, b1, H1, nullptr,
            D_MODEL, D_MODEL, DFF, DFF, 1.f, 0,0,0,0,0,0, 1);
    }

    // 7) W2 split-K=3, then out = P0+P1+P2 + b2 + X1
    {
        dim3 grid(D_MODEL / 128, NTOK / 128, 3);
        gemm_h<false,false,false,false,0><<<grid, 128, SMEM_NN>>>(H1, W2H, nullptr, P0, nullptr,
            DFF / 3, DFF, D_MODEL, D_MODEL, 1.f,
            0, (ll)(DFF / 3),
            0, (ll)(DFF / 3) * D_MODEL,
            0, (ll)NTOK * D_MODEL,
            3);
        const int n4 = NTOK * D_MODEL / 4;
        combine3_kernel<<<(n4 + 255) / 256, 256>>>((const float4*)P0, (const float4*)P1,
                                                   (const float4*)P2, b2,
                                                   (const float4*)X1, (float4*)out, n4);
    }

    (void)in_sizes; (void)n_in; (void)out_size;
}

// round 17
// speedup vs baseline: 2.4216x; 1.0930x over previous
#include <cuda_runtime.h>
#include <cuda_fp16.h>
#include <cstdint>

#define D_MODEL 768
#define NHEAD   12
#define SEQ     1024
#define BATCH   4
#define NTOK    (BATCH*SEQ)        /* 4096 */
#define DH      (D_MODEL*NHEAD)    /* 9216 */
#define DFF     (4*D_MODEL)        /* 3072 */
#define LN_EPS  1e-5f

typedef long long ll;

// ---------------- scratch (device globals; no allocation allowed) ----------------
__device__ __half g_Yh   [(size_t)NTOK * D_MODEL];
// slab0: Q' [12][4096][768]; slab1: M [12][768][768] then N [12][768][768]; slab2: V'' [4][12][1024][768]
__device__ __half g_QKVh [(size_t)3 * NTOK * DH];
__device__ __half g_Sh   [(size_t)BATCH * SEQ * (NHEAD * SEQ)];  // [b][m][h*1024+n]
__device__ __half g_H1h  [(size_t)NTOK * DFF];
__device__ float  g_X1   [(size_t)NTOK * D_MODEL];
__device__ float  g_P    [(size_t)3 * NTOK * D_MODEL];     // rowsum partials / split-K partials
__device__ float  g_RS   [(size_t)BATCH * NHEAD * SEQ];    // 1/rowsum
__device__ __half g_WqkvH[(size_t)3 * D_MODEL * DH];
__device__ __half g_WuH  [(size_t)DH * D_MODEL];
__device__ __half g_W1H  [(size_t)D_MODEL * DFF];
__device__ __half g_W2H  [(size_t)DFF * D_MODEL];

// ---------------- helpers ----------------
__device__ __forceinline__ uint32_t smem_u32(const void* p) {
    uint32_t a;
    asm("{ .reg .u64 t; cvta.to.shared.u64 t, %1; cvt.u32.u64 %0, t; }" : "=r"(a) : "l"(p));
    return a;
}
__device__ __forceinline__ void cp16(uint32_t dst, const void* src) {
    asm volatile("cp.async.cg.shared.global [%0], [%1], 16;" :: "r"(dst), "l"(src) : "memory");
}
__device__ __forceinline__ void cp_commit() {
    asm volatile("cp.async.commit_group;" ::: "memory");
}
template<int N>
__device__ __forceinline__ void cp_wait() {
    asm volatile("cp.async.wait_group %0;" :: "n"(N) : "memory");
}
__device__ __forceinline__ void ldsm_x4(uint32_t& r0, uint32_t& r1, uint32_t& r2, uint32_t& r3,
                                        uint32_t addr) {
    asm volatile("ldmatrix.sync.aligned.m8n8.x4.shared.b16 {%0,%1,%2,%3}, [%4];"
                 : "=r"(r0), "=r"(r1), "=r"(r2), "=r"(r3) : "r"(addr));
}
__device__ __forceinline__ void ldsm_x4_t(uint32_t& r0, uint32_t& r1, uint32_t& r2, uint32_t& r3,
                                          uint32_t addr) {
    asm volatile("ldmatrix.sync.aligned.m8n8.x4.trans.shared.b16 {%0,%1,%2,%3}, [%4];"
                 : "=r"(r0), "=r"(r1), "=r"(r2), "=r"(r3) : "r"(addr));
}
__device__ __forceinline__ float ex2f(float x) {
    float r;
    asm("ex2.approx.ftz.f32 %0, %1;" : "=f"(r) : "f"(x));
    return r;
}
__device__ __forceinline__ void mma_f16(float c[4],
                                        uint32_t a0, uint32_t a1, uint32_t a2, uint32_t a3,
                                        uint32_t b0, uint32_t b1) {
    asm("mma.sync.aligned.m16n8k16.row.col.f32.f16.f16.f32 "
        "{%0,%1,%2,%3}, {%4,%5,%6,%7}, {%8,%9}, {%0,%1,%2,%3};"
        : "+f"(c[0]), "+f"(c[1]), "+f"(c[2]), "+f"(c[3])
        : "r"(a0), "r"(a1), "r"(a2), "r"(a3), "r"(b0), "r"(b1));
}

// ---------------- fp16 tensor-core GEMM (R12 mainloop unchanged) -------------------
// MODE 0: plain.
// MODE 1: epilogue x = 2^(alpha*acc), emit per-slice row partial sums (deterministic).
template<bool BT, bool RELU, bool HASB, bool OUT_HALF, int MODE>
__global__ __launch_bounds__(128, 2)
void gemm_h(const __half* __restrict__ A, const __half* __restrict__ B,
            const float* __restrict__ bias, void* __restrict__ Cv,
            float* __restrict__ rsPtr,
            int K, int lda, int ldb, int ldc, float alpha,
            ll saO, ll saI, ll sbO, ll sbI, ll scO, ll scI, int innerCnt)
{
    constexpr int STAGES  = 3;
    constexpr int PAH     = 72;
    constexpr int PBH     = 136;
    constexpr int A_H     = 128 * PAH;
    constexpr int B_H     = BT ? 128 * PAH : 64 * PBH;
    constexpr int STAGE_H = A_H + B_H;

    extern __shared__ __half dynsm[];

    const int tid  = threadIdx.x;
    const int wid  = tid >> 5;
    const int lane = tid & 31;
    const int g    = lane >> 2;
    const int tig  = lane & 3;
    const int wm   = wid >> 1;
    const int wn   = wid & 1;

    const int mi = lane >> 3;
    const int r8 = lane & 7;
    const int aRowOff = (mi & 1) * 8 + r8;
    const int aK8     = (mi >> 1) * 8;
    const int bRowOff = (mi >> 1) * 8 + r8;
    const int bK8     = (mi & 1) * 8;
    const int cKRow   = (mi & 1) * 8 + r8;
    const int cN8     = (mi >> 1) * 8;

    const int z  = blockIdx.z;
    const int zo = z / innerCnt;
    const int zi = z - zo * innerCnt;
    A += zo * saO + zi * saI;
    B += zo * sbO + zi * sbI;
    __half* Ch = (__half*)Cv + zo * scO + zi * scI;
    float*  Cf = (float*) Cv + zo * scO + zi * scI;
    float* rsOut = (MODE == 1) ? rsPtr + (ll)z * 16384 : nullptr;

    const int m0 = blockIdx.y * 128;
    const int n0 = blockIdx.x * 128;
    A += (ll)m0 * lda;
    B += BT ? (ll)n0 * ldb : (ll)n0;

    const uint32_t smb = smem_u32(dynsm);

    auto issue = [&](int tile) {
        const int stage = tile % STAGES;
        const uint32_t sA = smb + (uint32_t)(stage * STAGE_H) * 2u;
        const uint32_t sB = sA + (uint32_t)A_H * 2u;
        const int k0 = tile * 64;
        #pragma unroll
        for (int i = 0; i < 8; i++) {
            const int v = tid + i * 128;
            const int m = v >> 3, c = (v & 7) * 8;
            cp16(sA + (uint32_t)(m * PAH + c) * 2u, A + (ll)m * lda + k0 + c);
        }
        #pragma unroll
        for (int i = 0; i < 8; i++) {
            const int v = tid + i * 128;
            if (BT) {
                const int n = v >> 3, c = (v & 7) * 8;
                cp16(sB + (uint32_t)(n * PAH + c) * 2u, B + (ll)n * ldb + k0 + c);
            } else {
                const int k = v >> 4, c = (v & 15) * 8;
                cp16(sB + (uint32_t)(k * PBH + c) * 2u, B + (ll)(k0 + k) * ldb + c);
            }
        }
        cp_commit();
    };

    float acc[4][8][4];
    #pragma unroll
    for (int mt = 0; mt < 4; mt++)
        #pragma unroll
        for (int nt = 0; nt < 8; nt++)
            #pragma unroll
            for (int rr = 0; rr < 4; rr++) acc[mt][nt][rr] = 0.f;

    const int T = K >> 6;
    issue(0); issue(1);

    for (int it = 0; it < T; ++it) {
        cp_wait<1>();
        __syncthreads();
        if (it + 2 < T) issue(it + 2);

        const uint32_t sA = smb + (uint32_t)((it % STAGES) * STAGE_H) * 2u;
        const uint32_t sB = sA + (uint32_t)A_H * 2u;

        #pragma unroll
        for (int ksi = 0; ksi < 4; ksi++) {
            uint32_t a[4][4], b[8][2];
            #pragma unroll
            for (int mt = 0; mt < 4; mt++) {
                const int m = wm * 64 + mt * 16 + aRowOff;
                ldsm_x4(a[mt][0], a[mt][1], a[mt][2], a[mt][3],
                        sA + (uint32_t)(m * PAH + ksi * 16 + aK8) * 2u);
            }
            if (BT) {
                #pragma unroll
                for (int ntp = 0; ntp < 4; ntp++) {
                    const int n = wn * 64 + ntp * 16 + bRowOff;
                    ldsm_x4(b[2*ntp][0], b[2*ntp][1], b[2*ntp+1][0], b[2*ntp+1][1],
                            sB + (uint32_t)(n * PAH + ksi * 16 + bK8) * 2u);
                }
            } else {
                #pragma unroll
                for (int ntp = 0; ntp < 4; ntp++) {
                    const int kR = ksi * 16 + cKRow;
                    const int nO = wn * 64 + ntp * 16 + cN8;
                    ldsm_x4_t(b[2*ntp][0], b[2*ntp][1], b[2*ntp+1][0], b[2*ntp+1][1],
                              sB + (uint32_t)(kR * PBH + nO) * 2u);
                }
            }
            #pragma unroll
            for (int mt = 0; mt < 4; mt++)
                #pragma unroll
                for (int nt = 0; nt < 8; nt++)
                    mma_f16(acc[mt][nt], a[mt][0], a[mt][1], a[mt][2], a[mt][3],
                            b[nt][0], b[nt][1]);
        }
    }

    // ---- epilogue ----
    float rs[4][2];
    if (MODE == 1) {
        #pragma unroll
        for (int mt = 0; mt < 4; mt++) { rs[mt][0] = 0.f; rs[mt][1] = 0.f; }
    }
    #pragma unroll
    for (int mt = 0; mt < 4; mt++) {
        #pragma unroll
        for (int nt = 0; nt < 8; nt++) {
            const int n = n0 + wn * 64 + nt * 8 + tig * 2;
            float bv0 = 0.f, bv1 = 0.f;
            if (HASB) { bv0 = bias[n]; bv1 = bias[n + 1]; }
            #pragma unroll
            for (int h = 0; h < 2; h++) {
                const int m = m0 + wm * 64 + mt * 16 + g + h * 8;
                float x0 = alpha * acc[mt][nt][h * 2 + 0] + bv0;
                float x1 = alpha * acc[mt][nt][h * 2 + 1] + bv1;
                if (MODE == 1) {
                    x0 = ex2f(x0); x1 = ex2f(x1);
                    rs[mt][h] += x0 + x1;
                }
                if (RELU) { x0 = fmaxf(x0, 0.f); x1 = fmaxf(x1, 0.f); }
                if (OUT_HALF) {
                    __half2 w = __floats2half2_rn(x0, x1);
                    *reinterpret_cast<__half2*>(Ch + (ll)m * ldc + n) = w;
                } else {
                    float2 w; w.x = x0; w.y = x1;
                    *reinterpret_cast<float2*>(Cf + (ll)m * ldc + n) = w;
                }
            }
        }
    }
    if (MODE == 1) {
        const int slot = blockIdx.x * 2 + wn;
        #pragma unroll
        for (int mt = 0; mt < 4; mt++)
            #pragma unroll
            for (int h = 0; h < 2; h++) {
                float v = rs[mt][h];
                v += __shfl_xor_sync(0xffffffffu, v, 1);
                v += __shfl_xor_sync(0xffffffffu, v, 2);
                if (tig == 0) {
                    const int m = m0 + wm * 64 + mt * 16 + g + h * 8;
                    rsOut[slot * 1024 + m] = v;
                }
            }
    }
}

// ---------------- reduce 16 row partials -> 1/rowsum ----------------
__global__ void rowsum_inv_kernel(const float* __restrict__ pr, float* __restrict__ inv,
                                  int nrows)
{
    const int t = blockIdx.x * blockDim.x + threadIdx.x;
    if (t >= nrows) return;
    const int z = t >> 10, m = t & 1023;
    const float* p = pr + (ll)z * 16384 + m;
    float s = 0.f;
    #pragma unroll
    for (int nb = 0; nb < 16; nb++) s += p[nb * 1024];
    inv[t] = 1.f / s;
}

// ---------------- normalize S rows: S[b][m][h*1024+n] *= RS[(b*12+h)*1024+m] --------
// grid (6, 4096), 256 thr; each thread handles one uint4 (8 halves, same b,m,h).
__global__ void normalize_S_kernel(uint4* __restrict__ S, const float* __restrict__ RS)
{
    const int row  = blockIdx.y;                    // b*1024 + m
    const int col8 = blockIdx.x * 256 + threadIdx.x; // 0..1535 (uint4 within row)
    const int b = row >> 10, m = row & 1023;
    const int h = col8 >> 7;                        // 128 uint4 per head
    const float sc = RS[((b * NHEAD + h) << 10) + m];

    uint4 u = S[(ll)row * 1536 + col8];
    __half2* hp = reinterpret_cast<__half2*>(&u);
    #pragma unroll
    for (int i = 0; i < 4; i++) {
        float2 f = __half22float2(hp[i]);
        f.x *= sc; f.y *= sc;
        hp[i] = __floats2half2_rn(f.x, f.y);
    }
    S[(ll)row * 1536 + col8] = u;
}

// ---------------- fused fp32 -> fp16 conversion: 6 weight segments, one launch ------
__global__ void h_convert_all(const float4* s0, const float4* s1, const float4* s2,
                              const float4* s3, const float4* s4, const float4* s5,
                              uint2* d0, uint2* d1, uint2* d2,
                              uint2* d3, uint2* d4, uint2* d5,
                              int nbig, int nsmall)
{
    const int seg = blockIdx.y;
    const float4* src; uint2* dst; int n4;
    switch (seg) {
        case 0: src = s0; dst = d0; n4 = nbig;   break;
        case 1: src = s1; dst = d1; n4 = nbig;   break;
        case 2: src = s2; dst = d2; n4 = nbig;   break;
        case 3: src = s3; dst = d3; n4 = nbig;   break;
        case 4: src = s4; dst = d4; n4 = nsmall; break;
        default: src = s5; dst = d5; n4 = nsmall; break;
    }
    const int i = blockIdx.x * blockDim.x + threadIdx.x;
    if (i >= n4) return;
    const float4 v = src[i];
    __half2 lo = __floats2half2_rn(v.x, v.y);
    __half2 hi = __floats2half2_rn(v.z, v.w);
    uint2 o;
    o.x = *reinterpret_cast<uint32_t*>(&lo);
    o.y = *reinterpret_cast<uint32_t*>(&hi);
    dst[i] = o;
}

// ---------------- final split-K combine: out = P0 + P1 + P2 + bias + res ------------
__global__ void combine3_kernel(const float4* __restrict__ P0, const float4* __restrict__ P1,
                                const float4* __restrict__ P2,
                                const float* __restrict__ bias, const float4* __restrict__ res,
                                float4* __restrict__ out, int n4)
{
    const int i = blockIdx.x * blockDim.x + threadIdx.x;
    if (i >= n4) return;
    const int c = (i % (D_MODEL / 4)) * 4;
    const float4 p = P0[i], q = P1[i], s = P2[i], r = res[i];
    float4 o;
    o.x = p.x + q.x + s.x + bias[c + 0] + r.x;
    o.y = p.y + q.y + s.y + bias[c + 1] + r.y;
    o.z = p.z + q.z + s.z + bias[c + 2] + r.z;
    o.w = p.w + q.w + s.w + bias[c + 3] + r.w;
    out[i] = o;
}

// ---------------- fused split-K combine + LN2: one block per row --------------------
__global__ void combine_ln_kernel(const float4* __restrict__ P0, const float4* __restrict__ P1,
                                  const float4* __restrict__ P2,
                                  const float* __restrict__ bias, const float4* __restrict__ res,
                                  float4* __restrict__ X1out,
                                  const float4* __restrict__ gm, const float4* __restrict__ bt,
                                  uint2* __restrict__ y)
{
    const ll base = (ll)blockIdx.x * (D_MODEL / 4);
    const int t = threadIdx.x;                    // 0..191
    const ll i = base + t;

    const float4 p = P0[i], q = P1[i], s2 = P2[i], r = res[i];
    const float4 b4 = reinterpret_cast<const float4*>(bias)[t];
    float4 v;
    v.x = p.x + q.x + s2.x + b4.x + r.x;
    v.y = p.y + q.y + s2.y + b4.y + r.y;
    v.z = p.z + q.z + s2.z + b4.z + r.z;
    v.w = p.w + q.w + s2.w + b4.w + r.w;
    X1out[i] = v;

    float lsum = v.x + v.y + v.z + v.w;
    float lsq  = v.x * v.x + v.y * v.y + v.z * v.z + v.w * v.w;

    __shared__ float sh[12];
    #pragma unroll
    for (int o = 16; o; o >>= 1) {
        lsum += __shfl_xor_sync(0xffffffffu, lsum, o);
        lsq  += __shfl_xor_sync(0xffffffffu, lsq,  o);
    }
    const int wid = t >> 5, lane = t & 31;
    if (lane == 0) { sh[wid] = lsum; sh[6 + wid] = lsq; }
    __syncthreads();
    if (wid == 0) {
        float a = (lane < 6) ? sh[lane] : 0.f;
        float b = (lane < 6) ? sh[6 + lane] : 0.f;
        #pragma unroll
        for (int o = 4; o; o >>= 1) {
            a += __shfl_xor_sync(0xffffffffu, a, o);
            b += __shfl_xor_sync(0xffffffffu, b, o);
        }
        if (lane == 0) { sh[0] = a; sh[1] = b; }
    }
    __syncthreads();
    const float mu   = sh[0] * (1.f / D_MODEL);
    const float var  = sh[1] * (1.f / D_MODEL) - mu * mu;
    const float rstd = rsqrtf(var + LN_EPS);

    const float4 gv = gm[t];
    const float4 bv = bt[t];
    __half2 lo = __floats2half2_rn((v.x - mu) * rstd * gv.x + bv.x,
                                   (v.y - mu) * rstd * gv.y + bv.y);
    __half2 hi = __floats2half2_rn((v.z - mu) * rstd * gv.z + bv.z,
                                   (v.w - mu) * rstd * gv.w + bv.w);
    uint2 o;
    o.x = *reinterpret_cast<uint32_t*>(&lo);
    o.y = *reinterpret_cast<uint32_t*>(&hi);
    y[i] = o;
}

// ---------------- layernorm (LN1): fp32 in, fp16 out -------------------------------
__global__ void layernorm_kernel(const float4* __restrict__ x,
                                 const float4* __restrict__ gm,
                                 const float4* __restrict__ bt,
                                 uint2* __restrict__ y)
{
    const ll base = (ll)blockIdx.x * (D_MODEL / 4);
    const int t = threadIdx.x;
    const float4 v = x[base + t];
    float lsum = v.x + v.y + v.z + v.w;
    float lsq  = v.x * v.x + v.y * v.y + v.z * v.z + v.w * v.w;

    __shared__ float sh[12];
    #pragma unroll
    for (int o = 16; o; o >>= 1) {
        lsum += __shfl_xor_sync(0xffffffffu, lsum, o);
        lsq  += __shfl_xor_sync(0xffffffffu, lsq,  o);
    }
    const int wid = t >> 5, lane = t & 31;
    if (lane == 0) { sh[wid] = lsum; sh[6 + wid] = lsq; }
    __syncthreads();
    if (wid == 0) {
        float a = (lane < 6) ? sh[lane] : 0.f;
        float b = (lane < 6) ? sh[6 + lane] : 0.f;
        #pragma unroll
        for (int o = 4; o; o >>= 1) {
            a += __shfl_xor_sync(0xffffffffu, a, o);
            b += __shfl_xor_sync(0xffffffffu, b, o);
        }
        if (lane == 0) { sh[0] = a; sh[1] = b; }
    }
    __syncthreads();
    const float mu   = sh[0] * (1.f / D_MODEL);
    const float var  = sh[1] * (1.f / D_MODEL) - mu * mu;
    const float rstd = rsqrtf(var + LN_EPS);

    const float4 gv = gm[t];
    const float4 bv = bt[t];
    __half2 lo = __floats2half2_rn((v.x - mu) * rstd * gv.x + bv.x,
                                   (v.y - mu) * rstd * gv.y + bv.y);
    __half2 hi = __floats2half2_rn((v.z - mu) * rstd * gv.z + bv.z,
                                   (v.w - mu) * rstd * gv.w + bv.w);
    uint2 o;
    o.x = *reinterpret_cast<uint32_t*>(&lo);
    o.y = *reinterpret_cast<uint32_t*>(&hi);
    y[base + t] = o;
}

// ---------------- launch ----------------
#define SMEM_NN 107520
#define SMEM_NT 110592

extern "C" void kernel_launch(void* const* d_in, const int* in_sizes, int n_in,
                              void* d_out, int out_size)
{
    const float* x    = (const float*)d_in[0];
    const float* Wq   = (const float*)d_in[1];
    const float* Wk   = (const float*)d_in[2];
    const float* Wv   = (const float*)d_in[3];
    const float* Wu   = (const float*)d_in[4];
    const float* bu   = (const float*)d_in[5];
    const float* ln1g = (const float*)d_in[6];
    const float* ln1b = (const float*)d_in[7];
    const float* ln2g = (const float*)d_in[8];
    const float* ln2b = (const float*)d_in[9];
    const float* W1   = (const float*)d_in[10];
    const float* b1   = (const float*)d_in[11];
    const float* W2   = (const float*)d_in[12];
    const float* b2   = (const float*)d_in[13];
    float* out = (float*)d_out;

    __half *Y, *QKV, *S, *H1, *Wqkv, *WuH, *W1H, *W2H;
    float *X1, *P, *RS;
    cudaGetSymbolAddress((void**)&Y,    g_Yh);
    cudaGetSymbolAddress((void**)&QKV,  g_QKVh);
    cudaGetSymbolAddress((void**)&S,    g_Sh);
    cudaGetSymbolAddress((void**)&H1,   g_H1h);
    cudaGetSymbolAddress((void**)&X1,   g_X1);
    cudaGetSymbolAddress((void**)&P,    g_P);
    cudaGetSymbolAddress((void**)&RS,   g_RS);
    cudaGetSymbolAddress((void**)&Wqkv, g_WqkvH);
    cudaGetSymbolAddress((void**)&WuH,  g_WuH);
    cudaGetSymbolAddress((void**)&W1H,  g_W1H);
    cudaGetSymbolAddress((void**)&W2H,  g_W2H);

    __half* QP = QKV;                                   // Q'  [12][4096][768]
    __half* MH = QKV + (size_t)NTOK * DH;               // M   [12][768][768]
    __half* NH = MH + (size_t)NHEAD * D_MODEL * D_MODEL;// N   [12][768][768]
    __half* VP = QKV + (size_t)2 * NTOK * DH;           // V'' [4][12][1024][768]
    __half* WqH = Wqkv;
    __half* WkH = Wqkv + (size_t)D_MODEL * DH;
    __half* WvH = Wqkv + (size_t)2 * D_MODEL * DH;

    float* P0 = P;
    float* P1 = P + (size_t)NTOK * D_MODEL;
    float* P2 = P + (size_t)2 * NTOK * D_MODEL;

    cudaFuncSetAttribute(gemm_h<false,false,false,true ,0>, cudaFuncAttributeMaxDynamicSharedMemorySize, SMEM_NN);
    cudaFuncSetAttribute(gemm_h<true ,false,false,true ,0>, cudaFuncAttributeMaxDynamicSharedMemorySize, SMEM_NT);
    cudaFuncSetAttribute(gemm_h<true ,false,false,true ,1>, cudaFuncAttributeMaxDynamicSharedMemorySize, SMEM_NT);
    cudaFuncSetAttribute(gemm_h<false,true ,true ,true ,0>, cudaFuncAttributeMaxDynamicSharedMemorySize, SMEM_NN);
    cudaFuncSetAttribute(gemm_h<false,false,false,false,0>, cudaFuncAttributeMaxDynamicSharedMemorySize, SMEM_NN);

    // MODE-1 alpha carries 1/sqrt(768) * log2(e)
    const float alpha_exp2 = 0.03608439182435161f * 1.4426950408889634f;

    // 0) weight conversions (one launch) + LN1
    {
        const int nbig = D_MODEL * DH / 4, nsmall = D_MODEL * DFF / 4;
        dim3 grid((nbig + 255) / 256, 6, 1);
        h_convert_all<<<grid, 256>>>(
            (const float4*)Wq, (const float4*)Wk, (const float4*)Wv,
            (const float4*)Wu, (const float4*)W1, (const float4*)W2,
            (uint2*)WqH, (uint2*)WkH, (uint2*)WvH,
            (uint2*)WuH, (uint2*)W1H, (uint2*)W2H,
            nbig, nsmall);
    }
    layernorm_kernel<<<NTOK, 192>>>((const float4*)x, (const float4*)ln1g,
                                    (const float4*)ln1b, (uint2*)Y);

    // 1a) M_h = Wq_h @ Wk_h^T  (768^3, z=12; NT)
    {
        dim3 grid(D_MODEL / 128, D_MODEL / 128, NHEAD);
        gemm_h<true,false,false,true,0><<<grid, 128, SMEM_NT>>>(WqH, WkH, nullptr, MH, nullptr,
            D_MODEL, DH, DH, D_MODEL, 1.f,
            0, (ll)D_MODEL,
            0, (ll)D_MODEL,
            0, (ll)D_MODEL * D_MODEL,
            NHEAD);
    }
    // 1b) N_h = Wv_h @ Wu_h  (768^3, z=12; NN)
    {
        dim3 grid(D_MODEL / 128, D_MODEL / 128, NHEAD);
        gemm_h<false,false,false,true,0><<<grid, 128, SMEM_NN>>>(WvH, WuH, nullptr, NH, nullptr,
            D_MODEL, DH, D_MODEL, D_MODEL, 1.f,
            0, (ll)D_MODEL,                       // A: h-column slab of Wv
            0, (ll)D_MODEL * D_MODEL,             // B: h-row slab of Wu
            0, (ll)D_MODEL * D_MODEL,             // C: N_h slab
            NHEAD);
    }

    // 1c) Q'_h = Y @ M_h  (M=4096, z=h; NN) -> QP[h][tok][768]
    {
        dim3 grid(D_MODEL / 128, NTOK / 128, NHEAD);
        gemm_h<false,false,false,true,0><<<grid, 128, SMEM_NN>>>(Y, MH, nullptr, QP, nullptr,
            D_MODEL, D_MODEL, D_MODEL, D_MODEL, 1.f,
            0, 0,
            0, (ll)D_MODEL * D_MODEL,
            0, (ll)NTOK * D_MODEL,
            NHEAD);
    }

    // 1d) V''_bh = Y_b @ N_h  (M=1024, z=b*12+h; NN) -> VP[b][h][t][768]
    {
        dim3 grid(D_MODEL / 128, SEQ / 128, BATCH * NHEAD);
        gemm_h<false,false,false,true,0><<<grid, 128, SMEM_NN>>>(Y, NH, nullptr, VP, nullptr,
            D_MODEL, D_MODEL, D_MODEL, D_MODEL, 1.f,
            (ll)SEQ * D_MODEL, 0,                 // A: b-slab of Y
            0, (ll)D_MODEL * D_MODEL,             // B: N_h
            (ll)NHEAD * SEQ * D_MODEL, (ll)SEQ * D_MODEL,  // C: [b][h] slab
            NHEAD);
    }

    // 2) expS: S[b][m][h*1024+n] = 2^(alpha * Q'_bh @ Y_b^T) + row partials (MODE 1; NT)
    {
        dim3 grid(SEQ / 128, SEQ / 128, BATCH * NHEAD);
        gemm_h<true,false,false,true,1><<<grid, 128, SMEM_NT>>>(QP, Y, nullptr, S, P,
            D_MODEL, D_MODEL, D_MODEL, NHEAD * SEQ, alpha_exp2,
            (ll)SEQ * D_MODEL, (ll)NTOK * D_MODEL,   // A(Q'): b-slab, h-slab
            (ll)SEQ * D_MODEL, 0,                    // B(Y): b-slab
            (ll)SEQ * NHEAD * SEQ, (ll)SEQ,          // C: b-slab, h-column-offset
            NHEAD);
    }

    // 3) 1/rowsum
    {
        const int nrows = BATCH * NHEAD * SEQ;
        rowsum_inv_kernel<<<(nrows + 255) / 256, 256>>>(P, RS, nrows);
    }

    // 4) normalize S in place
    {
        dim3 grid((NHEAD * SEQ) / 8 / 256, NTOK, 1);   // (6, 4096)
        normalize_S_kernel<<<grid, 256>>>((uint4*)S, RS);
    }

    // 5) fused PV+Wu: P_ks[b] = S_b[:, ks*4096:(ks+1)*4096] @ V''_b[ks-slab]
    //    (M=1024, N=768, K=4096, z = ks*4 + b; split-K=3 over head-groups)
    {
        dim3 grid(D_MODEL / 128, SEQ / 128, 12);
        gemm_h<false,false,false,false,0><<<grid, 128, SMEM_NN>>>(S, VP, nullptr, P0, nullptr,
            4096, NHEAD * SEQ, D_MODEL, D_MODEL, 1.f,
            4096, (ll)SEQ * NHEAD * SEQ,              // A: ks column-offset, b-slab
            (ll)4096 * D_MODEL, (ll)NHEAD * SEQ * D_MODEL,  // B: ks row-slab, b-slab
            (ll)NTOK * D_MODEL, (ll)SEQ * D_MODEL,    // C: P_ks, b-rows
            BATCH);
        combine_ln_kernel<<<NTOK, 192>>>((const float4*)P0, (const float4*)P1,
                                         (const float4*)P2, bu, (const float4*)x,
                                         (float4*)X1,
                                         (const float4*)ln2g, (const float4*)ln2b,
                                         (uint2*)Y);
    }

    // 6) H1 = relu(Y @ W1 + b1)
    {
        dim3 grid(DFF / 128, NTOK / 128, 1);
        gemm_h<false,true,true,true,0><<<grid, 128, SMEM_NN>>>(Y, W1H, b1, H1, nullptr,
            D_MODEL, D_MODEL, DFF, DFF, 1.f, 0,0,0,0,0,0, 1);
    }

    // 7) W2 split-K=3, then out = P0+P1+P2 + b2 + X1
    {
        dim3 grid(D_MODEL / 128, NTOK / 128, 3);
        gemm_h<false,false,false,false,0><<<grid, 128, SMEM_NN>>>(H1, W2H, nullptr, P0, nullptr,
            DFF / 3, DFF, D_MODEL, D_MODEL, 1.f,
            0, (ll)(DFF / 3),
            0, (ll)(DFF / 3) * D_MODEL,
            0, (ll)NTOK * D_MODEL,
            3);
        const int n4 = NTOK * D_MODEL / 4;
        combine3_kernel<<<(n4 + 255) / 256, 256>>>((const float4*)P0, (const float4*)P1,
                                                   (const float4*)P2, b2,
                                                   (const float4*)X1, (float4*)out, n4);
    }

    (void)in_sizes; (void)n_in; (void)out_size;
}